// round 10
// baseline (speedup 1.0000x reference)
#include <cuda_runtime.h>
#include <cuda_bf16.h>
#include <math.h>
#include <stdint.h>

#define Bb 2
#define Ss 2048
#define Ee 512
#define Hh 8
#define DHh 64
#define Ww 5
#define PADp 2
#define SKk 2044
#define HIDh 2048
#define Ll 6
#define OUTo 6
#define SCALEc 0.125f
#define CHUNKS 128
#define SP 2048

#define AST 132   // smem A row stride (uint2)
#define BSW 132   // smem B row stride (uint2), 128-wide core
// fattn strides
#define QST2 84
#define KST 68
#define PST 68
#define VST 68
#define GS2 132   // G ring row stride (floats); mult of 4 -> aligned float4 loads

// ---------------- scratch ----------------
__device__ float g_x[Bb * Ss * Ee];
__device__ uint2 g_xp[Bb * Ss * (Ee / 2)];
__device__ uint2 g_qkvp[Bb * Ss * 768];
__device__ uint2 g_hidp[(size_t)Bb * Ss * (HIDh / 2)];
__device__ uint2 g_vsp[(size_t)Bb * Hh * (SP / 2) * DHh];
__device__ float g_attn[Bb * Ss * Ee];
__device__ float g_part[Bb * CHUNKS * OUTo];
__device__ uint2 g_wqkv[(Ee / 2) * 1536];
__device__ float g_bqkv[1536];
__device__ uint2 g_wfc1[(Ee / 2) * HIDh];
__device__ uint2 g_wfc2[(HIDh / 2) * Ee];

// ---------------- bf16 split/pack ----------------
__device__ __forceinline__ uint2 sp2(float x, float y) {
    __nv_bfloat16 xh = __float2bfloat16_rn(x);
    __nv_bfloat16 yh = __float2bfloat16_rn(y);
    float xr = x - __bfloat162float(xh);
    float yr = y - __bfloat162float(yh);
    __nv_bfloat16 xl = __float2bfloat16_rn(xr);
    __nv_bfloat16 yl = __float2bfloat16_rn(yr);
    uint2 w;
    w.x = ((uint32_t)__bfloat16_as_ushort(yh) << 16) | (uint32_t)__bfloat16_as_ushort(xh);
    w.y = ((uint32_t)__bfloat16_as_ushort(yl) << 16) | (uint32_t)__bfloat16_as_ushort(xl);
    return w;
}

__device__ __forceinline__ float blo(uint32_t u) {
    return __bfloat162float(__ushort_as_bfloat16((unsigned short)(u & 0xffffu)));
}
__device__ __forceinline__ float bhi(uint32_t u) {
    return __bfloat162float(__ushort_as_bfloat16((unsigned short)(u >> 16)));
}

__device__ __forceinline__ void mma16(float c[4], uint32_t a0, uint32_t a1, uint32_t a2,
                                      uint32_t a3, uint32_t b0, uint32_t b1) {
    asm volatile(
        "mma.sync.aligned.m16n8k16.row.col.f32.bf16.bf16.f32 "
        "{%0,%1,%2,%3},{%4,%5,%6,%7},{%8,%9},{%0,%1,%2,%3};"
        : "+f"(c[0]), "+f"(c[1]), "+f"(c[2]), "+f"(c[3])
        : "r"(a0), "r"(a1), "r"(a2), "r"(a3), "r"(b0), "r"(b1));
}

// ---------------- 128x128 packed GEMM (qkv, fc1, fc2) ----------------
template <int BIAS, int RELU, int RES, int WF32, int WPK>
__launch_bounds__(256, 2)
__global__ void k_gemm128(const uint2* __restrict__ A, const uint2* __restrict__ B,
                          const float* __restrict__ bias, const float* __restrict__ res,
                          float* __restrict__ Cf, uint2* __restrict__ Cp,
                          int K, int lda2, int ldb2, int ldc) {
    __shared__ uint2 sA[2][8 * AST];
    __shared__ uint2 sB2[2][8 * BSW];
    int t = threadIdx.x, lane = t & 31, wid = t >> 5;
    int wm = wid & 3, wn = wid >> 2;
    int g = lane >> 2, tg = lane & 3;
    int bm = blockIdx.y * 128, bn = blockIdx.x * 128;
    float acc[2][8][4] = {};

    int mA = t & 127, koA2 = (t >> 7) * 4;
    const uint2* Arow = A + (size_t)(bm + mA) * lda2 + koA2;
    int kpB = t >> 5, nB = (t & 31) * 4;
    const uint2* Bp = B + (size_t)kpB * ldb2 + bn + nB;

    uint4 a0 = *(const uint4*)(Arow);
    uint4 a1 = *(const uint4*)(Arow + 2);
    uint4 b0 = *(const uint4*)(Bp);
    uint4 b1 = *(const uint4*)(Bp + 2);

    {
        uint2* pa = sA[0];
        pa[(size_t)(koA2 + 0) * AST + mA] = make_uint2(a0.x, a0.y);
        pa[(size_t)(koA2 + 1) * AST + mA] = make_uint2(a0.z, a0.w);
        pa[(size_t)(koA2 + 2) * AST + mA] = make_uint2(a1.x, a1.y);
        pa[(size_t)(koA2 + 3) * AST + mA] = make_uint2(a1.z, a1.w);
        uint2* pb = sB2[0];
        pb[(size_t)kpB * BSW + nB]     = make_uint2(b0.x, b0.y);
        pb[(size_t)kpB * BSW + nB + 1] = make_uint2(b0.z, b0.w);
        pb[(size_t)kpB * BSW + nB + 2] = make_uint2(b1.x, b1.y);
        pb[(size_t)kpB * BSW + nB + 3] = make_uint2(b1.z, b1.w);
    }
    __syncthreads();

    int nch = K >> 4;
    for (int ch = 0; ch < nch; ch++) {
        int s = ch & 1;
        bool more = (ch + 1 < nch);
        if (more) {
            int off = (ch + 1) * 8;
            a0 = *(const uint4*)(Arow + off);
            a1 = *(const uint4*)(Arow + off + 2);
            const uint2* Bn = Bp + (size_t)(ch + 1) * 8 * ldb2;
            b0 = *(const uint4*)(Bn);
            b1 = *(const uint4*)(Bn + 2);
        }
        {
            const uint2* pa = sA[s];
            const uint2* pb = sB2[s];
            uint32_t ah[2][4], al[2][4];
#pragma unroll
            for (int mi = 0; mi < 2; mi++) {
                int m = wm * 32 + mi * 16 + g;
                uint2 u0 = pa[(size_t)tg * AST + m];
                uint2 u1 = pa[(size_t)tg * AST + m + 8];
                uint2 u2 = pa[(size_t)(tg + 4) * AST + m];
                uint2 u3 = pa[(size_t)(tg + 4) * AST + m + 8];
                ah[mi][0] = u0.x; al[mi][0] = u0.y;
                ah[mi][1] = u1.x; al[mi][1] = u1.y;
                ah[mi][2] = u2.x; al[mi][2] = u2.y;
                ah[mi][3] = u3.x; al[mi][3] = u3.y;
            }
#pragma unroll
            for (int ni = 0; ni < 8; ni++) {
                int n = wn * 64 + ni * 8 + g;
                uint2 v0 = pb[(size_t)tg * BSW + n];
                uint2 v1 = pb[(size_t)(tg + 4) * BSW + n];
#pragma unroll
                for (int mi = 0; mi < 2; mi++) {
                    mma16(acc[mi][ni], ah[mi][0], ah[mi][1], ah[mi][2], ah[mi][3], v0.x, v1.x);
                    mma16(acc[mi][ni], ah[mi][0], ah[mi][1], ah[mi][2], ah[mi][3], v0.y, v1.y);
                    mma16(acc[mi][ni], al[mi][0], al[mi][1], al[mi][2], al[mi][3], v0.x, v1.x);
                }
            }
        }
        if (more) {
            int s2 = s ^ 1;
            uint2* pa = sA[s2];
            pa[(size_t)(koA2 + 0) * AST + mA] = make_uint2(a0.x, a0.y);
            pa[(size_t)(koA2 + 1) * AST + mA] = make_uint2(a0.z, a0.w);
            pa[(size_t)(koA2 + 2) * AST + mA] = make_uint2(a1.x, a1.y);
            pa[(size_t)(koA2 + 3) * AST + mA] = make_uint2(a1.z, a1.w);
            uint2* pb = sB2[s2];
            pb[(size_t)kpB * BSW + nB]     = make_uint2(b0.x, b0.y);
            pb[(size_t)kpB * BSW + nB + 1] = make_uint2(b0.z, b0.w);
            pb[(size_t)kpB * BSW + nB + 2] = make_uint2(b1.x, b1.y);
            pb[(size_t)kpB * BSW + nB + 3] = make_uint2(b1.z, b1.w);
        }
        __syncthreads();
    }

#pragma unroll
    for (int mi = 0; mi < 2; mi++)
#pragma unroll
        for (int ni = 0; ni < 8; ni++) {
            int r0 = bm + wm * 32 + mi * 16 + g;
            int c0 = bn + wn * 64 + ni * 8 + 2 * tg;
            float v00 = acc[mi][ni][0], v01 = acc[mi][ni][1];
            float v10 = acc[mi][ni][2], v11 = acc[mi][ni][3];
            if (BIAS) {
                float bv0 = bias[c0], bv1 = bias[c0 + 1];
                v00 += bv0; v01 += bv1; v10 += bv0; v11 += bv1;
            }
            if (RES) {
                v00 += res[(size_t)r0 * ldc + c0];
                v01 += res[(size_t)r0 * ldc + c0 + 1];
                v10 += res[(size_t)(r0 + 8) * ldc + c0];
                v11 += res[(size_t)(r0 + 8) * ldc + c0 + 1];
            }
            if (RELU) {
                v00 = fmaxf(v00, 0.f); v01 = fmaxf(v01, 0.f);
                v10 = fmaxf(v10, 0.f); v11 = fmaxf(v11, 0.f);
            }
            if (WF32) {
                Cf[(size_t)r0 * ldc + c0] = v00;
                Cf[(size_t)r0 * ldc + c0 + 1] = v01;
                Cf[(size_t)(r0 + 8) * ldc + c0] = v10;
                Cf[(size_t)(r0 + 8) * ldc + c0 + 1] = v11;
            }
            if (WPK) {
                Cp[(size_t)r0 * (ldc >> 1) + (c0 >> 1)] = sp2(v00, v01);
                Cp[(size_t)(r0 + 8) * (ldc >> 1) + (c0 >> 1)] = sp2(v10, v11);
            }
        }
}

// ---------------- weight packing ----------------
__global__ void k_pack_qkv(const float* __restrict__ qw, const float* __restrict__ kw,
                           const float* __restrict__ vw, const float* __restrict__ qb,
                           const float* __restrict__ kb, const float* __restrict__ vb) {
    int idx = blockIdx.x * 256 + threadIdx.x;
    if (idx < (Ee / 2) * 1536) {
        int n = idx % 1536, kp = idx / 1536;
        const float* W = (n < 512) ? qw : (n < 1024 ? kw : vw);
        int c = n & 511;
        g_wqkv[idx] = sp2(W[(size_t)(2 * kp) * 512 + c], W[(size_t)(2 * kp + 1) * 512 + c]);
    }
    if (idx < 1536)
        g_bqkv[idx] = (idx < 512) ? qb[idx] : (idx < 1024 ? kb[idx - 512] : vb[idx - 1024]);
}

__global__ void k_pack_w(const float* __restrict__ W, uint2* __restrict__ out, int Kp, int N) {
    int idx = blockIdx.x * 256 + threadIdx.x;
    if (idx >= Kp * N) return;
    int n = idx % N, kp = idx / N;
    out[idx] = sp2(W[(size_t)(2 * kp) * N + n], W[(size_t)(2 * kp + 1) * N + n]);
}

// ---------------- embedding + positional encoding ----------------
__global__ void k_embed(const int* __restrict__ inp, const float* __restrict__ emb) {
    int idx = blockIdx.x * blockDim.x + threadIdx.x;
    if (idx >= Bb * Ss * (Ee / 2)) return;
    int ep = idx % (Ee / 2);
    int bs = idx / (Ee / 2);
    int s = bs % Ss;
    int tok = inp[bs];
    int e0 = 2 * ep;
    const float LN1E4 = 9.210340371976184f;
    float freq = expf(-(float)e0 * (LN1E4 / (float)Ee));
    float ang = (float)s * freq;
    float x0 = emb[(size_t)tok * Ee + e0] + sinf(ang);
    float x1 = emb[(size_t)tok * Ee + e0 + 1] + cosf(ang);
    g_x[(size_t)bs * Ee + e0] = x0;
    g_x[(size_t)bs * Ee + e0 + 1] = x1;
    g_xp[(size_t)bs * (Ee / 2) + ep] = sp2(x0, x1);
}

// ---------------- window-summed V from packed QKV ----------------
__global__ void k_build_vs() {
    int idx = blockIdx.x * blockDim.x + threadIdx.x;
    if (idx >= Bb * Hh * (SKk / 2) * (DHh / 2)) return;
    int dp = idx & 31;
    int rest = idx >> 5;
    int kp = rest % (SKk / 2);
    int bh = rest / (SKk / 2);
    int b = bh >> 3, h = bh & 7;
    const uint2* Vp = g_qkvp + (size_t)b * Ss * 768 + 512 + h * 32 + dp;
    int k = 2 * kp;
    float v0[6], v1[6];
#pragma unroll
    for (int r = 0; r < 6; r++) {
        uint2 w = Vp[(size_t)(k + r) * 768];
        v0[r] = blo(w.x) + blo(w.y);
        v1[r] = bhi(w.x) + bhi(w.y);
    }
    float s00 = v0[0] + v0[1] + v0[2] + v0[3] + v0[4];
    float s10 = v0[1] + v0[2] + v0[3] + v0[4] + v0[5];
    float s01 = v1[0] + v1[1] + v1[2] + v1[3] + v1[4];
    float s11 = v1[1] + v1[2] + v1[3] + v1[4] + v1[5];
    uint2* dst = g_vsp + ((size_t)bh * (SP / 2) + kp) * DHh + 2 * dp;
    dst[0] = sp2(s00, s10);
    dst[1] = sp2(s01, s11);
}

// ---------------- fused attention (64-row q-tiles) ----------------
#define FA_OFF_Q  0                          // 32 x 84 uint2  = 21504
#define FA_OFF_K  21504                      // 32 x 68 uint2  = 17408
#define FA_OFF_G  38912                      // 68 x 132 float = 35904
#define FA_OFF_P  74816                      // 32 x 68 uint2  = 17408
#define FA_OFF_V  92224                      // 32 x 68 uint2  = 17408
#define FA_OFF_S  109632                     // sFac[64] + sLf[64]
#define FA_SMEM   110144

__launch_bounds__(256)
__global__ void k_fattn() {
    extern __shared__ char dyn[];
    uint2* sQ = (uint2*)(dyn + FA_OFF_Q);
    uint2* sK = (uint2*)(dyn + FA_OFF_K);
    float* sG = (float*)(dyn + FA_OFF_G);
    uint2* sP = (uint2*)(dyn + FA_OFF_P);
    uint2* sV = (uint2*)(dyn + FA_OFF_V);
    float* sFac = (float*)(dyn + FA_OFF_S);
    float* sLf = sFac + 64;

    int qt = blockIdx.x;
    int bh = blockIdx.y;
    int b = bh >> 3, h = bh & 7;
    int q0 = qt * 64;
    const uint2* Qb = g_qkvp + (size_t)b * Ss * 768 + h * 32;
    const uint2* Kb = g_qkvp + (size_t)b * Ss * 768 + 256 + h * 32;
    const uint2* Vb = g_vsp + (size_t)bh * (SP / 2) * DHh;

    int t = threadIdx.x, lane = t & 31, wid = t >> 5;
    int wm = wid & 3, wn = wid >> 2;
    int g = lane >> 2, tg = lane & 3;
    float acc[4][4] = {};
    float m_run = -1e30f, l_run = 0.f;
    int srow = t >> 2, kbase = (t & 3) * 16;

    // load Q tile: rows 0..67 = global q0-2..q0+65; rows 68..79 zero
    {
        int dpq = (t & 3) * 8;
        int rr = t >> 2;
#pragma unroll
        for (int rb = 0; rb < 80; rb += 64) {
            int r = rb + rr;
            if (r < 80) {
                int gr = q0 - 2 + r;
                bool ok = (r < 68) && (gr >= 0) && (gr < Ss);
#pragma unroll
                for (int u = 0; u < 8; u += 2) {
                    uint4 v = make_uint4(0, 0, 0, 0);
                    if (ok) v = *(const uint4*)(Qb + (size_t)gr * 768 + dpq + u);
                    sQ[(size_t)(dpq + u) * QST2 + r] = make_uint2(v.x, v.y);
                    sQ[(size_t)(dpq + u + 1) * QST2 + r] = make_uint2(v.z, v.w);
                }
            }
        }
    }
    // load K panel 0
    {
        int r = t >> 2, dpq = (t & 3) * 8;
        const uint2* src = Kb + (size_t)r * 768 + dpq;
#pragma unroll
        for (int u = 0; u < 8; u += 2) {
            uint4 v = *(const uint4*)(src + u);
            sK[(size_t)(dpq + u) * KST + r] = make_uint2(v.x, v.y);
            sK[(size_t)(dpq + u + 1) * KST + r] = make_uint2(v.z, v.w);
        }
    }
    __syncthreads();

    // gram panel 0 -> ring slot 0
    {
        float accg[5][4] = {};
        int nb = wid * 8 + g;
#pragma unroll
        for (int c = 0; c < 4; c++) {
            uint2 v0 = sK[(size_t)(c * 8 + tg) * KST + nb];
            uint2 v1 = sK[(size_t)(c * 8 + tg + 4) * KST + nb];
#pragma unroll
            for (int mi = 0; mi < 5; mi++) {
                int m = mi * 16 + g;
                uint2 u0 = sQ[(size_t)(c * 8 + tg) * QST2 + m];
                uint2 u1 = sQ[(size_t)(c * 8 + tg) * QST2 + m + 8];
                uint2 u2 = sQ[(size_t)(c * 8 + tg + 4) * QST2 + m];
                uint2 u3 = sQ[(size_t)(c * 8 + tg + 4) * QST2 + m + 8];
                mma16(accg[mi], u0.x, u1.x, u2.x, u3.x, v0.x, v1.x);
                mma16(accg[mi], u0.x, u1.x, u2.x, u3.x, v0.y, v1.y);
                mma16(accg[mi], u0.y, u1.y, u2.y, u3.y, v0.x, v1.x);
            }
        }
        int c0 = wid * 8 + 2 * tg;
#pragma unroll
        for (int mi = 0; mi < 5; mi++) {
            int r0 = mi * 16 + g;
            if (r0 < 68) {
                sG[r0 * GS2 + c0] = accg[mi][0] * SCALEc;
                sG[r0 * GS2 + c0 + 1] = accg[mi][1] * SCALEc;
            }
            if (r0 + 8 < 68) {
                sG[(r0 + 8) * GS2 + c0] = accg[mi][2] * SCALEc;
                sG[(r0 + 8) * GS2 + c0 + 1] = accg[mi][3] * SCALEc;
            }
        }
    }
    __syncthreads();

    for (int it = 0; it < 32; it++) {
        int k0 = it * 64;
        bool more = (it < 31);

        if (more) {
            int r = t >> 2, dpq = (t & 3) * 8;
            const uint2* src = Kb + (size_t)((it + 1) * 64 + r) * 768 + dpq;
#pragma unroll
            for (int u = 0; u < 8; u += 2) {
                uint4 v = *(const uint4*)(src + u);
                sK[(size_t)(dpq + u) * KST + r] = make_uint2(v.x, v.y);
                sK[(size_t)(dpq + u + 1) * KST + r] = make_uint2(v.z, v.w);
            }
        }
        {
            int kpB = t >> 5, dB = (t & 31) * 2;
#pragma unroll
            for (int r = 0; r < 4; r++) {
                int kp = r * 8 + kpB;
                uint4 v = *(const uint4*)(Vb + (size_t)((k0 >> 1) + kp) * DHh + dB);
                sV[(size_t)kp * VST + dB] = make_uint2(v.x, v.y);
                sV[(size_t)kp * VST + dB + 1] = make_uint2(v.z, v.w);
            }
        }
        __syncthreads();   // A

        if (more) {
            float accg[5][4] = {};
            int nb = wid * 8 + g;
#pragma unroll
            for (int c = 0; c < 4; c++) {
                uint2 v0 = sK[(size_t)(c * 8 + tg) * KST + nb];
                uint2 v1 = sK[(size_t)(c * 8 + tg + 4) * KST + nb];
#pragma unroll
                for (int mi = 0; mi < 5; mi++) {
                    int m = mi * 16 + g;
                    uint2 u0 = sQ[(size_t)(c * 8 + tg) * QST2 + m];
                    uint2 u1 = sQ[(size_t)(c * 8 + tg) * QST2 + m + 8];
                    uint2 u2 = sQ[(size_t)(c * 8 + tg + 4) * QST2 + m];
                    uint2 u3 = sQ[(size_t)(c * 8 + tg + 4) * QST2 + m + 8];
                    mma16(accg[mi], u0.x, u1.x, u2.x, u3.x, v0.x, v1.x);
                    mma16(accg[mi], u0.x, u1.x, u2.x, u3.x, v0.y, v1.y);
                    mma16(accg[mi], u0.y, u1.y, u2.y, u3.y, v0.x, v1.x);
                }
            }
            int c0 = ((it + 1) & 1) * 64 + wid * 8 + 2 * tg;
#pragma unroll
            for (int mi = 0; mi < 5; mi++) {
                int r0 = mi * 16 + g;
                if (r0 < 68) {
                    sG[r0 * GS2 + c0] = accg[mi][0] * SCALEc;
                    sG[r0 * GS2 + c0 + 1] = accg[mi][1] * SCALEc;
                }
                if (r0 + 8 < 68) {
                    sG[(r0 + 8) * GS2 + c0] = accg[mi][2] * SCALEc;
                    sG[(r0 + 8) * GS2 + c0 + 1] = accg[mi][3] * SCALEc;
                }
            }
        }
        __syncthreads();   // B

        // scores: vectorized shift-sum (5 rows x 5 float4 + register shifts)
        float sv[16];
#pragma unroll
        for (int i = 0; i < 16; i++) sv[i] = 0.f;
        int cb0 = ((it & 1) << 6) + kbase;
#pragma unroll
        for (int j = 0; j < Ww; j++) {
            const float* rp = sG + (srow + j) * GS2;
            float rr[20];
#pragma unroll
            for (int m = 0; m < 5; m++) {
                float4 v = *(const float4*)(rp + ((cb0 + 4 * m) & 127));
                rr[4 * m + 0] = v.x; rr[4 * m + 1] = v.y;
                rr[4 * m + 2] = v.z; rr[4 * m + 3] = v.w;
            }
#pragma unroll
            for (int i = 0; i < 16; i++) sv[i] += rr[i + j];
        }
        float lmax = -1e30f;
#pragma unroll
        for (int i = 0; i < 16; i++) {
            if (k0 + kbase + i >= SKk) sv[i] = -1e30f;
            lmax = fmaxf(lmax, sv[i]);
        }
        lmax = fmaxf(lmax, __shfl_xor_sync(0xffffffffu, lmax, 1));
        lmax = fmaxf(lmax, __shfl_xor_sync(0xffffffffu, lmax, 2));
        float mnew = fmaxf(m_run, lmax);
        float lsum = 0.f;
#pragma unroll
        for (int i = 0; i < 16; i += 2) {
            float p0 = __expf(sv[i] - mnew);
            float p1 = __expf(sv[i + 1] - mnew);
            lsum += p0 + p1;
            sP[(size_t)((kbase >> 1) + (i >> 1)) * PST + srow] = sp2(p0, p1);
        }
        lsum += __shfl_xor_sync(0xffffffffu, lsum, 1);
        lsum += __shfl_xor_sync(0xffffffffu, lsum, 2);
        float fac = __expf(m_run - mnew);
        l_run = l_run * fac + lsum;
        m_run = mnew;
        if ((t & 3) == 0) sFac[srow] = fac;
        __syncthreads();   // C

        {
            float f0 = sFac[wm * 16 + g];
            float f1 = sFac[wm * 16 + g + 8];
#pragma unroll
            for (int ni = 0; ni < 4; ni++) {
                acc[ni][0] *= f0; acc[ni][1] *= f0;
                acc[ni][2] *= f1; acc[ni][3] *= f1;
            }
#pragma unroll
            for (int c = 0; c < 4; c++) {
                int m = wm * 16 + g;
                uint2 u0 = sP[(size_t)(c * 8 + tg) * PST + m];
                uint2 u1 = sP[(size_t)(c * 8 + tg) * PST + m + 8];
                uint2 u2 = sP[(size_t)(c * 8 + tg + 4) * PST + m];
                uint2 u3 = sP[(size_t)(c * 8 + tg + 4) * PST + m + 8];
#pragma unroll
                for (int ni = 0; ni < 4; ni++) {
                    int n = wn * 32 + ni * 8 + g;
                    uint2 v0 = sV[(size_t)(c * 8 + tg) * VST + n];
                    uint2 v1 = sV[(size_t)(c * 8 + tg + 4) * VST + n];
                    mma16(acc[ni], u0.x, u1.x, u2.x, u3.x, v0.x, v1.x);
                    mma16(acc[ni], u0.x, u1.x, u2.x, u3.x, v0.y, v1.y);
                    mma16(acc[ni], u0.y, u1.y, u2.y, u3.y, v0.x, v1.x);
                }
            }
        }
        __syncthreads();   // D
    }

    if ((t & 3) == 0) sLf[srow] = l_run;
    __syncthreads();

    float inv0 = 1.f / sLf[wm * 16 + g];
    float inv1 = 1.f / sLf[wm * 16 + g + 8];
    float* Cb = g_attn + (size_t)b * Ss * Ee + h * DHh;
#pragma unroll
    for (int ni = 0; ni < 4; ni++) {
        int r0 = q0 + wm * 16 + g;
        int c0 = wn * 32 + ni * 8 + 2 * tg;
        Cb[(size_t)r0 * Ee + c0] = acc[ni][0] * inv0;
        Cb[(size_t)r0 * Ee + c0 + 1] = acc[ni][1] * inv0;
        Cb[(size_t)(r0 + 8) * Ee + c0] = acc[ni][2] * inv1;
        Cb[(size_t)(r0 + 8) * Ee + c0 + 1] = acc[ni][3] * inv1;
    }
}

// ---------------- LayerNorm: one warp per row, shuffle-only reductions ----------------
__launch_bounds__(256)
__global__ void k_ln(const float* __restrict__ in, const float* __restrict__ w,
                     const float* __restrict__ bz, float* __restrict__ out,
                     uint2* __restrict__ outp) {
    int row = blockIdx.x * 8 + (threadIdx.x >> 5);
    int lane = threadIdx.x & 31;
    const float* x = in + (size_t)row * Ee;

    float4 v[4];
#pragma unroll
    for (int j = 0; j < 4; j++)
        v[j] = *(const float4*)(x + 4 * (lane + j * 32));

    float s = 0.f;
#pragma unroll
    for (int j = 0; j < 4; j++) s += v[j].x + v[j].y + v[j].z + v[j].w;
#pragma unroll
    for (int off = 16; off > 0; off >>= 1)
        s += __shfl_xor_sync(0xffffffffu, s, off);
    float m = s * (1.0f / Ee);

    float vs = 0.f;
#pragma unroll
    for (int j = 0; j < 4; j++) {
        float d0 = v[j].x - m, d1 = v[j].y - m, d2 = v[j].z - m, d3 = v[j].w - m;
        vs += d0 * d0 + d1 * d1 + d2 * d2 + d3 * d3;
    }
#pragma unroll
    for (int off = 16; off > 0; off >>= 1)
        vs += __shfl_xor_sync(0xffffffffu, vs, off);
    float inv = rsqrtf(vs * (1.0f / Ee) + 1e-5f);

#pragma unroll
    for (int j = 0; j < 4; j++) {
        int c = 4 * (lane + j * 32);
        float4 wv = *(const float4*)(w + c);
        float4 bv = *(const float4*)(bz + c);
        float y0 = (v[j].x - m) * inv * wv.x + bv.x;
        float y1 = (v[j].y - m) * inv * wv.y + bv.y;
        float y2 = (v[j].z - m) * inv * wv.z + bv.z;
        float y3 = (v[j].w - m) * inv * wv.w + bv.w;
        *(float4*)(out + (size_t)row * Ee + c) = make_float4(y0, y1, y2, y3);
        uint2 p0 = sp2(y0, y1);
        uint2 p1 = sp2(y2, y3);
        *(uint4*)(outp + (size_t)row * (Ee / 2) + (c >> 1)) =
            make_uint4(p0.x, p0.y, p1.x, p1.y);
    }
}

// ---------------- output head ----------------
__launch_bounds__(256)
__global__ void k_out_partial(const float* __restrict__ ow) {
    int b = blockIdx.y, c = blockIdx.x;
    const int per = (Ss * Ee) / CHUNKS;
    const float* x = g_x + (size_t)b * Ss * Ee + (size_t)c * per;
    const float* wr = ow + (size_t)c * per * OUTo;
    int t = threadIdx.x;
    float acc[OUTo] = {};
    for (int i = t; i < per; i += 256) {
        float xv = x[i];
#pragma unroll
        for (int o = 0; o < OUTo; o++) acc[o] = fmaf(xv, wr[(size_t)i * OUTo + o], acc[o]);
    }
    __shared__ float red[256 * OUTo];
#pragma unroll
    for (int o = 0; o < OUTo; o++) red[t * OUTo + o] = acc[o];
    __syncthreads();
    for (int off = 128; off > 0; off >>= 1) {
        if (t < off) {
#pragma unroll
            for (int o = 0; o < OUTo; o++)
                red[t * OUTo + o] += red[(t + off) * OUTo + o];
        }
        __syncthreads();
    }
    if (t == 0) {
#pragma unroll
        for (int o = 0; o < OUTo; o++)
            g_part[((size_t)b * CHUNKS + c) * OUTo + o] = red[o];
    }
}

__global__ void k_out_final(const float* __restrict__ ob, float* __restrict__ out) {
    int b = blockIdx.x;
    int o = threadIdx.x;
    if (o < OUTo) {
        float s = ob[o];
        for (int c = 0; c < CHUNKS; c++) s += g_part[(b * CHUNKS + c) * OUTo + o];
        out[b * OUTo + o] = s;
    }
}

// ---------------- host launcher ----------------
extern "C" void kernel_launch(void* const* d_in, const int* in_sizes, int n_in,
                              void* d_out, int out_size) {
    const int*   inputs = (const int*)d_in[0];
    const float* emb    = (const float*)d_in[1];
    const float* ln_w   = (const float*)d_in[2];
    const float* ln_b   = (const float*)d_in[3];
    const float* q_w    = (const float*)d_in[4];
    const float* q_b    = (const float*)d_in[5];
    const float* k_w    = (const float*)d_in[6];
    const float* k_b    = (const float*)d_in[7];
    const float* v_w    = (const float*)d_in[8];
    const float* v_b    = (const float*)d_in[9];
    const float* fc1_w  = (const float*)d_in[10];
    const float* fc1_b  = (const float*)d_in[11];
    const float* fc2_w  = (const float*)d_in[12];
    const float* fc2_b  = (const float*)d_in[13];
    const float* out_w  = (const float*)d_in[14];
    const float* out_b  = (const float*)d_in[15];
    float* out = (float*)d_out;

    static int smem_set = 0;
    if (!smem_set) {
        cudaFuncSetAttribute(k_fattn, cudaFuncAttributeMaxDynamicSharedMemorySize, FA_SMEM);
        smem_set = 1;
    }

    float *px, *pattn, *pbqkv;
    uint2 *pxp, *pqkvp, *phidp, *pwqkv, *pwfc1, *pwfc2;
    cudaGetSymbolAddress((void**)&px, g_x);
    cudaGetSymbolAddress((void**)&pattn, g_attn);
    cudaGetSymbolAddress((void**)&pxp, g_xp);
    cudaGetSymbolAddress((void**)&pqkvp, g_qkvp);
    cudaGetSymbolAddress((void**)&phidp, g_hidp);
    cudaGetSymbolAddress((void**)&pwqkv, g_wqkv);
    cudaGetSymbolAddress((void**)&pwfc1, g_wfc1);
    cudaGetSymbolAddress((void**)&pwfc2, g_wfc2);
    cudaGetSymbolAddress((void**)&pbqkv, g_bqkv);

    const int M = Bb * Ss;  // 4096

    k_pack_qkv<<<((Ee / 2) * 1536 + 255) / 256, 256>>>(q_w, k_w, v_w, q_b, k_b, v_b);
    k_pack_w<<<((Ee / 2) * HIDh + 255) / 256, 256>>>(fc1_w, pwfc1, Ee / 2, HIDh);
    k_pack_w<<<((HIDh / 2) * Ee + 255) / 256, 256>>>(fc2_w, pwfc2, HIDh / 2, Ee);

    k_embed<<<(Bb * Ss * (Ee / 2) + 255) / 256, 256>>>(inputs, emb);

    for (int l = 0; l < Ll; l++) {
        // QKV: 128x128 tiles, packed-only output
        k_gemm128<1, 0, 0, 0, 1><<<dim3(1536 / 128, M / 128), 256>>>(
            pxp, pwqkv, pbqkv, nullptr, nullptr, pqkvp, Ee, Ee / 2, 1536, 1536);

        k_build_vs<<<(Bb * Hh * (SKk / 2) * (DHh / 2) + 255) / 256, 256>>>();

        dim3 gf(Ss / 64, Bb * Hh);
        k_fattn<<<gf, 256, FA_SMEM>>>();

        k_ln<<<M / 8, 256>>>(pattn, ln_w, ln_b, px, pxp);

        // fc1: 128x128 tiles, relu, packed-only output
        k_gemm128<1, 1, 0, 0, 1><<<dim3(HIDh / 128, M / 128), 256>>>(
            pxp, pwfc1, fc1_b, nullptr, nullptr, phidp, Ee, Ee / 2, HIDh, HIDh);
        // fc2: 128x128 tiles, residual + fp32 out
        k_gemm128<1, 0, 1, 1, 0><<<dim3(Ee / 128, M / 128), 256>>>(
            phidp, pwfc2, fc2_b, px, pattn, nullptr, HIDh, HIDh / 2, Ee, Ee);

        k_ln<<<M / 8, 256>>>(pattn, ln_w, ln_b, px, pxp);
    }

    dim3 go(CHUNKS, Bb);
    k_out_partial<<<go, 256>>>(out_w);
    k_out_final<<<Bb, 32>>>(out_b, out);
}

// round 11
// speedup vs baseline: 1.0514x; 1.0514x over previous
#include <cuda_runtime.h>
#include <cuda_bf16.h>
#include <math.h>
#include <stdint.h>

#define Bb 2
#define Ss 2048
#define Ee 512
#define Hh 8
#define DHh 64
#define Ww 5
#define PADp 2
#define SKk 2044
#define HIDh 2048
#define Ll 6
#define OUTo 6
#define SCALEc 0.125f
#define CHUNKS 128
#define SP 2048

#define AST 132   // smem A row stride (uint2)
#define BST 68    // smem B row stride (uint2), 64-wide core
#define BSW 132   // smem B row stride (uint2), 128-wide core
// fattn strides
#define QST2 84
#define KST 68
#define PST 68
#define VST 68
#define GS2 132   // G ring row stride (floats); mult of 4 -> aligned float4 loads

// ---------------- scratch ----------------
__device__ float g_x[Bb * Ss * Ee];
__device__ uint2 g_xp[Bb * Ss * (Ee / 2)];
__device__ uint2 g_qkvp[Bb * Ss * 768];
__device__ uint2 g_hidp[(size_t)Bb * Ss * (HIDh / 2)];
__device__ uint2 g_vsp[(size_t)Bb * Hh * (SP / 2) * DHh];
__device__ float g_attn[Bb * Ss * Ee];
__device__ float g_part[Bb * CHUNKS * OUTo];
__device__ uint2 g_wqkv[(Ee / 2) * 1536];
__device__ float g_bqkv[1536];
__device__ uint2 g_wfc1[(Ee / 2) * HIDh];
__device__ uint2 g_wfc2[(HIDh / 2) * Ee];

// ---------------- bf16 split/pack ----------------
__device__ __forceinline__ uint2 sp2(float x, float y) {
    __nv_bfloat16 xh = __float2bfloat16_rn(x);
    __nv_bfloat16 yh = __float2bfloat16_rn(y);
    float xr = x - __bfloat162float(xh);
    float yr = y - __bfloat162float(yh);
    __nv_bfloat16 xl = __float2bfloat16_rn(xr);
    __nv_bfloat16 yl = __float2bfloat16_rn(yr);
    uint2 w;
    w.x = ((uint32_t)__bfloat16_as_ushort(yh) << 16) | (uint32_t)__bfloat16_as_ushort(xh);
    w.y = ((uint32_t)__bfloat16_as_ushort(yl) << 16) | (uint32_t)__bfloat16_as_ushort(xl);
    return w;
}

__device__ __forceinline__ float blo(uint32_t u) {
    return __bfloat162float(__ushort_as_bfloat16((unsigned short)(u & 0xffffu)));
}
__device__ __forceinline__ float bhi(uint32_t u) {
    return __bfloat162float(__ushort_as_bfloat16((unsigned short)(u >> 16)));
}

__device__ __forceinline__ void mma16(float c[4], uint32_t a0, uint32_t a1, uint32_t a2,
                                      uint32_t a3, uint32_t b0, uint32_t b1) {
    asm volatile(
        "mma.sync.aligned.m16n8k16.row.col.f32.bf16.bf16.f32 "
        "{%0,%1,%2,%3},{%4,%5,%6,%7},{%8,%9},{%0,%1,%2,%3};"
        : "+f"(c[0]), "+f"(c[1]), "+f"(c[2]), "+f"(c[3])
        : "r"(a0), "r"(a1), "r"(a2), "r"(a3), "r"(b0), "r"(b1));
}

// one 16-k chunk over 128x64 tile (warp tile 32x32) -- used by 64-wide core
__device__ __forceinline__ void mma_chunk(const uint2* sA, const uint2* sB,
                                          int wm, int wn, int lane, float acc[2][4][4]) {
    int g = lane >> 2, tg = lane & 3;
    uint32_t ah[2][4], al[2][4];
#pragma unroll
    for (int mi = 0; mi < 2; mi++) {
        int m = wm * 32 + mi * 16 + g;
        uint2 u0 = sA[(size_t)tg * AST + m];
        uint2 u1 = sA[(size_t)tg * AST + m + 8];
        uint2 u2 = sA[(size_t)(tg + 4) * AST + m];
        uint2 u3 = sA[(size_t)(tg + 4) * AST + m + 8];
        ah[mi][0] = u0.x; al[mi][0] = u0.y;
        ah[mi][1] = u1.x; al[mi][1] = u1.y;
        ah[mi][2] = u2.x; al[mi][2] = u2.y;
        ah[mi][3] = u3.x; al[mi][3] = u3.y;
    }
#pragma unroll
    for (int ni = 0; ni < 4; ni++) {
        int n = wn * 32 + ni * 8 + g;
        uint2 v0 = sB[(size_t)tg * BST + n];
        uint2 v1 = sB[(size_t)(tg + 4) * BST + n];
#pragma unroll
        for (int mi = 0; mi < 2; mi++) {
            mma16(acc[mi][ni], ah[mi][0], ah[mi][1], ah[mi][2], ah[mi][3], v0.x, v1.x);
            mma16(acc[mi][ni], ah[mi][0], ah[mi][1], ah[mi][2], ah[mi][3], v0.y, v1.y);
            mma16(acc[mi][ni], al[mi][0], al[mi][1], al[mi][2], al[mi][3], v0.x, v1.x);
        }
    }
}

// ---------------- 64-wide packed GEMM core (fc2) ----------------
__launch_bounds__(256)
__global__ void k_fc2(const float* __restrict__ bias) {
    const uint2* __restrict__ A = g_hidp;
    const uint2* __restrict__ B = g_wfc2;
    const float* __restrict__ res = g_x;
    float* __restrict__ C = g_attn;
    const int K = HIDh, lda2 = HIDh / 2, ldb2 = Ee, ldc = Ee;

    __shared__ uint2 sA[2][8 * AST];
    __shared__ uint2 sB[2][8 * BST];
    int t = threadIdx.x, lane = t & 31, wid = t >> 5;
    int wm = wid & 3, wn = wid >> 2;
    int bm = blockIdx.y * 128, bn = blockIdx.x * 64;
    float acc[2][4][4] = {};

    int mA = t & 127, koA2 = (t >> 7) * 4;
    const uint2* Arow = A + (size_t)(bm + mA) * lda2 + koA2;
    int kpB = t >> 5, nB = (t & 31) * 2;
    const uint2* Bp = B + (size_t)kpB * ldb2 + bn + nB;

    uint4 a0 = *(const uint4*)(Arow);
    uint4 a1 = *(const uint4*)(Arow + 2);
    uint4 b0 = *(const uint4*)(Bp);

    {
        uint2* pa = sA[0];
        pa[(size_t)(koA2 + 0) * AST + mA] = make_uint2(a0.x, a0.y);
        pa[(size_t)(koA2 + 1) * AST + mA] = make_uint2(a0.z, a0.w);
        pa[(size_t)(koA2 + 2) * AST + mA] = make_uint2(a1.x, a1.y);
        pa[(size_t)(koA2 + 3) * AST + mA] = make_uint2(a1.z, a1.w);
        uint2* pb = sB[0];
        pb[(size_t)kpB * BST + nB]     = make_uint2(b0.x, b0.y);
        pb[(size_t)kpB * BST + nB + 1] = make_uint2(b0.z, b0.w);
    }
    __syncthreads();

    int nch = K >> 4;
    for (int ch = 0; ch < nch; ch++) {
        int s = ch & 1;
        bool more = (ch + 1 < nch);
        if (more) {
            int off = (ch + 1) * 8;
            a0 = *(const uint4*)(Arow + off);
            a1 = *(const uint4*)(Arow + off + 2);
            b0 = *(const uint4*)(Bp + (size_t)(ch + 1) * 8 * ldb2);
        }
        mma_chunk(sA[s], sB[s], wm, wn, lane, acc);
        if (more) {
            int s2 = s ^ 1;
            uint2* pa = sA[s2];
            pa[(size_t)(koA2 + 0) * AST + mA] = make_uint2(a0.x, a0.y);
            pa[(size_t)(koA2 + 1) * AST + mA] = make_uint2(a0.z, a0.w);
            pa[(size_t)(koA2 + 2) * AST + mA] = make_uint2(a1.x, a1.y);
            pa[(size_t)(koA2 + 3) * AST + mA] = make_uint2(a1.z, a1.w);
            uint2* pb = sB[s2];
            pb[(size_t)kpB * BST + nB]     = make_uint2(b0.x, b0.y);
            pb[(size_t)kpB * BST + nB + 1] = make_uint2(b0.z, b0.w);
        }
        __syncthreads();
    }

    int g = lane >> 2, tg = lane & 3;
#pragma unroll
    for (int mi = 0; mi < 2; mi++)
#pragma unroll
        for (int ni = 0; ni < 4; ni++) {
            int r0 = bm + wm * 32 + mi * 16 + g;
            int c0 = bn + wn * 32 + ni * 8 + 2 * tg;
            float bv0 = bias[c0], bv1 = bias[c0 + 1];
            float v00 = acc[mi][ni][0] + bv0 + res[(size_t)r0 * ldc + c0];
            float v01 = acc[mi][ni][1] + bv1 + res[(size_t)r0 * ldc + c0 + 1];
            float v10 = acc[mi][ni][2] + bv0 + res[(size_t)(r0 + 8) * ldc + c0];
            float v11 = acc[mi][ni][3] + bv1 + res[(size_t)(r0 + 8) * ldc + c0 + 1];
            C[(size_t)r0 * ldc + c0] = v00;
            C[(size_t)r0 * ldc + c0 + 1] = v01;
            C[(size_t)(r0 + 8) * ldc + c0] = v10;
            C[(size_t)(r0 + 8) * ldc + c0 + 1] = v11;
        }
}

// ---------------- 128x128 packed GEMM (qkv, fc1) ----------------
template <int BIAS, int RELU, int WPK>
__launch_bounds__(256, 2)
__global__ void k_gemm128(const uint2* __restrict__ A, const uint2* __restrict__ B,
                          const float* __restrict__ bias,
                          uint2* __restrict__ Cp,
                          int K, int lda2, int ldb2, int ldc) {
    __shared__ uint2 sA[2][8 * AST];
    __shared__ uint2 sB2[2][8 * BSW];
    int t = threadIdx.x, lane = t & 31, wid = t >> 5;
    int wm = wid & 3, wn = wid >> 2;
    int g = lane >> 2, tg = lane & 3;
    int bm = blockIdx.y * 128, bn = blockIdx.x * 128;
    float acc[2][8][4] = {};

    int mA = t & 127, koA2 = (t >> 7) * 4;
    const uint2* Arow = A + (size_t)(bm + mA) * lda2 + koA2;
    int kpB = t >> 5, nB = (t & 31) * 4;
    const uint2* Bp = B + (size_t)kpB * ldb2 + bn + nB;

    uint4 a0 = *(const uint4*)(Arow);
    uint4 a1 = *(const uint4*)(Arow + 2);
    uint4 b0 = *(const uint4*)(Bp);
    uint4 b1 = *(const uint4*)(Bp + 2);

    {
        uint2* pa = sA[0];
        pa[(size_t)(koA2 + 0) * AST + mA] = make_uint2(a0.x, a0.y);
        pa[(size_t)(koA2 + 1) * AST + mA] = make_uint2(a0.z, a0.w);
        pa[(size_t)(koA2 + 2) * AST + mA] = make_uint2(a1.x, a1.y);
        pa[(size_t)(koA2 + 3) * AST + mA] = make_uint2(a1.z, a1.w);
        uint2* pb = sB2[0];
        pb[(size_t)kpB * BSW + nB]     = make_uint2(b0.x, b0.y);
        pb[(size_t)kpB * BSW + nB + 1] = make_uint2(b0.z, b0.w);
        pb[(size_t)kpB * BSW + nB + 2] = make_uint2(b1.x, b1.y);
        pb[(size_t)kpB * BSW + nB + 3] = make_uint2(b1.z, b1.w);
    }
    __syncthreads();

    int nch = K >> 4;
    for (int ch = 0; ch < nch; ch++) {
        int s = ch & 1;
        bool more = (ch + 1 < nch);
        if (more) {
            int off = (ch + 1) * 8;
            a0 = *(const uint4*)(Arow + off);
            a1 = *(const uint4*)(Arow + off + 2);
            const uint2* Bn = Bp + (size_t)(ch + 1) * 8 * ldb2;
            b0 = *(const uint4*)(Bn);
            b1 = *(const uint4*)(Bn + 2);
        }
        {
            const uint2* pa = sA[s];
            const uint2* pb = sB2[s];
            uint32_t ah[2][4], al[2][4];
#pragma unroll
            for (int mi = 0; mi < 2; mi++) {
                int m = wm * 32 + mi * 16 + g;
                uint2 u0 = pa[(size_t)tg * AST + m];
                uint2 u1 = pa[(size_t)tg * AST + m + 8];
                uint2 u2 = pa[(size_t)(tg + 4) * AST + m];
                uint2 u3 = pa[(size_t)(tg + 4) * AST + m + 8];
                ah[mi][0] = u0.x; al[mi][0] = u0.y;
                ah[mi][1] = u1.x; al[mi][1] = u1.y;
                ah[mi][2] = u2.x; al[mi][2] = u2.y;
                ah[mi][3] = u3.x; al[mi][3] = u3.y;
            }
#pragma unroll
            for (int ni = 0; ni < 8; ni++) {
                int n = wn * 64 + ni * 8 + g;
                uint2 v0 = pb[(size_t)tg * BSW + n];
                uint2 v1 = pb[(size_t)(tg + 4) * BSW + n];
#pragma unroll
                for (int mi = 0; mi < 2; mi++) {
                    mma16(acc[mi][ni], ah[mi][0], ah[mi][1], ah[mi][2], ah[mi][3], v0.x, v1.x);
                    mma16(acc[mi][ni], ah[mi][0], ah[mi][1], ah[mi][2], ah[mi][3], v0.y, v1.y);
                    mma16(acc[mi][ni], al[mi][0], al[mi][1], al[mi][2], al[mi][3], v0.x, v1.x);
                }
            }
        }
        if (more) {
            int s2 = s ^ 1;
            uint2* pa = sA[s2];
            pa[(size_t)(koA2 + 0) * AST + mA] = make_uint2(a0.x, a0.y);
            pa[(size_t)(koA2 + 1) * AST + mA] = make_uint2(a0.z, a0.w);
            pa[(size_t)(koA2 + 2) * AST + mA] = make_uint2(a1.x, a1.y);
            pa[(size_t)(koA2 + 3) * AST + mA] = make_uint2(a1.z, a1.w);
            uint2* pb = sB2[s2];
            pb[(size_t)kpB * BSW + nB]     = make_uint2(b0.x, b0.y);
            pb[(size_t)kpB * BSW + nB + 1] = make_uint2(b0.z, b0.w);
            pb[(size_t)kpB * BSW + nB + 2] = make_uint2(b1.x, b1.y);
            pb[(size_t)kpB * BSW + nB + 3] = make_uint2(b1.z, b1.w);
        }
        __syncthreads();
    }

#pragma unroll
    for (int mi = 0; mi < 2; mi++)
#pragma unroll
        for (int ni = 0; ni < 8; ni++) {
            int r0 = bm + wm * 32 + mi * 16 + g;
            int c0 = bn + wn * 64 + ni * 8 + 2 * tg;
            float v00 = acc[mi][ni][0], v01 = acc[mi][ni][1];
            float v10 = acc[mi][ni][2], v11 = acc[mi][ni][3];
            if (BIAS) {
                float bv0 = bias[c0], bv1 = bias[c0 + 1];
                v00 += bv0; v01 += bv1; v10 += bv0; v11 += bv1;
            }
            if (RELU) {
                v00 = fmaxf(v00, 0.f); v01 = fmaxf(v01, 0.f);
                v10 = fmaxf(v10, 0.f); v11 = fmaxf(v11, 0.f);
            }
            if (WPK) {
                Cp[(size_t)r0 * (ldc >> 1) + (c0 >> 1)] = sp2(v00, v01);
                Cp[(size_t)(r0 + 8) * (ldc >> 1) + (c0 >> 1)] = sp2(v10, v11);
            }
        }
}

// ---------------- weight packing ----------------
__global__ void k_pack_qkv(const float* __restrict__ qw, const float* __restrict__ kw,
                           const float* __restrict__ vw, const float* __restrict__ qb,
                           const float* __restrict__ kb, const float* __restrict__ vb) {
    int idx = blockIdx.x * 256 + threadIdx.x;
    if (idx < (Ee / 2) * 1536) {
        int n = idx % 1536, kp = idx / 1536;
        const float* W = (n < 512) ? qw : (n < 1024 ? kw : vw);
        int c = n & 511;
        g_wqkv[idx] = sp2(W[(size_t)(2 * kp) * 512 + c], W[(size_t)(2 * kp + 1) * 512 + c]);
    }
    if (idx < 1536)
        g_bqkv[idx] = (idx < 512) ? qb[idx] : (idx < 1024 ? kb[idx - 512] : vb[idx - 1024]);
}

__global__ void k_pack_w(const float* __restrict__ W, uint2* __restrict__ out, int Kp, int N) {
    int idx = blockIdx.x * 256 + threadIdx.x;
    if (idx >= Kp * N) return;
    int n = idx % N, kp = idx / N;
    out[idx] = sp2(W[(size_t)(2 * kp) * N + n], W[(size_t)(2 * kp + 1) * N + n]);
}

// ---------------- embedding + positional encoding ----------------
__global__ void k_embed(const int* __restrict__ inp, const float* __restrict__ emb) {
    int idx = blockIdx.x * blockDim.x + threadIdx.x;
    if (idx >= Bb * Ss * (Ee / 2)) return;
    int ep = idx % (Ee / 2);
    int bs = idx / (Ee / 2);
    int s = bs % Ss;
    int tok = inp[bs];
    int e0 = 2 * ep;
    const float LN1E4 = 9.210340371976184f;
    float freq = expf(-(float)e0 * (LN1E4 / (float)Ee));
    float ang = (float)s * freq;
    float x0 = emb[(size_t)tok * Ee + e0] + sinf(ang);
    float x1 = emb[(size_t)tok * Ee + e0 + 1] + cosf(ang);
    g_x[(size_t)bs * Ee + e0] = x0;
    g_x[(size_t)bs * Ee + e0 + 1] = x1;
    g_xp[(size_t)bs * (Ee / 2) + ep] = sp2(x0, x1);
}

// ---------------- window-summed V from packed QKV ----------------
__global__ void k_build_vs() {
    int idx = blockIdx.x * blockDim.x + threadIdx.x;
    if (idx >= Bb * Hh * (SKk / 2) * (DHh / 2)) return;
    int dp = idx & 31;
    int rest = idx >> 5;
    int kp = rest % (SKk / 2);
    int bh = rest / (SKk / 2);
    int b = bh >> 3, h = bh & 7;
    const uint2* Vp = g_qkvp + (size_t)b * Ss * 768 + 512 + h * 32 + dp;
    int k = 2 * kp;
    float v0[6], v1[6];
#pragma unroll
    for (int r = 0; r < 6; r++) {
        uint2 w = Vp[(size_t)(k + r) * 768];
        v0[r] = blo(w.x) + blo(w.y);
        v1[r] = bhi(w.x) + bhi(w.y);
    }
    float s00 = v0[0] + v0[1] + v0[2] + v0[3] + v0[4];
    float s10 = v0[1] + v0[2] + v0[3] + v0[4] + v0[5];
    float s01 = v1[0] + v1[1] + v1[2] + v1[3] + v1[4];
    float s11 = v1[1] + v1[2] + v1[3] + v1[4] + v1[5];
    uint2* dst = g_vsp + ((size_t)bh * (SP / 2) + kp) * DHh + 2 * dp;
    dst[0] = sp2(s00, s10);
    dst[1] = sp2(s01, s11);
}

// ---------------- fused attention (64-row q-tiles) ----------------
#define FA_OFF_Q  0                          // 32 x 84 uint2  = 21504
#define FA_OFF_K  21504                      // 32 x 68 uint2  = 17408
#define FA_OFF_G  38912                      // 68 x 132 float = 35904
#define FA_OFF_P  74816                      // 32 x 68 uint2  = 17408
#define FA_OFF_V  92224                      // 32 x 68 uint2  = 17408
#define FA_OFF_S  109632                     // sFac[64] + sLf[64]
#define FA_SMEM   110144

__launch_bounds__(256)
__global__ void k_fattn() {
    extern __shared__ char dyn[];
    uint2* sQ = (uint2*)(dyn + FA_OFF_Q);
    uint2* sK = (uint2*)(dyn + FA_OFF_K);
    float* sG = (float*)(dyn + FA_OFF_G);
    uint2* sP = (uint2*)(dyn + FA_OFF_P);
    uint2* sV = (uint2*)(dyn + FA_OFF_V);
    float* sFac = (float*)(dyn + FA_OFF_S);
    float* sLf = sFac + 64;

    int qt = blockIdx.x;
    int bh = blockIdx.y;
    int b = bh >> 3, h = bh & 7;
    int q0 = qt * 64;
    const uint2* Qb = g_qkvp + (size_t)b * Ss * 768 + h * 32;
    const uint2* Kb = g_qkvp + (size_t)b * Ss * 768 + 256 + h * 32;
    const uint2* Vb = g_vsp + (size_t)bh * (SP / 2) * DHh;

    int t = threadIdx.x, lane = t & 31, wid = t >> 5;
    int wm = wid & 3, wn = wid >> 2;
    int g = lane >> 2, tg = lane & 3;
    float acc[4][4] = {};
    float m_run = -1e30f, l_run = 0.f;
    int srow = t >> 2, kbase = (t & 3) * 16;

    // load Q tile: rows 0..67 = global q0-2..q0+65; rows 68..79 zero
    {
        int dpq = (t & 3) * 8;
        int rr = t >> 2;
#pragma unroll
        for (int rb = 0; rb < 80; rb += 64) {
            int r = rb + rr;
            if (r < 80) {
                int gr = q0 - 2 + r;
                bool ok = (r < 68) && (gr >= 0) && (gr < Ss);
#pragma unroll
                for (int u = 0; u < 8; u += 2) {
                    uint4 v = make_uint4(0, 0, 0, 0);
                    if (ok) v = *(const uint4*)(Qb + (size_t)gr * 768 + dpq + u);
                    sQ[(size_t)(dpq + u) * QST2 + r] = make_uint2(v.x, v.y);
                    sQ[(size_t)(dpq + u + 1) * QST2 + r] = make_uint2(v.z, v.w);
                }
            }
        }
    }
    // load K panel 0
    {
        int r = t >> 2, dpq = (t & 3) * 8;
        const uint2* src = Kb + (size_t)r * 768 + dpq;
#pragma unroll
        for (int u = 0; u < 8; u += 2) {
            uint4 v = *(const uint4*)(src + u);
            sK[(size_t)(dpq + u) * KST + r] = make_uint2(v.x, v.y);
            sK[(size_t)(dpq + u + 1) * KST + r] = make_uint2(v.z, v.w);
        }
    }
    __syncthreads();

    // gram panel 0 -> ring slot 0
    {
        float accg[5][4] = {};
        int nb = wid * 8 + g;
#pragma unroll
        for (int c = 0; c < 4; c++) {
            uint2 v0 = sK[(size_t)(c * 8 + tg) * KST + nb];
            uint2 v1 = sK[(size_t)(c * 8 + tg + 4) * KST + nb];
#pragma unroll
            for (int mi = 0; mi < 5; mi++) {
                int m = mi * 16 + g;
                uint2 u0 = sQ[(size_t)(c * 8 + tg) * QST2 + m];
                uint2 u1 = sQ[(size_t)(c * 8 + tg) * QST2 + m + 8];
                uint2 u2 = sQ[(size_t)(c * 8 + tg + 4) * QST2 + m];
                uint2 u3 = sQ[(size_t)(c * 8 + tg + 4) * QST2 + m + 8];
                mma16(accg[mi], u0.x, u1.x, u2.x, u3.x, v0.x, v1.x);
                mma16(accg[mi], u0.x, u1.x, u2.x, u3.x, v0.y, v1.y);
                mma16(accg[mi], u0.y, u1.y, u2.y, u3.y, v0.x, v1.x);
            }
        }
        int c0 = wid * 8 + 2 * tg;
#pragma unroll
        for (int mi = 0; mi < 5; mi++) {
            int r0 = mi * 16 + g;
            if (r0 < 68) {
                sG[r0 * GS2 + c0] = accg[mi][0] * SCALEc;
                sG[r0 * GS2 + c0 + 1] = accg[mi][1] * SCALEc;
            }
            if (r0 + 8 < 68) {
                sG[(r0 + 8) * GS2 + c0] = accg[mi][2] * SCALEc;
                sG[(r0 + 8) * GS2 + c0 + 1] = accg[mi][3] * SCALEc;
            }
        }
    }
    __syncthreads();

    for (int it = 0; it < 32; it++) {
        int k0 = it * 64;
        bool more = (it < 31);

        if (more) {
            int r = t >> 2, dpq = (t & 3) * 8;
            const uint2* src = Kb + (size_t)((it + 1) * 64 + r) * 768 + dpq;
#pragma unroll
            for (int u = 0; u < 8; u += 2) {
                uint4 v = *(const uint4*)(src + u);
                sK[(size_t)(dpq + u) * KST + r] = make_uint2(v.x, v.y);
                sK[(size_t)(dpq + u + 1) * KST + r] = make_uint2(v.z, v.w);
            }
        }
        {
            int kpB = t >> 5, dB = (t & 31) * 2;
#pragma unroll
            for (int r = 0; r < 4; r++) {
                int kp = r * 8 + kpB;
                uint4 v = *(const uint4*)(Vb + (size_t)((k0 >> 1) + kp) * DHh + dB);
                sV[(size_t)kp * VST + dB] = make_uint2(v.x, v.y);
                sV[(size_t)kp * VST + dB + 1] = make_uint2(v.z, v.w);
            }
        }
        __syncthreads();   // A

        if (more) {
            float accg[5][4] = {};
            int nb = wid * 8 + g;
#pragma unroll
            for (int c = 0; c < 4; c++) {
                uint2 v0 = sK[(size_t)(c * 8 + tg) * KST + nb];
                uint2 v1 = sK[(size_t)(c * 8 + tg + 4) * KST + nb];
#pragma unroll
                for (int mi = 0; mi < 5; mi++) {
                    int m = mi * 16 + g;
                    uint2 u0 = sQ[(size_t)(c * 8 + tg) * QST2 + m];
                    uint2 u1 = sQ[(size_t)(c * 8 + tg) * QST2 + m + 8];
                    uint2 u2 = sQ[(size_t)(c * 8 + tg + 4) * QST2 + m];
                    uint2 u3 = sQ[(size_t)(c * 8 + tg + 4) * QST2 + m + 8];
                    mma16(accg[mi], u0.x, u1.x, u2.x, u3.x, v0.x, v1.x);
                    mma16(accg[mi], u0.x, u1.x, u2.x, u3.x, v0.y, v1.y);
                    mma16(accg[mi], u0.y, u1.y, u2.y, u3.y, v0.x, v1.x);
                }
            }
            int c0 = ((it + 1) & 1) * 64 + wid * 8 + 2 * tg;
#pragma unroll
            for (int mi = 0; mi < 5; mi++) {
                int r0 = mi * 16 + g;
                if (r0 < 68) {
                    sG[r0 * GS2 + c0] = accg[mi][0] * SCALEc;
                    sG[r0 * GS2 + c0 + 1] = accg[mi][1] * SCALEc;
                }
                if (r0 + 8 < 68) {
                    sG[(r0 + 8) * GS2 + c0] = accg[mi][2] * SCALEc;
                    sG[(r0 + 8) * GS2 + c0 + 1] = accg[mi][3] * SCALEc;
                }
            }
        }
        __syncthreads();   // B

        // scores: vectorized shift-sum (5 rows x 5 float4 + register shifts)
        float sv[16];
#pragma unroll
        for (int i = 0; i < 16; i++) sv[i] = 0.f;
        int cb0 = ((it & 1) << 6) + kbase;
#pragma unroll
        for (int j = 0; j < Ww; j++) {
            const float* rp = sG + (srow + j) * GS2;
            float rr[20];
#pragma unroll
            for (int m = 0; m < 5; m++) {
                float4 v = *(const float4*)(rp + ((cb0 + 4 * m) & 127));
                rr[4 * m + 0] = v.x; rr[4 * m + 1] = v.y;
                rr[4 * m + 2] = v.z; rr[4 * m + 3] = v.w;
            }
#pragma unroll
            for (int i = 0; i < 16; i++) sv[i] += rr[i + j];
        }
        float lmax = -1e30f;
#pragma unroll
        for (int i = 0; i < 16; i++) {
            if (k0 + kbase + i >= SKk) sv[i] = -1e30f;
            lmax = fmaxf(lmax, sv[i]);
        }
        lmax = fmaxf(lmax, __shfl_xor_sync(0xffffffffu, lmax, 1));
        lmax = fmaxf(lmax, __shfl_xor_sync(0xffffffffu, lmax, 2));
        float mnew = fmaxf(m_run, lmax);
        float lsum = 0.f;
#pragma unroll
        for (int i = 0; i < 16; i += 2) {
            float p0 = __expf(sv[i] - mnew);
            float p1 = __expf(sv[i + 1] - mnew);
            lsum += p0 + p1;
            sP[(size_t)((kbase >> 1) + (i >> 1)) * PST + srow] = sp2(p0, p1);
        }
        lsum += __shfl_xor_sync(0xffffffffu, lsum, 1);
        lsum += __shfl_xor_sync(0xffffffffu, lsum, 2);
        float fac = __expf(m_run - mnew);
        l_run = l_run * fac + lsum;
        m_run = mnew;
        if ((t & 3) == 0) sFac[srow] = fac;
        __syncthreads();   // C

        {
            float f0 = sFac[wm * 16 + g];
            float f1 = sFac[wm * 16 + g + 8];
#pragma unroll
            for (int ni = 0; ni < 4; ni++) {
                acc[ni][0] *= f0; acc[ni][1] *= f0;
                acc[ni][2] *= f1; acc[ni][3] *= f1;
            }
#pragma unroll
            for (int c = 0; c < 4; c++) {
                int m = wm * 16 + g;
                uint2 u0 = sP[(size_t)(c * 8 + tg) * PST + m];
                uint2 u1 = sP[(size_t)(c * 8 + tg) * PST + m + 8];
                uint2 u2 = sP[(size_t)(c * 8 + tg + 4) * PST + m];
                uint2 u3 = sP[(size_t)(c * 8 + tg + 4) * PST + m + 8];
#pragma unroll
                for (int ni = 0; ni < 4; ni++) {
                    int n = wn * 32 + ni * 8 + g;
                    uint2 v0 = sV[(size_t)(c * 8 + tg) * VST + n];
                    uint2 v1 = sV[(size_t)(c * 8 + tg + 4) * VST + n];
                    mma16(acc[ni], u0.x, u1.x, u2.x, u3.x, v0.x, v1.x);
                    mma16(acc[ni], u0.x, u1.x, u2.x, u3.x, v0.y, v1.y);
                    mma16(acc[ni], u0.y, u1.y, u2.y, u3.y, v0.x, v1.x);
                }
            }
        }
        __syncthreads();   // D
    }

    if ((t & 3) == 0) sLf[srow] = l_run;
    __syncthreads();

    float inv0 = 1.f / sLf[wm * 16 + g];
    float inv1 = 1.f / sLf[wm * 16 + g + 8];
    float* Cb = g_attn + (size_t)b * Ss * Ee + h * DHh;
#pragma unroll
    for (int ni = 0; ni < 4; ni++) {
        int r0 = q0 + wm * 16 + g;
        int c0 = wn * 32 + ni * 8 + 2 * tg;
        Cb[(size_t)r0 * Ee + c0] = acc[ni][0] * inv0;
        Cb[(size_t)r0 * Ee + c0 + 1] = acc[ni][1] * inv0;
        Cb[(size_t)(r0 + 8) * Ee + c0] = acc[ni][2] * inv1;
        Cb[(size_t)(r0 + 8) * Ee + c0 + 1] = acc[ni][3] * inv1;
    }
}

// ---------------- LayerNorm: one warp per row, shuffle-only reductions ----------------
__launch_bounds__(256)
__global__ void k_ln(const float* __restrict__ in, const float* __restrict__ w,
                     const float* __restrict__ bz, float* __restrict__ out,
                     uint2* __restrict__ outp) {
    int row = blockIdx.x * 8 + (threadIdx.x >> 5);
    int lane = threadIdx.x & 31;
    const float* x = in + (size_t)row * Ee;

    float4 v[4];
#pragma unroll
    for (int j = 0; j < 4; j++)
        v[j] = *(const float4*)(x + 4 * (lane + j * 32));

    float s = 0.f;
#pragma unroll
    for (int j = 0; j < 4; j++) s += v[j].x + v[j].y + v[j].z + v[j].w;
#pragma unroll
    for (int off = 16; off > 0; off >>= 1)
        s += __shfl_xor_sync(0xffffffffu, s, off);
    float m = s * (1.0f / Ee);

    float vs = 0.f;
#pragma unroll
    for (int j = 0; j < 4; j++) {
        float d0 = v[j].x - m, d1 = v[j].y - m, d2 = v[j].z - m, d3 = v[j].w - m;
        vs += d0 * d0 + d1 * d1 + d2 * d2 + d3 * d3;
    }
#pragma unroll
    for (int off = 16; off > 0; off >>= 1)
        vs += __shfl_xor_sync(0xffffffffu, vs, off);
    float inv = rsqrtf(vs * (1.0f / Ee) + 1e-5f);

#pragma unroll
    for (int j = 0; j < 4; j++) {
        int c = 4 * (lane + j * 32);
        float4 wv = *(const float4*)(w + c);
        float4 bv = *(const float4*)(bz + c);
        float y0 = (v[j].x - m) * inv * wv.x + bv.x;
        float y1 = (v[j].y - m) * inv * wv.y + bv.y;
        float y2 = (v[j].z - m) * inv * wv.z + bv.z;
        float y3 = (v[j].w - m) * inv * wv.w + bv.w;
        *(float4*)(out + (size_t)row * Ee + c) = make_float4(y0, y1, y2, y3);
        uint2 p0 = sp2(y0, y1);
        uint2 p1 = sp2(y2, y3);
        *(uint4*)(outp + (size_t)row * (Ee / 2) + (c >> 1)) =
            make_uint4(p0.x, p0.y, p1.x, p1.y);
    }
}

// ---------------- output head ----------------
__launch_bounds__(256)
__global__ void k_out_partial(const float* __restrict__ ow) {
    int b = blockIdx.y, c = blockIdx.x;
    const int per = (Ss * Ee) / CHUNKS;
    const float* x = g_x + (size_t)b * Ss * Ee + (size_t)c * per;
    const float* wr = ow + (size_t)c * per * OUTo;
    int t = threadIdx.x;
    float acc[OUTo] = {};
    for (int i = t; i < per; i += 256) {
        float xv = x[i];
#pragma unroll
        for (int o = 0; o < OUTo; o++) acc[o] = fmaf(xv, wr[(size_t)i * OUTo + o], acc[o]);
    }
    __shared__ float red[256 * OUTo];
#pragma unroll
    for (int o = 0; o < OUTo; o++) red[t * OUTo + o] = acc[o];
    __syncthreads();
    for (int off = 128; off > 0; off >>= 1) {
        if (t < off) {
#pragma unroll
            for (int o = 0; o < OUTo; o++)
                red[t * OUTo + o] += red[(t + off) * OUTo + o];
        }
        __syncthreads();
    }
    if (t == 0) {
#pragma unroll
        for (int o = 0; o < OUTo; o++)
            g_part[((size_t)b * CHUNKS + c) * OUTo + o] = red[o];
    }
}

__global__ void k_out_final(const float* __restrict__ ob, float* __restrict__ out) {
    int b = blockIdx.x;
    int o = threadIdx.x;
    if (o < OUTo) {
        float s = ob[o];
        for (int c = 0; c < CHUNKS; c++) s += g_part[(b * CHUNKS + c) * OUTo + o];
        out[b * OUTo + o] = s;
    }
}

// ---------------- host launcher ----------------
extern "C" void kernel_launch(void* const* d_in, const int* in_sizes, int n_in,
                              void* d_out, int out_size) {
    const int*   inputs = (const int*)d_in[0];
    const float* emb    = (const float*)d_in[1];
    const float* ln_w   = (const float*)d_in[2];
    const float* ln_b   = (const float*)d_in[3];
    const float* q_w    = (const float*)d_in[4];
    const float* q_b    = (const float*)d_in[5];
    const float* k_w    = (const float*)d_in[6];
    const float* k_b    = (const float*)d_in[7];
    const float* v_w    = (const float*)d_in[8];
    const float* v_b    = (const float*)d_in[9];
    const float* fc1_w  = (const float*)d_in[10];
    const float* fc1_b  = (const float*)d_in[11];
    const float* fc2_w  = (const float*)d_in[12];
    const float* fc2_b  = (const float*)d_in[13];
    const float* out_w  = (const float*)d_in[14];
    const float* out_b  = (const float*)d_in[15];
    float* out = (float*)d_out;

    static int smem_set = 0;
    if (!smem_set) {
        cudaFuncSetAttribute(k_fattn, cudaFuncAttributeMaxDynamicSharedMemorySize, FA_SMEM);
        smem_set = 1;
    }

    float *px, *pattn, *pbqkv;
    uint2 *pxp, *pqkvp, *phidp, *pwqkv, *pwfc1, *pwfc2;
    cudaGetSymbolAddress((void**)&px, g_x);
    cudaGetSymbolAddress((void**)&pattn, g_attn);
    cudaGetSymbolAddress((void**)&pxp, g_xp);
    cudaGetSymbolAddress((void**)&pqkvp, g_qkvp);
    cudaGetSymbolAddress((void**)&phidp, g_hidp);
    cudaGetSymbolAddress((void**)&pwqkv, g_wqkv);
    cudaGetSymbolAddress((void**)&pwfc1, g_wfc1);
    cudaGetSymbolAddress((void**)&pwfc2, g_wfc2);
    cudaGetSymbolAddress((void**)&pbqkv, g_bqkv);

    const int M = Bb * Ss;  // 4096

    k_pack_qkv<<<((Ee / 2) * 1536 + 255) / 256, 256>>>(q_w, k_w, v_w, q_b, k_b, v_b);
    k_pack_w<<<((Ee / 2) * HIDh + 255) / 256, 256>>>(fc1_w, pwfc1, Ee / 2, HIDh);
    k_pack_w<<<((HIDh / 2) * Ee + 255) / 256, 256>>>(fc2_w, pwfc2, HIDh / 2, Ee);

    k_embed<<<(Bb * Ss * (Ee / 2) + 255) / 256, 256>>>(inputs, emb);

    for (int l = 0; l < Ll; l++) {
        // QKV: 128x128 tiles, packed-only output
        k_gemm128<1, 0, 1><<<dim3(1536 / 128, M / 128), 256>>>(
            pxp, pwqkv, pbqkv, pqkvp, Ee, Ee / 2, 1536, 1536);

        k_build_vs<<<(Bb * Hh * (SKk / 2) * (DHh / 2) + 255) / 256, 256>>>();

        dim3 gf(Ss / 64, Bb * Hh);
        k_fattn<<<gf, 256, FA_SMEM>>>();

        k_ln<<<M / 8, 256>>>(pattn, ln_w, ln_b, px, pxp);

        // fc1: 128x128 tiles, relu, packed-only output
        k_gemm128<1, 1, 1><<<dim3(HIDh / 128, M / 128), 256>>>(
            pxp, pwfc1, fc1_b, phidp, Ee, Ee / 2, HIDh, HIDh);
        // fc2: 64-wide core (residual + fp32 out), 256 CTAs
        dim3 g2(Ee / 64, M / 128);
        k_fc2<<<g2, 256>>>(fc2_b);

        k_ln<<<M / 8, 256>>>(pattn, ln_w, ln_b, px, pxp);
    }

    dim3 go(CHUNKS, Bb);
    k_out_partial<<<go, 256>>>(out_w);
    k_out_final<<<Bb, 32>>>(out_b, out);
}

// round 12
// speedup vs baseline: 1.1054x; 1.0514x over previous
#include <cuda_runtime.h>
#include <cuda_bf16.h>
#include <cuda_fp16.h>
#include <math.h>
#include <stdint.h>

#define Bb 2
#define Ss 2048
#define Ee 512
#define Hh 8
#define DHh 64
#define Ww 5
#define PADp 2
#define SKk 2044
#define HIDh 2048
#define Ll 6
#define OUTo 6
#define SCALEc 0.125f
#define CHUNKS 128
#define SP 2048

#define AST 132   // smem A row stride (uint2)
#define BST 68    // smem B row stride (uint2), 64-wide core
#define BSW 132   // smem B row stride (uint2), 128-wide core
// fattn strides
#define QST2 84
#define KST 68
#define PST 68
#define VST 68
#define GS2 132

// ---------------- scratch ----------------
__device__ float g_x[Bb * Ss * Ee];
__device__ uint2 g_xp[Bb * Ss * (Ee / 2)];               // bf16 hi/lo (GEMM operand)
__device__ uint2 g_qkvp[Bb * Ss * 768];                  // fp16 hi/lo (attention operand)
__device__ uint2 g_hidp[(size_t)Bb * Ss * (HIDh / 2)];   // bf16 hi/lo
__device__ uint2 g_vsp[(size_t)Bb * Hh * (SP / 2) * DHh];// fp16 hi/lo
__device__ float g_attn[Bb * Ss * Ee];
__device__ float g_part[Bb * CHUNKS * OUTo];
__device__ uint2 g_wqkv[(Ee / 2) * 1536];
__device__ float g_bqkv[1536];
__device__ uint2 g_wfc1[(Ee / 2) * HIDh];
__device__ uint2 g_wfc2[(HIDh / 2) * Ee];

// ---------------- bf16 split/pack ----------------
__device__ __forceinline__ uint2 sp2(float x, float y) {
    __nv_bfloat16 xh = __float2bfloat16_rn(x);
    __nv_bfloat16 yh = __float2bfloat16_rn(y);
    float xr = x - __bfloat162float(xh);
    float yr = y - __bfloat162float(yh);
    __nv_bfloat16 xl = __float2bfloat16_rn(xr);
    __nv_bfloat16 yl = __float2bfloat16_rn(yr);
    uint2 w;
    w.x = ((uint32_t)__bfloat16_as_ushort(yh) << 16) | (uint32_t)__bfloat16_as_ushort(xh);
    w.y = ((uint32_t)__bfloat16_as_ushort(yl) << 16) | (uint32_t)__bfloat16_as_ushort(xl);
    return w;
}

// ---------------- fp16 split/pack ----------------
__device__ __forceinline__ uint32_t h2pack(float x, float y) {
    __half2 h = __floats2half2_rn(x, y);   // low = x, high = y
    return *(uint32_t*)&h;
}
__device__ __forceinline__ float2 h2f2(uint32_t u) {
    __half2 h = *(__half2*)&u;
    return __half22float2(h);
}
__device__ __forceinline__ uint2 sph2(float x, float y) {
    float hx = __half2float(__float2half_rn(x));
    float hy = __half2float(__float2half_rn(y));
    uint2 w;
    w.x = h2pack(hx, hy);
    w.y = h2pack(x - hx, y - hy);
    return w;
}

__device__ __forceinline__ void mma16(float c[4], uint32_t a0, uint32_t a1, uint32_t a2,
                                      uint32_t a3, uint32_t b0, uint32_t b1) {
    asm volatile(
        "mma.sync.aligned.m16n8k16.row.col.f32.bf16.bf16.f32 "
        "{%0,%1,%2,%3},{%4,%5,%6,%7},{%8,%9},{%0,%1,%2,%3};"
        : "+f"(c[0]), "+f"(c[1]), "+f"(c[2]), "+f"(c[3])
        : "r"(a0), "r"(a1), "r"(a2), "r"(a3), "r"(b0), "r"(b1));
}

__device__ __forceinline__ void mma16h(float c[4], uint32_t a0, uint32_t a1, uint32_t a2,
                                       uint32_t a3, uint32_t b0, uint32_t b1) {
    asm volatile(
        "mma.sync.aligned.m16n8k16.row.col.f32.f16.f16.f32 "
        "{%0,%1,%2,%3},{%4,%5,%6,%7},{%8,%9},{%0,%1,%2,%3};"
        : "+f"(c[0]), "+f"(c[1]), "+f"(c[2]), "+f"(c[3])
        : "r"(a0), "r"(a1), "r"(a2), "r"(a3), "r"(b0), "r"(b1));
}

// one 16-k chunk over 128x64 tile (warp tile 32x32) -- 64-wide core (bf16x3)
__device__ __forceinline__ void mma_chunk(const uint2* sA, const uint2* sB,
                                          int wm, int wn, int lane, float acc[2][4][4]) {
    int g = lane >> 2, tg = lane & 3;
    uint32_t ah[2][4], al[2][4];
#pragma unroll
    for (int mi = 0; mi < 2; mi++) {
        int m = wm * 32 + mi * 16 + g;
        uint2 u0 = sA[(size_t)tg * AST + m];
        uint2 u1 = sA[(size_t)tg * AST + m + 8];
        uint2 u2 = sA[(size_t)(tg + 4) * AST + m];
        uint2 u3 = sA[(size_t)(tg + 4) * AST + m + 8];
        ah[mi][0] = u0.x; al[mi][0] = u0.y;
        ah[mi][1] = u1.x; al[mi][1] = u1.y;
        ah[mi][2] = u2.x; al[mi][2] = u2.y;
        ah[mi][3] = u3.x; al[mi][3] = u3.y;
    }
#pragma unroll
    for (int ni = 0; ni < 4; ni++) {
        int n = wn * 32 + ni * 8 + g;
        uint2 v0 = sB[(size_t)tg * BST + n];
        uint2 v1 = sB[(size_t)(tg + 4) * BST + n];
#pragma unroll
        for (int mi = 0; mi < 2; mi++) {
            mma16(acc[mi][ni], ah[mi][0], ah[mi][1], ah[mi][2], ah[mi][3], v0.x, v1.x);
            mma16(acc[mi][ni], ah[mi][0], ah[mi][1], ah[mi][2], ah[mi][3], v0.y, v1.y);
            mma16(acc[mi][ni], al[mi][0], al[mi][1], al[mi][2], al[mi][3], v0.x, v1.x);
        }
    }
}

// ---------------- 64-wide packed GEMM core (fc2, bf16x3) ----------------
__launch_bounds__(256)
__global__ void k_fc2(const float* __restrict__ bias) {
    const uint2* __restrict__ A = g_hidp;
    const uint2* __restrict__ B = g_wfc2;
    const float* __restrict__ res = g_x;
    float* __restrict__ C = g_attn;
    const int K = HIDh, lda2 = HIDh / 2, ldb2 = Ee, ldc = Ee;

    __shared__ uint2 sA[2][8 * AST];
    __shared__ uint2 sB[2][8 * BST];
    int t = threadIdx.x, lane = t & 31, wid = t >> 5;
    int wm = wid & 3, wn = wid >> 2;
    int bm = blockIdx.y * 128, bn = blockIdx.x * 64;
    float acc[2][4][4] = {};

    int mA = t & 127, koA2 = (t >> 7) * 4;
    const uint2* Arow = A + (size_t)(bm + mA) * lda2 + koA2;
    int kpB = t >> 5, nB = (t & 31) * 2;
    const uint2* Bp = B + (size_t)kpB * ldb2 + bn + nB;

    uint4 a0 = *(const uint4*)(Arow);
    uint4 a1 = *(const uint4*)(Arow + 2);
    uint4 b0 = *(const uint4*)(Bp);

    {
        uint2* pa = sA[0];
        pa[(size_t)(koA2 + 0) * AST + mA] = make_uint2(a0.x, a0.y);
        pa[(size_t)(koA2 + 1) * AST + mA] = make_uint2(a0.z, a0.w);
        pa[(size_t)(koA2 + 2) * AST + mA] = make_uint2(a1.x, a1.y);
        pa[(size_t)(koA2 + 3) * AST + mA] = make_uint2(a1.z, a1.w);
        uint2* pb = sB[0];
        pb[(size_t)kpB * BST + nB]     = make_uint2(b0.x, b0.y);
        pb[(size_t)kpB * BST + nB + 1] = make_uint2(b0.z, b0.w);
    }
    __syncthreads();

    int nch = K >> 4;
    for (int ch = 0; ch < nch; ch++) {
        int s = ch & 1;
        bool more = (ch + 1 < nch);
        if (more) {
            int off = (ch + 1) * 8;
            a0 = *(const uint4*)(Arow + off);
            a1 = *(const uint4*)(Arow + off + 2);
            b0 = *(const uint4*)(Bp + (size_t)(ch + 1) * 8 * ldb2);
        }
        mma_chunk(sA[s], sB[s], wm, wn, lane, acc);
        if (more) {
            int s2 = s ^ 1;
            uint2* pa = sA[s2];
            pa[(size_t)(koA2 + 0) * AST + mA] = make_uint2(a0.x, a0.y);
            pa[(size_t)(koA2 + 1) * AST + mA] = make_uint2(a0.z, a0.w);
            pa[(size_t)(koA2 + 2) * AST + mA] = make_uint2(a1.x, a1.y);
            pa[(size_t)(koA2 + 3) * AST + mA] = make_uint2(a1.z, a1.w);
            uint2* pb = sB[s2];
            pb[(size_t)kpB * BST + nB]     = make_uint2(b0.x, b0.y);
            pb[(size_t)kpB * BST + nB + 1] = make_uint2(b0.z, b0.w);
        }
        __syncthreads();
    }

    int g = lane >> 2, tg = lane & 3;
#pragma unroll
    for (int mi = 0; mi < 2; mi++)
#pragma unroll
        for (int ni = 0; ni < 4; ni++) {
            int r0 = bm + wm * 32 + mi * 16 + g;
            int c0 = bn + wn * 32 + ni * 8 + 2 * tg;
            float bv0 = bias[c0], bv1 = bias[c0 + 1];
            float v00 = acc[mi][ni][0] + bv0 + res[(size_t)r0 * ldc + c0];
            float v01 = acc[mi][ni][1] + bv1 + res[(size_t)r0 * ldc + c0 + 1];
            float v10 = acc[mi][ni][2] + bv0 + res[(size_t)(r0 + 8) * ldc + c0];
            float v11 = acc[mi][ni][3] + bv1 + res[(size_t)(r0 + 8) * ldc + c0 + 1];
            C[(size_t)r0 * ldc + c0] = v00;
            C[(size_t)r0 * ldc + c0 + 1] = v01;
            C[(size_t)(r0 + 8) * ldc + c0] = v10;
            C[(size_t)(r0 + 8) * ldc + c0 + 1] = v11;
        }
}

// ---------------- 128x128 packed GEMM (qkv, fc1; bf16x3; PKH: fp16 vs bf16 out) ----
template <int BIAS, int RELU, int WPK, int PKH>
__launch_bounds__(256, 2)
__global__ void k_gemm128(const uint2* __restrict__ A, const uint2* __restrict__ B,
                          const float* __restrict__ bias,
                          uint2* __restrict__ Cp,
                          int K, int lda2, int ldb2, int ldc) {
    __shared__ uint2 sA[2][8 * AST];
    __shared__ uint2 sB2[2][8 * BSW];
    int t = threadIdx.x, lane = t & 31, wid = t >> 5;
    int wm = wid & 3, wn = wid >> 2;
    int g = lane >> 2, tg = lane & 3;
    int bm = blockIdx.y * 128, bn = blockIdx.x * 128;
    float acc[2][8][4] = {};

    int mA = t & 127, koA2 = (t >> 7) * 4;
    const uint2* Arow = A + (size_t)(bm + mA) * lda2 + koA2;
    int kpB = t >> 5, nB = (t & 31) * 4;
    const uint2* Bp = B + (size_t)kpB * ldb2 + bn + nB;

    uint4 a0 = *(const uint4*)(Arow);
    uint4 a1 = *(const uint4*)(Arow + 2);
    uint4 b0 = *(const uint4*)(Bp);
    uint4 b1 = *(const uint4*)(Bp + 2);

    {
        uint2* pa = sA[0];
        pa[(size_t)(koA2 + 0) * AST + mA] = make_uint2(a0.x, a0.y);
        pa[(size_t)(koA2 + 1) * AST + mA] = make_uint2(a0.z, a0.w);
        pa[(size_t)(koA2 + 2) * AST + mA] = make_uint2(a1.x, a1.y);
        pa[(size_t)(koA2 + 3) * AST + mA] = make_uint2(a1.z, a1.w);
        uint2* pb = sB2[0];
        pb[(size_t)kpB * BSW + nB]     = make_uint2(b0.x, b0.y);
        pb[(size_t)kpB * BSW + nB + 1] = make_uint2(b0.z, b0.w);
        pb[(size_t)kpB * BSW + nB + 2] = make_uint2(b1.x, b1.y);
        pb[(size_t)kpB * BSW + nB + 3] = make_uint2(b1.z, b1.w);
    }
    __syncthreads();

    int nch = K >> 4;
    for (int ch = 0; ch < nch; ch++) {
        int s = ch & 1;
        bool more = (ch + 1 < nch);
        if (more) {
            int off = (ch + 1) * 8;
            a0 = *(const uint4*)(Arow + off);
            a1 = *(const uint4*)(Arow + off + 2);
            const uint2* Bn = Bp + (size_t)(ch + 1) * 8 * ldb2;
            b0 = *(const uint4*)(Bn);
            b1 = *(const uint4*)(Bn + 2);
        }
        {
            const uint2* pa = sA[s];
            const uint2* pb = sB2[s];
            uint32_t ah[2][4], al[2][4];
#pragma unroll
            for (int mi = 0; mi < 2; mi++) {
                int m = wm * 32 + mi * 16 + g;
                uint2 u0 = pa[(size_t)tg * AST + m];
                uint2 u1 = pa[(size_t)tg * AST + m + 8];
                uint2 u2 = pa[(size_t)(tg + 4) * AST + m];
                uint2 u3 = pa[(size_t)(tg + 4) * AST + m + 8];
                ah[mi][0] = u0.x; al[mi][0] = u0.y;
                ah[mi][1] = u1.x; al[mi][1] = u1.y;
                ah[mi][2] = u2.x; al[mi][2] = u2.y;
                ah[mi][3] = u3.x; al[mi][3] = u3.y;
            }
#pragma unroll
            for (int ni = 0; ni < 8; ni++) {
                int n = wn * 64 + ni * 8 + g;
                uint2 v0 = pb[(size_t)tg * BSW + n];
                uint2 v1 = pb[(size_t)(tg + 4) * BSW + n];
#pragma unroll
                for (int mi = 0; mi < 2; mi++) {
                    mma16(acc[mi][ni], ah[mi][0], ah[mi][1], ah[mi][2], ah[mi][3], v0.x, v1.x);
                    mma16(acc[mi][ni], ah[mi][0], ah[mi][1], ah[mi][2], ah[mi][3], v0.y, v1.y);
                    mma16(acc[mi][ni], al[mi][0], al[mi][1], al[mi][2], al[mi][3], v0.x, v1.x);
                }
            }
        }
        if (more) {
            int s2 = s ^ 1;
            uint2* pa = sA[s2];
            pa[(size_t)(koA2 + 0) * AST + mA] = make_uint2(a0.x, a0.y);
            pa[(size_t)(koA2 + 1) * AST + mA] = make_uint2(a0.z, a0.w);
            pa[(size_t)(koA2 + 2) * AST + mA] = make_uint2(a1.x, a1.y);
            pa[(size_t)(koA2 + 3) * AST + mA] = make_uint2(a1.z, a1.w);
            uint2* pb = sB2[s2];
            pb[(size_t)kpB * BSW + nB]     = make_uint2(b0.x, b0.y);
            pb[(size_t)kpB * BSW + nB + 1] = make_uint2(b0.z, b0.w);
            pb[(size_t)kpB * BSW + nB + 2] = make_uint2(b1.x, b1.y);
            pb[(size_t)kpB * BSW + nB + 3] = make_uint2(b1.z, b1.w);
        }
        __syncthreads();
    }

#pragma unroll
    for (int mi = 0; mi < 2; mi++)
#pragma unroll
        for (int ni = 0; ni < 8; ni++) {
            int r0 = bm + wm * 32 + mi * 16 + g;
            int c0 = bn + wn * 64 + ni * 8 + 2 * tg;
            float v00 = acc[mi][ni][0], v01 = acc[mi][ni][1];
            float v10 = acc[mi][ni][2], v11 = acc[mi][ni][3];
            if (BIAS) {
                float bv0 = bias[c0], bv1 = bias[c0 + 1];
                v00 += bv0; v01 += bv1; v10 += bv0; v11 += bv1;
            }
            if (RELU) {
                v00 = fmaxf(v00, 0.f); v01 = fmaxf(v01, 0.f);
                v10 = fmaxf(v10, 0.f); v11 = fmaxf(v11, 0.f);
            }
            if (WPK) {
                if (PKH) {
                    Cp[(size_t)r0 * (ldc >> 1) + (c0 >> 1)] = sph2(v00, v01);
                    Cp[(size_t)(r0 + 8) * (ldc >> 1) + (c0 >> 1)] = sph2(v10, v11);
                } else {
                    Cp[(size_t)r0 * (ldc >> 1) + (c0 >> 1)] = sp2(v00, v01);
                    Cp[(size_t)(r0 + 8) * (ldc >> 1) + (c0 >> 1)] = sp2(v10, v11);
                }
            }
        }
}

// ---------------- weight packing ----------------
__global__ void k_pack_qkv(const float* __restrict__ qw, const float* __restrict__ kw,
                           const float* __restrict__ vw, const float* __restrict__ qb,
                           const float* __restrict__ kb, const float* __restrict__ vb) {
    int idx = blockIdx.x * 256 + threadIdx.x;
    if (idx < (Ee / 2) * 1536) {
        int n = idx % 1536, kp = idx / 1536;
        const float* W = (n < 512) ? qw : (n < 1024 ? kw : vw);
        int c = n & 511;
        g_wqkv[idx] = sp2(W[(size_t)(2 * kp) * 512 + c], W[(size_t)(2 * kp + 1) * 512 + c]);
    }
    if (idx < 1536)
        g_bqkv[idx] = (idx < 512) ? qb[idx] : (idx < 1024 ? kb[idx - 512] : vb[idx - 1024]);
}

__global__ void k_pack_w(const float* __restrict__ W, uint2* __restrict__ out, int Kp, int N) {
    int idx = blockIdx.x * 256 + threadIdx.x;
    if (idx >= Kp * N) return;
    int n = idx % N, kp = idx / N;
    out[idx] = sp2(W[(size_t)(2 * kp) * N + n], W[(size_t)(2 * kp + 1) * N + n]);
}

// ---------------- embedding + positional encoding ----------------
__global__ void k_embed(const int* __restrict__ inp, const float* __restrict__ emb) {
    int idx = blockIdx.x * blockDim.x + threadIdx.x;
    if (idx >= Bb * Ss * (Ee / 2)) return;
    int ep = idx % (Ee / 2);
    int bs = idx / (Ee / 2);
    int s = bs % Ss;
    int tok = inp[bs];
    int e0 = 2 * ep;
    const float LN1E4 = 9.210340371976184f;
    float freq = expf(-(float)e0 * (LN1E4 / (float)Ee));
    float ang = (float)s * freq;
    float x0 = emb[(size_t)tok * Ee + e0] + sinf(ang);
    float x1 = emb[(size_t)tok * Ee + e0 + 1] + cosf(ang);
    g_x[(size_t)bs * Ee + e0] = x0;
    g_x[(size_t)bs * Ee + e0 + 1] = x1;
    g_xp[(size_t)bs * (Ee / 2) + ep] = sp2(x0, x1);
}

// ---------------- window-summed V (fp16 packed in/out) ----------------
__global__ void k_build_vs() {
    int idx = blockIdx.x * blockDim.x + threadIdx.x;
    if (idx >= Bb * Hh * (SKk / 2) * (DHh / 2)) return;
    int dp = idx & 31;
    int rest = idx >> 5;
    int kp = rest % (SKk / 2);
    int bh = rest / (SKk / 2);
    int b = bh >> 3, h = bh & 7;
    const uint2* Vp = g_qkvp + (size_t)b * Ss * 768 + 512 + h * 32 + dp;
    int k = 2 * kp;
    float v0[6], v1[6];
#pragma unroll
    for (int r = 0; r < 6; r++) {
        uint2 w = Vp[(size_t)(k + r) * 768];
        float2 hi = h2f2(w.x), lo = h2f2(w.y);
        v0[r] = hi.x + lo.x;
        v1[r] = hi.y + lo.y;
    }
    float s00 = v0[0] + v0[1] + v0[2] + v0[3] + v0[4];
    float s10 = v0[1] + v0[2] + v0[3] + v0[4] + v0[5];
    float s01 = v1[0] + v1[1] + v1[2] + v1[3] + v1[4];
    float s11 = v1[1] + v1[2] + v1[3] + v1[4] + v1[5];
    uint2* dst = g_vsp + ((size_t)bh * (SP / 2) + kp) * DHh + 2 * dp;
    dst[0] = sph2(s00, s10);
    dst[1] = sph2(s01, s11);
}

// ---------------- fused attention (64-row q-tiles; fp16 path) ----------------
#define FA_OFF_Q  0                          // 32 x 84 uint2  = 21504
#define FA_OFF_K  21504                      // 32 x 68 uint2  = 17408
#define FA_OFF_G  38912                      // 68 x 132 float = 35904
#define FA_OFF_P  74816                      // 32 x 68 uint   = 8704
#define FA_OFF_V  83520                      // 32 x 68 uint2  = 17408
#define FA_OFF_S  100928                     // sFac[64] + sLf[64]
#define FA_SMEM   101440

__launch_bounds__(256)
__global__ void k_fattn() {
    extern __shared__ char dyn[];
    uint2* sQ = (uint2*)(dyn + FA_OFF_Q);
    uint2* sK = (uint2*)(dyn + FA_OFF_K);
    float* sG = (float*)(dyn + FA_OFF_G);
    uint32_t* sPh = (uint32_t*)(dyn + FA_OFF_P);
    uint2* sV = (uint2*)(dyn + FA_OFF_V);
    float* sFac = (float*)(dyn + FA_OFF_S);
    float* sLf = sFac + 64;

    int qt = blockIdx.x;
    int bh = blockIdx.y;
    int b = bh >> 3, h = bh & 7;
    int q0 = qt * 64;
    const uint2* Qb = g_qkvp + (size_t)b * Ss * 768 + h * 32;
    const uint2* Kb = g_qkvp + (size_t)b * Ss * 768 + 256 + h * 32;
    const uint2* Vb = g_vsp + (size_t)bh * (SP / 2) * DHh;

    int t = threadIdx.x, lane = t & 31, wid = t >> 5;
    int wm = wid & 3, wn = wid >> 2;
    int g = lane >> 2, tg = lane & 3;
    float acc[4][4] = {};
    float m_run = -1e30f, l_run = 0.f;
    int srow = t >> 2, kbase = (t & 3) * 16;

    // load Q tile: rows 0..67 = global q0-2..q0+65; rows 68..79 zero
    {
        int dpq = (t & 3) * 8;
        int rr = t >> 2;
#pragma unroll
        for (int rb = 0; rb < 80; rb += 64) {
            int r = rb + rr;
            if (r < 80) {
                int gr = q0 - 2 + r;
                bool ok = (r < 68) && (gr >= 0) && (gr < Ss);
#pragma unroll
                for (int u = 0; u < 8; u += 2) {
                    uint4 v = make_uint4(0, 0, 0, 0);
                    if (ok) v = *(const uint4*)(Qb + (size_t)gr * 768 + dpq + u);
                    sQ[(size_t)(dpq + u) * QST2 + r] = make_uint2(v.x, v.y);
                    sQ[(size_t)(dpq + u + 1) * QST2 + r] = make_uint2(v.z, v.w);
                }
            }
        }
    }
    // load K panel 0
    {
        int r = t >> 2, dpq = (t & 3) * 8;
        const uint2* src = Kb + (size_t)r * 768 + dpq;
#pragma unroll
        for (int u = 0; u < 8; u += 2) {
            uint4 v = *(const uint4*)(src + u);
            sK[(size_t)(dpq + u) * KST + r] = make_uint2(v.x, v.y);
            sK[(size_t)(dpq + u + 1) * KST + r] = make_uint2(v.z, v.w);
        }
    }
    __syncthreads();

    // gram panel 0 -> ring slot 0 (fp16 x3)
    {
        float accg[5][4] = {};
        int nb = wid * 8 + g;
#pragma unroll
        for (int c = 0; c < 4; c++) {
            uint2 v0 = sK[(size_t)(c * 8 + tg) * KST + nb];
            uint2 v1 = sK[(size_t)(c * 8 + tg + 4) * KST + nb];
#pragma unroll
            for (int mi = 0; mi < 5; mi++) {
                int m = mi * 16 + g;
                uint2 u0 = sQ[(size_t)(c * 8 + tg) * QST2 + m];
                uint2 u1 = sQ[(size_t)(c * 8 + tg) * QST2 + m + 8];
                uint2 u2 = sQ[(size_t)(c * 8 + tg + 4) * QST2 + m];
                uint2 u3 = sQ[(size_t)(c * 8 + tg + 4) * QST2 + m + 8];
                mma16h(accg[mi], u0.x, u1.x, u2.x, u3.x, v0.x, v1.x);
                mma16h(accg[mi], u0.x, u1.x, u2.x, u3.x, v0.y, v1.y);
                mma16h(accg[mi], u0.y, u1.y, u2.y, u3.y, v0.x, v1.x);
            }
        }
        int c0 = wid * 8 + 2 * tg;
#pragma unroll
        for (int mi = 0; mi < 5; mi++) {
            int r0 = mi * 16 + g;
            if (r0 < 68) {
                sG[r0 * GS2 + c0] = accg[mi][0] * SCALEc;
                sG[r0 * GS2 + c0 + 1] = accg[mi][1] * SCALEc;
            }
            if (r0 + 8 < 68) {
                sG[(r0 + 8) * GS2 + c0] = accg[mi][2] * SCALEc;
                sG[(r0 + 8) * GS2 + c0 + 1] = accg[mi][3] * SCALEc;
            }
        }
    }
    __syncthreads();

    for (int it = 0; it < 32; it++) {
        int k0 = it * 64;
        bool more = (it < 31);

        if (more) {
            int r = t >> 2, dpq = (t & 3) * 8;
            const uint2* src = Kb + (size_t)((it + 1) * 64 + r) * 768 + dpq;
#pragma unroll
            for (int u = 0; u < 8; u += 2) {
                uint4 v = *(const uint4*)(src + u);
                sK[(size_t)(dpq + u) * KST + r] = make_uint2(v.x, v.y);
                sK[(size_t)(dpq + u + 1) * KST + r] = make_uint2(v.z, v.w);
            }
        }
        {
            int kpB = t >> 5, dB = (t & 31) * 2;
#pragma unroll
            for (int r = 0; r < 4; r++) {
                int kp = r * 8 + kpB;
                uint4 v = *(const uint4*)(Vb + (size_t)((k0 >> 1) + kp) * DHh + dB);
                sV[(size_t)kp * VST + dB] = make_uint2(v.x, v.y);
                sV[(size_t)kp * VST + dB + 1] = make_uint2(v.z, v.w);
            }
        }
        __syncthreads();   // A

        if (more) {
            float accg[5][4] = {};
            int nb = wid * 8 + g;
#pragma unroll
            for (int c = 0; c < 4; c++) {
                uint2 v0 = sK[(size_t)(c * 8 + tg) * KST + nb];
                uint2 v1 = sK[(size_t)(c * 8 + tg + 4) * KST + nb];
#pragma unroll
                for (int mi = 0; mi < 5; mi++) {
                    int m = mi * 16 + g;
                    uint2 u0 = sQ[(size_t)(c * 8 + tg) * QST2 + m];
                    uint2 u1 = sQ[(size_t)(c * 8 + tg) * QST2 + m + 8];
                    uint2 u2 = sQ[(size_t)(c * 8 + tg + 4) * QST2 + m];
                    uint2 u3 = sQ[(size_t)(c * 8 + tg + 4) * QST2 + m + 8];
                    mma16h(accg[mi], u0.x, u1.x, u2.x, u3.x, v0.x, v1.x);
                    mma16h(accg[mi], u0.x, u1.x, u2.x, u3.x, v0.y, v1.y);
                    mma16h(accg[mi], u0.y, u1.y, u2.y, u3.y, v0.x, v1.x);
                }
            }
            int c0 = ((it + 1) & 1) * 64 + wid * 8 + 2 * tg;
#pragma unroll
            for (int mi = 0; mi < 5; mi++) {
                int r0 = mi * 16 + g;
                if (r0 < 68) {
                    sG[r0 * GS2 + c0] = accg[mi][0] * SCALEc;
                    sG[r0 * GS2 + c0 + 1] = accg[mi][1] * SCALEc;
                }
                if (r0 + 8 < 68) {
                    sG[(r0 + 8) * GS2 + c0] = accg[mi][2] * SCALEc;
                    sG[(r0 + 8) * GS2 + c0 + 1] = accg[mi][3] * SCALEc;
                }
            }
        }
        __syncthreads();   // B

        // scores: vectorized shift-sum (5 rows x 5 float4 + register shifts)
        float sv[16];
#pragma unroll
        for (int i = 0; i < 16; i++) sv[i] = 0.f;
        int cb0 = ((it & 1) << 6) + kbase;
#pragma unroll
        for (int j = 0; j < Ww; j++) {
            const float* rp = sG + (srow + j) * GS2;
            float rr[20];
#pragma unroll
            for (int m = 0; m < 5; m++) {
                float4 v = *(const float4*)(rp + ((cb0 + 4 * m) & 127));
                rr[4 * m + 0] = v.x; rr[4 * m + 1] = v.y;
                rr[4 * m + 2] = v.z; rr[4 * m + 3] = v.w;
            }
#pragma unroll
            for (int i = 0; i < 16; i++) sv[i] += rr[i + j];
        }
        float lmax = -1e30f;
#pragma unroll
        for (int i = 0; i < 16; i++) {
            if (k0 + kbase + i >= SKk) sv[i] = -1e30f;
            lmax = fmaxf(lmax, sv[i]);
        }
        lmax = fmaxf(lmax, __shfl_xor_sync(0xffffffffu, lmax, 1));
        lmax = fmaxf(lmax, __shfl_xor_sync(0xffffffffu, lmax, 2));
        float mnew = fmaxf(m_run, lmax);
        float lsum = 0.f;
#pragma unroll
        for (int i = 0; i < 16; i += 2) {
            float p0 = __expf(sv[i] - mnew);
            float p1 = __expf(sv[i + 1] - mnew);
            lsum += p0 + p1;
            sPh[(size_t)((kbase >> 1) + (i >> 1)) * PST + srow] = h2pack(p0, p1);
        }
        lsum += __shfl_xor_sync(0xffffffffu, lsum, 1);
        lsum += __shfl_xor_sync(0xffffffffu, lsum, 2);
        float fac = __expf(m_run - mnew);
        l_run = l_run * fac + lsum;
        m_run = mnew;
        if ((t & 3) == 0) sFac[srow] = fac;
        __syncthreads();   // C

        // rescale + AV MMA (fp16 x2: P single, V hi/lo)
        {
            float f0 = sFac[wm * 16 + g];
            float f1 = sFac[wm * 16 + g + 8];
#pragma unroll
            for (int ni = 0; ni < 4; ni++) {
                acc[ni][0] *= f0; acc[ni][1] *= f0;
                acc[ni][2] *= f1; acc[ni][3] *= f1;
            }
#pragma unroll
            for (int c = 0; c < 4; c++) {
                int m = wm * 16 + g;
                uint32_t u0 = sPh[(size_t)(c * 8 + tg) * PST + m];
                uint32_t u1 = sPh[(size_t)(c * 8 + tg) * PST + m + 8];
                uint32_t u2 = sPh[(size_t)(c * 8 + tg + 4) * PST + m];
                uint32_t u3 = sPh[(size_t)(c * 8 + tg + 4) * PST + m + 8];
#pragma unroll
                for (int ni = 0; ni < 4; ni++) {
                    int n = wn * 32 + ni * 8 + g;
                    uint2 v0 = sV[(size_t)(c * 8 + tg) * VST + n];
                    uint2 v1 = sV[(size_t)(c * 8 + tg + 4) * VST + n];
                    mma16h(acc[ni], u0, u1, u2, u3, v0.x, v1.x);
                    mma16h(acc[ni], u0, u1, u2, u3, v0.y, v1.y);
                }
            }
        }
        __syncthreads();   // D
    }

    if ((t & 3) == 0) sLf[srow] = l_run;
    __syncthreads();

    float inv0 = 1.f / sLf[wm * 16 + g];
    float inv1 = 1.f / sLf[wm * 16 + g + 8];
    float* Cb = g_attn + (size_t)b * Ss * Ee + h * DHh;
#pragma unroll
    for (int ni = 0; ni < 4; ni++) {
        int r0 = q0 + wm * 16 + g;
        int c0 = wn * 32 + ni * 8 + 2 * tg;
        Cb[(size_t)r0 * Ee + c0] = acc[ni][0] * inv0;
        Cb[(size_t)r0 * Ee + c0 + 1] = acc[ni][1] * inv0;
        Cb[(size_t)(r0 + 8) * Ee + c0] = acc[ni][2] * inv1;
        Cb[(size_t)(r0 + 8) * Ee + c0 + 1] = acc[ni][3] * inv1;
    }
}

// ---------------- LayerNorm: one warp per row, shuffle-only reductions ----------------
__launch_bounds__(256)
__global__ void k_ln(const float* __restrict__ in, const float* __restrict__ w,
                     const float* __restrict__ bz, float* __restrict__ out,
                     uint2* __restrict__ outp) {
    int row = blockIdx.x * 8 + (threadIdx.x >> 5);
    int lane = threadIdx.x & 31;
    const float* x = in + (size_t)row * Ee;

    float4 v[4];
#pragma unroll
    for (int j = 0; j < 4; j++)
        v[j] = *(const float4*)(x + 4 * (lane + j * 32));

    float s = 0.f;
#pragma unroll
    for (int j = 0; j < 4; j++) s += v[j].x + v[j].y + v[j].z + v[j].w;
#pragma unroll
    for (int off = 16; off > 0; off >>= 1)
        s += __shfl_xor_sync(0xffffffffu, s, off);
    float m = s * (1.0f / Ee);

    float vs = 0.f;
#pragma unroll
    for (int j = 0; j < 4; j++) {
        float d0 = v[j].x - m, d1 = v[j].y - m, d2 = v[j].z - m, d3 = v[j].w - m;
        vs += d0 * d0 + d1 * d1 + d2 * d2 + d3 * d3;
    }
#pragma unroll
    for (int off = 16; off > 0; off >>= 1)
        vs += __shfl_xor_sync(0xffffffffu, vs, off);
    float inv = rsqrtf(vs * (1.0f / Ee) + 1e-5f);

#pragma unroll
    for (int j = 0; j < 4; j++) {
        int c = 4 * (lane + j * 32);
        float4 wv = *(const float4*)(w + c);
        float4 bv = *(const float4*)(bz + c);
        float y0 = (v[j].x - m) * inv * wv.x + bv.x;
        float y1 = (v[j].y - m) * inv * wv.y + bv.y;
        float y2 = (v[j].z - m) * inv * wv.z + bv.z;
        float y3 = (v[j].w - m) * inv * wv.w + bv.w;
        *(float4*)(out + (size_t)row * Ee + c) = make_float4(y0, y1, y2, y3);
        uint2 p0 = sp2(y0, y1);
        uint2 p1 = sp2(y2, y3);
        *(uint4*)(outp + (size_t)row * (Ee / 2) + (c >> 1)) =
            make_uint4(p0.x, p0.y, p1.x, p1.y);
    }
}

// ---------------- output head ----------------
__launch_bounds__(256)
__global__ void k_out_partial(const float* __restrict__ ow) {
    int b = blockIdx.y, c = blockIdx.x;
    const int per = (Ss * Ee) / CHUNKS;
    const float* x = g_x + (size_t)b * Ss * Ee + (size_t)c * per;
    const float* wr = ow + (size_t)c * per * OUTo;
    int t = threadIdx.x;
    float acc[OUTo] = {};
    for (int i = t; i < per; i += 256) {
        float xv = x[i];
#pragma unroll
        for (int o = 0; o < OUTo; o++) acc[o] = fmaf(xv, wr[(size_t)i * OUTo + o], acc[o]);
    }
    __shared__ float red[256 * OUTo];
#pragma unroll
    for (int o = 0; o < OUTo; o++) red[t * OUTo + o] = acc[o];
    __syncthreads();
    for (int off = 128; off > 0; off >>= 1) {
        if (t < off) {
#pragma unroll
            for (int o = 0; o < OUTo; o++)
                red[t * OUTo + o] += red[(t + off) * OUTo + o];
        }
        __syncthreads();
    }
    if (t == 0) {
#pragma unroll
        for (int o = 0; o < OUTo; o++)
            g_part[((size_t)b * CHUNKS + c) * OUTo + o] = red[o];
    }
}

__global__ void k_out_final(const float* __restrict__ ob, float* __restrict__ out) {
    int b = blockIdx.x;
    int o = threadIdx.x;
    if (o < OUTo) {
        float s = ob[o];
        for (int c = 0; c < CHUNKS; c++) s += g_part[(b * CHUNKS + c) * OUTo + o];
        out[b * OUTo + o] = s;
    }
}

// ---------------- host launcher ----------------
extern "C" void kernel_launch(void* const* d_in, const int* in_sizes, int n_in,
                              void* d_out, int out_size) {
    const int*   inputs = (const int*)d_in[0];
    const float* emb    = (const float*)d_in[1];
    const float* ln_w   = (const float*)d_in[2];
    const float* ln_b   = (const float*)d_in[3];
    const float* q_w    = (const float*)d_in[4];
    const float* q_b    = (const float*)d_in[5];
    const float* k_w    = (const float*)d_in[6];
    const float* k_b    = (const float*)d_in[7];
    const float* v_w    = (const float*)d_in[8];
    const float* v_b    = (const float*)d_in[9];
    const float* fc1_w  = (const float*)d_in[10];
    const float* fc1_b  = (const float*)d_in[11];
    const float* fc2_w  = (const float*)d_in[12];
    const float* fc2_b  = (const float*)d_in[13];
    const float* out_w  = (const float*)d_in[14];
    const float* out_b  = (const float*)d_in[15];
    float* out = (float*)d_out;

    static int smem_set = 0;
    if (!smem_set) {
        cudaFuncSetAttribute(k_fattn, cudaFuncAttributeMaxDynamicSharedMemorySize, FA_SMEM);
        smem_set = 1;
    }

    float *px, *pattn, *pbqkv;
    uint2 *pxp, *pqkvp, *phidp, *pwqkv, *pwfc1, *pwfc2;
    cudaGetSymbolAddress((void**)&px, g_x);
    cudaGetSymbolAddress((void**)&pattn, g_attn);
    cudaGetSymbolAddress((void**)&pxp, g_xp);
    cudaGetSymbolAddress((void**)&pqkvp, g_qkvp);
    cudaGetSymbolAddress((void**)&phidp, g_hidp);
    cudaGetSymbolAddress((void**)&pwqkv, g_wqkv);
    cudaGetSymbolAddress((void**)&pwfc1, g_wfc1);
    cudaGetSymbolAddress((void**)&pwfc2, g_wfc2);
    cudaGetSymbolAddress((void**)&pbqkv, g_bqkv);

    const int M = Bb * Ss;  // 4096

    k_pack_qkv<<<((Ee / 2) * 1536 + 255) / 256, 256>>>(q_w, k_w, v_w, q_b, k_b, v_b);
    k_pack_w<<<((Ee / 2) * HIDh + 255) / 256, 256>>>(fc1_w, pwfc1, Ee / 2, HIDh);
    k_pack_w<<<((HIDh / 2) * Ee + 255) / 256, 256>>>(fc2_w, pwfc2, HIDh / 2, Ee);

    k_embed<<<(Bb * Ss * (Ee / 2) + 255) / 256, 256>>>(inputs, emb);

    for (int l = 0; l < Ll; l++) {
        // QKV: 128x128 tiles, fp16-packed output for attention
        k_gemm128<1, 0, 1, 1><<<dim3(1536 / 128, M / 128), 256>>>(
            pxp, pwqkv, pbqkv, pqkvp, Ee, Ee / 2, 1536, 1536);

        k_build_vs<<<(Bb * Hh * (SKk / 2) * (DHh / 2) + 255) / 256, 256>>>();

        dim3 gf(Ss / 64, Bb * Hh);
        k_fattn<<<gf, 256, FA_SMEM>>>();

        k_ln<<<M / 8, 256>>>(pattn, ln_w, ln_b, px, pxp);

        // fc1: 128x128 tiles, relu, bf16-packed output
        k_gemm128<1, 1, 1, 0><<<dim3(HIDh / 128, M / 128), 256>>>(
            pxp, pwfc1, fc1_b, phidp, Ee, Ee / 2, HIDh, HIDh);
        // fc2: 64-wide core (residual + fp32 out), 256 CTAs
        dim3 g2(Ee / 64, M / 128);
        k_fc2<<<g2, 256>>>(fc2_b);

        k_ln<<<M / 8, 256>>>(pattn, ln_w, ln_b, px, pxp);
    }

    dim3 go(CHUNKS, Bb);
    k_out_partial<<<go, 256>>>(out_w);
    k_out_final<<<Bb, 32>>>(out_b, out);
}

// round 13
// speedup vs baseline: 1.1254x; 1.0181x over previous
#include <cuda_runtime.h>
#include <cuda_bf16.h>
#include <cuda_fp16.h>
#include <math.h>
#include <stdint.h>

#define Bb 2
#define Ss 2048
#define Ee 512
#define Hh 8
#define DHh 64
#define Ww 5
#define PADp 2
#define SKk 2044
#define HIDh 2048
#define Ll 6
#define OUTo 6
#define SCALEc 0.125f
#define CHUNKS 128
#define SP 2048

#define AST 132   // smem A row stride (uint2)
#define BST 68    // smem B row stride (uint2), 64-wide core
#define BSW 132   // smem B row stride (uint2), 128-wide core
// fattn strides
#define QST2 84
#define KST 68
#define PST 68
#define VST 68
#define GS2 132

// ---------------- scratch ----------------
__device__ float g_x[Bb * Ss * Ee];
__device__ uint2 g_xp[Bb * Ss * (Ee / 2)];               // bf16 hi/lo (GEMM operand)
__device__ uint2 g_qkvp[Bb * Ss * 768];                  // fp16 hi/lo (attention operand)
__device__ uint2 g_hidp[(size_t)Bb * Ss * (HIDh / 2)];   // bf16 hi/lo
__device__ uint2 g_vsp[(size_t)Bb * Hh * (SP / 2) * DHh];// fp16 hi/lo
__device__ float g_attn[Bb * Ss * Ee];
__device__ float g_part[Bb * CHUNKS * OUTo];
__device__ uint2 g_wqkv[(Ee / 2) * 1536];
__device__ float g_bqkv[1536];
__device__ uint2 g_wfc1[(Ee / 2) * HIDh];
__device__ uint2 g_wfc2[(HIDh / 2) * Ee];

// ---------------- bf16 split/pack ----------------
__device__ __forceinline__ uint2 sp2(float x, float y) {
    __nv_bfloat16 xh = __float2bfloat16_rn(x);
    __nv_bfloat16 yh = __float2bfloat16_rn(y);
    float xr = x - __bfloat162float(xh);
    float yr = y - __bfloat162float(yh);
    __nv_bfloat16 xl = __float2bfloat16_rn(xr);
    __nv_bfloat16 yl = __float2bfloat16_rn(yr);
    uint2 w;
    w.x = ((uint32_t)__bfloat16_as_ushort(yh) << 16) | (uint32_t)__bfloat16_as_ushort(xh);
    w.y = ((uint32_t)__bfloat16_as_ushort(yl) << 16) | (uint32_t)__bfloat16_as_ushort(xl);
    return w;
}

// ---------------- fp16 split/pack ----------------
__device__ __forceinline__ uint32_t h2pack(float x, float y) {
    __half2 h = __floats2half2_rn(x, y);
    return *(uint32_t*)&h;
}
__device__ __forceinline__ float2 h2f2(uint32_t u) {
    __half2 h = *(__half2*)&u;
    return __half22float2(h);
}
__device__ __forceinline__ uint2 sph2(float x, float y) {
    float hx = __half2float(__float2half_rn(x));
    float hy = __half2float(__float2half_rn(y));
    uint2 w;
    w.x = h2pack(hx, hy);
    w.y = h2pack(x - hx, y - hy);
    return w;
}

__device__ __forceinline__ void mma16(float c[4], uint32_t a0, uint32_t a1, uint32_t a2,
                                      uint32_t a3, uint32_t b0, uint32_t b1) {
    asm volatile(
        "mma.sync.aligned.m16n8k16.row.col.f32.bf16.bf16.f32 "
        "{%0,%1,%2,%3},{%4,%5,%6,%7},{%8,%9},{%0,%1,%2,%3};"
        : "+f"(c[0]), "+f"(c[1]), "+f"(c[2]), "+f"(c[3])
        : "r"(a0), "r"(a1), "r"(a2), "r"(a3), "r"(b0), "r"(b1));
}

__device__ __forceinline__ void mma16h(float c[4], uint32_t a0, uint32_t a1, uint32_t a2,
                                       uint32_t a3, uint32_t b0, uint32_t b1) {
    asm volatile(
        "mma.sync.aligned.m16n8k16.row.col.f32.f16.f16.f32 "
        "{%0,%1,%2,%3},{%4,%5,%6,%7},{%8,%9},{%0,%1,%2,%3};"
        : "+f"(c[0]), "+f"(c[1]), "+f"(c[2]), "+f"(c[3])
        : "r"(a0), "r"(a1), "r"(a2), "r"(a3), "r"(b0), "r"(b1));
}

// one 16-k chunk over 128x64 tile (warp tile 32x32) -- 64-wide core (bf16x3)
__device__ __forceinline__ void mma_chunk(const uint2* sA, const uint2* sB,
                                          int wm, int wn, int lane, float acc[2][4][4]) {
    int g = lane >> 2, tg = lane & 3;
    uint32_t ah[2][4], al[2][4];
#pragma unroll
    for (int mi = 0; mi < 2; mi++) {
        int m = wm * 32 + mi * 16 + g;
        uint2 u0 = sA[(size_t)tg * AST + m];
        uint2 u1 = sA[(size_t)tg * AST + m + 8];
        uint2 u2 = sA[(size_t)(tg + 4) * AST + m];
        uint2 u3 = sA[(size_t)(tg + 4) * AST + m + 8];
        ah[mi][0] = u0.x; al[mi][0] = u0.y;
        ah[mi][1] = u1.x; al[mi][1] = u1.y;
        ah[mi][2] = u2.x; al[mi][2] = u2.y;
        ah[mi][3] = u3.x; al[mi][3] = u3.y;
    }
#pragma unroll
    for (int ni = 0; ni < 4; ni++) {
        int n = wn * 32 + ni * 8 + g;
        uint2 v0 = sB[(size_t)tg * BST + n];
        uint2 v1 = sB[(size_t)(tg + 4) * BST + n];
#pragma unroll
        for (int mi = 0; mi < 2; mi++) {
            mma16(acc[mi][ni], ah[mi][0], ah[mi][1], ah[mi][2], ah[mi][3], v0.x, v1.x);
            mma16(acc[mi][ni], ah[mi][0], ah[mi][1], ah[mi][2], ah[mi][3], v0.y, v1.y);
            mma16(acc[mi][ni], al[mi][0], al[mi][1], al[mi][2], al[mi][3], v0.x, v1.x);
        }
    }
}

// ---------------- 64-wide packed GEMM core (fc2, bf16x3) ----------------
__launch_bounds__(256)
__global__ void k_fc2(const float* __restrict__ bias) {
    const uint2* __restrict__ A = g_hidp;
    const uint2* __restrict__ B = g_wfc2;
    const float* __restrict__ res = g_x;
    float* __restrict__ C = g_attn;
    const int K = HIDh, lda2 = HIDh / 2, ldb2 = Ee, ldc = Ee;

    __shared__ uint2 sA[2][8 * AST];
    __shared__ uint2 sB[2][8 * BST];
    int t = threadIdx.x, lane = t & 31, wid = t >> 5;
    int wm = wid & 3, wn = wid >> 2;
    int bm = blockIdx.y * 128, bn = blockIdx.x * 64;
    float acc[2][4][4] = {};

    int mA = t & 127, koA2 = (t >> 7) * 4;
    const uint2* Arow = A + (size_t)(bm + mA) * lda2 + koA2;
    int kpB = t >> 5, nB = (t & 31) * 2;
    const uint2* Bp = B + (size_t)kpB * ldb2 + bn + nB;

    uint4 a0 = *(const uint4*)(Arow);
    uint4 a1 = *(const uint4*)(Arow + 2);
    uint4 b0 = *(const uint4*)(Bp);

    {
        uint2* pa = sA[0];
        pa[(size_t)(koA2 + 0) * AST + mA] = make_uint2(a0.x, a0.y);
        pa[(size_t)(koA2 + 1) * AST + mA] = make_uint2(a0.z, a0.w);
        pa[(size_t)(koA2 + 2) * AST + mA] = make_uint2(a1.x, a1.y);
        pa[(size_t)(koA2 + 3) * AST + mA] = make_uint2(a1.z, a1.w);
        uint2* pb = sB[0];
        pb[(size_t)kpB * BST + nB]     = make_uint2(b0.x, b0.y);
        pb[(size_t)kpB * BST + nB + 1] = make_uint2(b0.z, b0.w);
    }
    __syncthreads();

    int nch = K >> 4;
    for (int ch = 0; ch < nch; ch++) {
        int s = ch & 1;
        bool more = (ch + 1 < nch);
        if (more) {
            int off = (ch + 1) * 8;
            a0 = *(const uint4*)(Arow + off);
            a1 = *(const uint4*)(Arow + off + 2);
            b0 = *(const uint4*)(Bp + (size_t)(ch + 1) * 8 * ldb2);
        }
        mma_chunk(sA[s], sB[s], wm, wn, lane, acc);
        if (more) {
            int s2 = s ^ 1;
            uint2* pa = sA[s2];
            pa[(size_t)(koA2 + 0) * AST + mA] = make_uint2(a0.x, a0.y);
            pa[(size_t)(koA2 + 1) * AST + mA] = make_uint2(a0.z, a0.w);
            pa[(size_t)(koA2 + 2) * AST + mA] = make_uint2(a1.x, a1.y);
            pa[(size_t)(koA2 + 3) * AST + mA] = make_uint2(a1.z, a1.w);
            uint2* pb = sB[s2];
            pb[(size_t)kpB * BST + nB]     = make_uint2(b0.x, b0.y);
            pb[(size_t)kpB * BST + nB + 1] = make_uint2(b0.z, b0.w);
        }
        __syncthreads();
    }

    int g = lane >> 2, tg = lane & 3;
#pragma unroll
    for (int mi = 0; mi < 2; mi++)
#pragma unroll
        for (int ni = 0; ni < 4; ni++) {
            int r0 = bm + wm * 32 + mi * 16 + g;
            int c0 = bn + wn * 32 + ni * 8 + 2 * tg;
            float bv0 = bias[c0], bv1 = bias[c0 + 1];
            float v00 = acc[mi][ni][0] + bv0 + res[(size_t)r0 * ldc + c0];
            float v01 = acc[mi][ni][1] + bv1 + res[(size_t)r0 * ldc + c0 + 1];
            float v10 = acc[mi][ni][2] + bv0 + res[(size_t)(r0 + 8) * ldc + c0];
            float v11 = acc[mi][ni][3] + bv1 + res[(size_t)(r0 + 8) * ldc + c0 + 1];
            C[(size_t)r0 * ldc + c0] = v00;
            C[(size_t)r0 * ldc + c0 + 1] = v01;
            C[(size_t)(r0 + 8) * ldc + c0] = v10;
            C[(size_t)(r0 + 8) * ldc + c0 + 1] = v11;
        }
}

// ---------------- 128x128 packed GEMM (qkv, fc1; bf16x3; PKH: fp16 vs bf16 out) ----
template <int BIAS, int RELU, int WPK, int PKH>
__launch_bounds__(256, 2)
__global__ void k_gemm128(const uint2* __restrict__ A, const uint2* __restrict__ B,
                          const float* __restrict__ bias,
                          uint2* __restrict__ Cp,
                          int K, int lda2, int ldb2, int ldc) {
    __shared__ uint2 sA[2][8 * AST];
    __shared__ uint2 sB2[2][8 * BSW];
    int t = threadIdx.x, lane = t & 31, wid = t >> 5;
    int wm = wid & 3, wn = wid >> 2;
    int g = lane >> 2, tg = lane & 3;
    int bm = blockIdx.y * 128, bn = blockIdx.x * 128;
    float acc[2][8][4] = {};

    int mA = t & 127, koA2 = (t >> 7) * 4;
    const uint2* Arow = A + (size_t)(bm + mA) * lda2 + koA2;
    int kpB = t >> 5, nB = (t & 31) * 4;
    const uint2* Bp = B + (size_t)kpB * ldb2 + bn + nB;

    uint4 a0 = *(const uint4*)(Arow);
    uint4 a1 = *(const uint4*)(Arow + 2);
    uint4 b0 = *(const uint4*)(Bp);
    uint4 b1 = *(const uint4*)(Bp + 2);

    {
        uint2* pa = sA[0];
        pa[(size_t)(koA2 + 0) * AST + mA] = make_uint2(a0.x, a0.y);
        pa[(size_t)(koA2 + 1) * AST + mA] = make_uint2(a0.z, a0.w);
        pa[(size_t)(koA2 + 2) * AST + mA] = make_uint2(a1.x, a1.y);
        pa[(size_t)(koA2 + 3) * AST + mA] = make_uint2(a1.z, a1.w);
        uint2* pb = sB2[0];
        pb[(size_t)kpB * BSW + nB]     = make_uint2(b0.x, b0.y);
        pb[(size_t)kpB * BSW + nB + 1] = make_uint2(b0.z, b0.w);
        pb[(size_t)kpB * BSW + nB + 2] = make_uint2(b1.x, b1.y);
        pb[(size_t)kpB * BSW + nB + 3] = make_uint2(b1.z, b1.w);
    }
    __syncthreads();

    int nch = K >> 4;
    for (int ch = 0; ch < nch; ch++) {
        int s = ch & 1;
        bool more = (ch + 1 < nch);
        if (more) {
            int off = (ch + 1) * 8;
            a0 = *(const uint4*)(Arow + off);
            a1 = *(const uint4*)(Arow + off + 2);
            const uint2* Bn = Bp + (size_t)(ch + 1) * 8 * ldb2;
            b0 = *(const uint4*)(Bn);
            b1 = *(const uint4*)(Bn + 2);
        }
        {
            const uint2* pa = sA[s];
            const uint2* pb = sB2[s];
            uint32_t ah[2][4], al[2][4];
#pragma unroll
            for (int mi = 0; mi < 2; mi++) {
                int m = wm * 32 + mi * 16 + g;
                uint2 u0 = pa[(size_t)tg * AST + m];
                uint2 u1 = pa[(size_t)tg * AST + m + 8];
                uint2 u2 = pa[(size_t)(tg + 4) * AST + m];
                uint2 u3 = pa[(size_t)(tg + 4) * AST + m + 8];
                ah[mi][0] = u0.x; al[mi][0] = u0.y;
                ah[mi][1] = u1.x; al[mi][1] = u1.y;
                ah[mi][2] = u2.x; al[mi][2] = u2.y;
                ah[mi][3] = u3.x; al[mi][3] = u3.y;
            }
#pragma unroll
            for (int ni = 0; ni < 8; ni++) {
                int n = wn * 64 + ni * 8 + g;
                uint2 v0 = pb[(size_t)tg * BSW + n];
                uint2 v1 = pb[(size_t)(tg + 4) * BSW + n];
#pragma unroll
                for (int mi = 0; mi < 2; mi++) {
                    mma16(acc[mi][ni], ah[mi][0], ah[mi][1], ah[mi][2], ah[mi][3], v0.x, v1.x);
                    mma16(acc[mi][ni], ah[mi][0], ah[mi][1], ah[mi][2], ah[mi][3], v0.y, v1.y);
                    mma16(acc[mi][ni], al[mi][0], al[mi][1], al[mi][2], al[mi][3], v0.x, v1.x);
                }
            }
        }
        if (more) {
            int s2 = s ^ 1;
            uint2* pa = sA[s2];
            pa[(size_t)(koA2 + 0) * AST + mA] = make_uint2(a0.x, a0.y);
            pa[(size_t)(koA2 + 1) * AST + mA] = make_uint2(a0.z, a0.w);
            pa[(size_t)(koA2 + 2) * AST + mA] = make_uint2(a1.x, a1.y);
            pa[(size_t)(koA2 + 3) * AST + mA] = make_uint2(a1.z, a1.w);
            uint2* pb = sB2[s2];
            pb[(size_t)kpB * BSW + nB]     = make_uint2(b0.x, b0.y);
            pb[(size_t)kpB * BSW + nB + 1] = make_uint2(b0.z, b0.w);
            pb[(size_t)kpB * BSW + nB + 2] = make_uint2(b1.x, b1.y);
            pb[(size_t)kpB * BSW + nB + 3] = make_uint2(b1.z, b1.w);
        }
        __syncthreads();
    }

#pragma unroll
    for (int mi = 0; mi < 2; mi++)
#pragma unroll
        for (int ni = 0; ni < 8; ni++) {
            int r0 = bm + wm * 32 + mi * 16 + g;
            int c0 = bn + wn * 64 + ni * 8 + 2 * tg;
            float v00 = acc[mi][ni][0], v01 = acc[mi][ni][1];
            float v10 = acc[mi][ni][2], v11 = acc[mi][ni][3];
            if (BIAS) {
                float bv0 = bias[c0], bv1 = bias[c0 + 1];
                v00 += bv0; v01 += bv1; v10 += bv0; v11 += bv1;
            }
            if (RELU) {
                v00 = fmaxf(v00, 0.f); v01 = fmaxf(v01, 0.f);
                v10 = fmaxf(v10, 0.f); v11 = fmaxf(v11, 0.f);
            }
            if (WPK) {
                if (PKH) {
                    Cp[(size_t)r0 * (ldc >> 1) + (c0 >> 1)] = sph2(v00, v01);
                    Cp[(size_t)(r0 + 8) * (ldc >> 1) + (c0 >> 1)] = sph2(v10, v11);
                } else {
                    Cp[(size_t)r0 * (ldc >> 1) + (c0 >> 1)] = sp2(v00, v01);
                    Cp[(size_t)(r0 + 8) * (ldc >> 1) + (c0 >> 1)] = sp2(v10, v11);
                }
            }
        }
}

// ---------------- weight packing ----------------
__global__ void k_pack_qkv(const float* __restrict__ qw, const float* __restrict__ kw,
                           const float* __restrict__ vw, const float* __restrict__ qb,
                           const float* __restrict__ kb, const float* __restrict__ vb) {
    int idx = blockIdx.x * 256 + threadIdx.x;
    if (idx < (Ee / 2) * 1536) {
        int n = idx % 1536, kp = idx / 1536;
        const float* W = (n < 512) ? qw : (n < 1024 ? kw : vw);
        int c = n & 511;
        g_wqkv[idx] = sp2(W[(size_t)(2 * kp) * 512 + c], W[(size_t)(2 * kp + 1) * 512 + c]);
    }
    if (idx < 1536)
        g_bqkv[idx] = (idx < 512) ? qb[idx] : (idx < 1024 ? kb[idx - 512] : vb[idx - 1024]);
}

__global__ void k_pack_w(const float* __restrict__ W, uint2* __restrict__ out, int Kp, int N) {
    int idx = blockIdx.x * 256 + threadIdx.x;
    if (idx >= Kp * N) return;
    int n = idx % N, kp = idx / N;
    out[idx] = sp2(W[(size_t)(2 * kp) * N + n], W[(size_t)(2 * kp + 1) * N + n]);
}

// ---------------- embedding + positional encoding ----------------
__global__ void k_embed(const int* __restrict__ inp, const float* __restrict__ emb) {
    int idx = blockIdx.x * blockDim.x + threadIdx.x;
    if (idx >= Bb * Ss * (Ee / 2)) return;
    int ep = idx % (Ee / 2);
    int bs = idx / (Ee / 2);
    int s = bs % Ss;
    int tok = inp[bs];
    int e0 = 2 * ep;
    const float LN1E4 = 9.210340371976184f;
    float freq = expf(-(float)e0 * (LN1E4 / (float)Ee));
    float ang = (float)s * freq;
    float x0 = emb[(size_t)tok * Ee + e0] + sinf(ang);
    float x1 = emb[(size_t)tok * Ee + e0 + 1] + cosf(ang);
    g_x[(size_t)bs * Ee + e0] = x0;
    g_x[(size_t)bs * Ee + e0 + 1] = x1;
    g_xp[(size_t)bs * (Ee / 2) + ep] = sp2(x0, x1);
}

// ---------------- window-summed V (fp16 packed in/out) ----------------
__global__ void k_build_vs() {
    int idx = blockIdx.x * blockDim.x + threadIdx.x;
    if (idx >= Bb * Hh * (SKk / 2) * (DHh / 2)) return;
    int dp = idx & 31;
    int rest = idx >> 5;
    int kp = rest % (SKk / 2);
    int bh = rest / (SKk / 2);
    int b = bh >> 3, h = bh & 7;
    const uint2* Vp = g_qkvp + (size_t)b * Ss * 768 + 512 + h * 32 + dp;
    int k = 2 * kp;
    float v0[6], v1[6];
#pragma unroll
    for (int r = 0; r < 6; r++) {
        uint2 w = Vp[(size_t)(k + r) * 768];
        float2 hi = h2f2(w.x), lo = h2f2(w.y);
        v0[r] = hi.x + lo.x;
        v1[r] = hi.y + lo.y;
    }
    float s00 = v0[0] + v0[1] + v0[2] + v0[3] + v0[4];
    float s10 = v0[1] + v0[2] + v0[3] + v0[4] + v0[5];
    float s01 = v1[0] + v1[1] + v1[2] + v1[3] + v1[4];
    float s11 = v1[1] + v1[2] + v1[3] + v1[4] + v1[5];
    uint2* dst = g_vsp + ((size_t)bh * (SP / 2) + kp) * DHh + 2 * dp;
    dst[0] = sph2(s00, s10);
    dst[1] = sph2(s01, s11);
}

// ---------------- fused attention (64-row q-tiles; fp16, Q/V single plane) --------
#define FA_OFF_Q  0                          // 32 x 84 uint   = 10752
#define FA_OFF_K  10752                      // 32 x 68 uint2  = 17408
#define FA_OFF_G  28160                      // 68 x 132 float = 35904
#define FA_OFF_P  64064                      // 32 x 68 uint   = 8704
#define FA_OFF_V  72768                      // 32 x 68 uint   = 8704
#define FA_OFF_S  81472                      // sFac[64] + sLf[64]
#define FA_SMEM   81984

__launch_bounds__(256)
__global__ void k_fattn() {
    extern __shared__ char dyn[];
    uint32_t* sQ = (uint32_t*)(dyn + FA_OFF_Q);
    uint2* sK = (uint2*)(dyn + FA_OFF_K);
    float* sG = (float*)(dyn + FA_OFF_G);
    uint32_t* sPh = (uint32_t*)(dyn + FA_OFF_P);
    uint32_t* sV = (uint32_t*)(dyn + FA_OFF_V);
    float* sFac = (float*)(dyn + FA_OFF_S);
    float* sLf = sFac + 64;

    int qt = blockIdx.x;
    int bh = blockIdx.y;
    int b = bh >> 3, h = bh & 7;
    int q0 = qt * 64;
    const uint2* Qb = g_qkvp + (size_t)b * Ss * 768 + h * 32;
    const uint2* Kb = g_qkvp + (size_t)b * Ss * 768 + 256 + h * 32;
    const uint2* Vb = g_vsp + (size_t)bh * (SP / 2) * DHh;

    int t = threadIdx.x, lane = t & 31, wid = t >> 5;
    int wm = wid & 3, wn = wid >> 2;
    int g = lane >> 2, tg = lane & 3;
    float acc[4][4] = {};
    float m_run = -1e30f, l_run = 0.f;
    int srow = t >> 2, kbase = (t & 3) * 16;

    // load Q tile (hi plane only): rows 0..67 = global q0-2..q0+65; 68..79 zero
    {
        int dpq = (t & 3) * 8;
        int rr = t >> 2;
#pragma unroll
        for (int rb = 0; rb < 80; rb += 64) {
            int r = rb + rr;
            if (r < 80) {
                int gr = q0 - 2 + r;
                bool ok = (r < 68) && (gr >= 0) && (gr < Ss);
#pragma unroll
                for (int u = 0; u < 8; u += 2) {
                    uint4 v = make_uint4(0, 0, 0, 0);
                    if (ok) v = *(const uint4*)(Qb + (size_t)gr * 768 + dpq + u);
                    sQ[(size_t)(dpq + u) * QST2 + r] = v.x;
                    sQ[(size_t)(dpq + u + 1) * QST2 + r] = v.z;
                }
            }
        }
    }
    // load K panel 0 (hi/lo)
    {
        int r = t >> 2, dpq = (t & 3) * 8;
        const uint2* src = Kb + (size_t)r * 768 + dpq;
#pragma unroll
        for (int u = 0; u < 8; u += 2) {
            uint4 v = *(const uint4*)(src + u);
            sK[(size_t)(dpq + u) * KST + r] = make_uint2(v.x, v.y);
            sK[(size_t)(dpq + u + 1) * KST + r] = make_uint2(v.z, v.w);
        }
    }
    __syncthreads();

    // gram panel 0 -> ring slot 0 (fp16 x2: Qh single, K hi/lo)
    {
        float accg[5][4] = {};
        int nb = wid * 8 + g;
#pragma unroll
        for (int c = 0; c < 4; c++) {
            uint2 v0 = sK[(size_t)(c * 8 + tg) * KST + nb];
            uint2 v1 = sK[(size_t)(c * 8 + tg + 4) * KST + nb];
#pragma unroll
            for (int mi = 0; mi < 5; mi++) {
                int m = mi * 16 + g;
                uint32_t u0 = sQ[(size_t)(c * 8 + tg) * QST2 + m];
                uint32_t u1 = sQ[(size_t)(c * 8 + tg) * QST2 + m + 8];
                uint32_t u2 = sQ[(size_t)(c * 8 + tg + 4) * QST2 + m];
                uint32_t u3 = sQ[(size_t)(c * 8 + tg + 4) * QST2 + m + 8];
                mma16h(accg[mi], u0, u1, u2, u3, v0.x, v1.x);
                mma16h(accg[mi], u0, u1, u2, u3, v0.y, v1.y);
            }
        }
        int c0 = wid * 8 + 2 * tg;
#pragma unroll
        for (int mi = 0; mi < 5; mi++) {
            int r0 = mi * 16 + g;
            if (r0 < 68) {
                sG[r0 * GS2 + c0] = accg[mi][0] * SCALEc;
                sG[r0 * GS2 + c0 + 1] = accg[mi][1] * SCALEc;
            }
            if (r0 + 8 < 68) {
                sG[(r0 + 8) * GS2 + c0] = accg[mi][2] * SCALEc;
                sG[(r0 + 8) * GS2 + c0 + 1] = accg[mi][3] * SCALEc;
            }
        }
    }
    __syncthreads();

    for (int it = 0; it < 32; it++) {
        int k0 = it * 64;
        bool more = (it < 31);

        if (more) {
            int r = t >> 2, dpq = (t & 3) * 8;
            const uint2* src = Kb + (size_t)((it + 1) * 64 + r) * 768 + dpq;
#pragma unroll
            for (int u = 0; u < 8; u += 2) {
                uint4 v = *(const uint4*)(src + u);
                sK[(size_t)(dpq + u) * KST + r] = make_uint2(v.x, v.y);
                sK[(size_t)(dpq + u + 1) * KST + r] = make_uint2(v.z, v.w);
            }
        }
        // load V tile (hi plane only)
        {
            int kpB = t >> 5, dB = (t & 31) * 2;
#pragma unroll
            for (int r = 0; r < 4; r++) {
                int kp = r * 8 + kpB;
                uint4 v = *(const uint4*)(Vb + (size_t)((k0 >> 1) + kp) * DHh + dB);
                sV[(size_t)kp * VST + dB] = v.x;
                sV[(size_t)kp * VST + dB + 1] = v.z;
            }
        }
        __syncthreads();   // A

        if (more) {
            float accg[5][4] = {};
            int nb = wid * 8 + g;
#pragma unroll
            for (int c = 0; c < 4; c++) {
                uint2 v0 = sK[(size_t)(c * 8 + tg) * KST + nb];
                uint2 v1 = sK[(size_t)(c * 8 + tg + 4) * KST + nb];
#pragma unroll
                for (int mi = 0; mi < 5; mi++) {
                    int m = mi * 16 + g;
                    uint32_t u0 = sQ[(size_t)(c * 8 + tg) * QST2 + m];
                    uint32_t u1 = sQ[(size_t)(c * 8 + tg) * QST2 + m + 8];
                    uint32_t u2 = sQ[(size_t)(c * 8 + tg + 4) * QST2 + m];
                    uint32_t u3 = sQ[(size_t)(c * 8 + tg + 4) * QST2 + m + 8];
                    mma16h(accg[mi], u0, u1, u2, u3, v0.x, v1.x);
                    mma16h(accg[mi], u0, u1, u2, u3, v0.y, v1.y);
                }
            }
            int c0 = ((it + 1) & 1) * 64 + wid * 8 + 2 * tg;
#pragma unroll
            for (int mi = 0; mi < 5; mi++) {
                int r0 = mi * 16 + g;
                if (r0 < 68) {
                    sG[r0 * GS2 + c0] = accg[mi][0] * SCALEc;
                    sG[r0 * GS2 + c0 + 1] = accg[mi][1] * SCALEc;
                }
                if (r0 + 8 < 68) {
                    sG[(r0 + 8) * GS2 + c0] = accg[mi][2] * SCALEc;
                    sG[(r0 + 8) * GS2 + c0 + 1] = accg[mi][3] * SCALEc;
                }
            }
        }
        __syncthreads();   // B

        // scores: vectorized shift-sum (5 rows x 5 float4 + register shifts)
        float sv[16];
#pragma unroll
        for (int i = 0; i < 16; i++) sv[i] = 0.f;
        int cb0 = ((it & 1) << 6) + kbase;
#pragma unroll
        for (int j = 0; j < Ww; j++) {
            const float* rp = sG + (srow + j) * GS2;
            float rr[20];
#pragma unroll
            for (int m = 0; m < 5; m++) {
                float4 v = *(const float4*)(rp + ((cb0 + 4 * m) & 127));
                rr[4 * m + 0] = v.x; rr[4 * m + 1] = v.y;
                rr[4 * m + 2] = v.z; rr[4 * m + 3] = v.w;
            }
#pragma unroll
            for (int i = 0; i < 16; i++) sv[i] += rr[i + j];
        }
        float lmax = -1e30f;
#pragma unroll
        for (int i = 0; i < 16; i++) {
            if (k0 + kbase + i >= SKk) sv[i] = -1e30f;
            lmax = fmaxf(lmax, sv[i]);
        }
        lmax = fmaxf(lmax, __shfl_xor_sync(0xffffffffu, lmax, 1));
        lmax = fmaxf(lmax, __shfl_xor_sync(0xffffffffu, lmax, 2));
        float mnew = fmaxf(m_run, lmax);
        float lsum = 0.f;
#pragma unroll
        for (int i = 0; i < 16; i += 2) {
            float p0 = __expf(sv[i] - mnew);
            float p1 = __expf(sv[i + 1] - mnew);
            lsum += p0 + p1;
            sPh[(size_t)((kbase >> 1) + (i >> 1)) * PST + srow] = h2pack(p0, p1);
        }
        lsum += __shfl_xor_sync(0xffffffffu, lsum, 1);
        lsum += __shfl_xor_sync(0xffffffffu, lsum, 2);
        float fac = __expf(m_run - mnew);
        l_run = l_run * fac + lsum;
        m_run = mnew;
        if ((t & 3) == 0) sFac[srow] = fac;
        __syncthreads();   // C

        // rescale + AV MMA (fp16 x1: P single, V single)
        {
            float f0 = sFac[wm * 16 + g];
            float f1 = sFac[wm * 16 + g + 8];
#pragma unroll
            for (int ni = 0; ni < 4; ni++) {
                acc[ni][0] *= f0; acc[ni][1] *= f0;
                acc[ni][2] *= f1; acc[ni][3] *= f1;
            }
#pragma unroll
            for (int c = 0; c < 4; c++) {
                int m = wm * 16 + g;
                uint32_t u0 = sPh[(size_t)(c * 8 + tg) * PST + m];
                uint32_t u1 = sPh[(size_t)(c * 8 + tg) * PST + m + 8];
                uint32_t u2 = sPh[(size_t)(c * 8 + tg + 4) * PST + m];
                uint32_t u3 = sPh[(size_t)(c * 8 + tg + 4) * PST + m + 8];
#pragma unroll
                for (int ni = 0; ni < 4; ni++) {
                    int n = wn * 32 + ni * 8 + g;
                    uint32_t v0 = sV[(size_t)(c * 8 + tg) * VST + n];
                    uint32_t v1 = sV[(size_t)(c * 8 + tg + 4) * VST + n];
                    mma16h(acc[ni], u0, u1, u2, u3, v0, v1);
                }
            }
        }
        __syncthreads();   // D
    }

    if ((t & 3) == 0) sLf[srow] = l_run;
    __syncthreads();

    float inv0 = 1.f / sLf[wm * 16 + g];
    float inv1 = 1.f / sLf[wm * 16 + g + 8];
    float* Cb = g_attn + (size_t)b * Ss * Ee + h * DHh;
#pragma unroll
    for (int ni = 0; ni < 4; ni++) {
        int r0 = q0 + wm * 16 + g;
        int c0 = wn * 32 + ni * 8 + 2 * tg;
        Cb[(size_t)r0 * Ee + c0] = acc[ni][0] * inv0;
        Cb[(size_t)r0 * Ee + c0 + 1] = acc[ni][1] * inv0;
        Cb[(size_t)(r0 + 8) * Ee + c0] = acc[ni][2] * inv1;
        Cb[(size_t)(r0 + 8) * Ee + c0 + 1] = acc[ni][3] * inv1;
    }
}

// ---------------- LayerNorm: one warp per row, shuffle-only reductions ----------------
__launch_bounds__(256)
__global__ void k_ln(const float* __restrict__ in, const float* __restrict__ w,
                     const float* __restrict__ bz, float* __restrict__ out,
                     uint2* __restrict__ outp) {
    int row = blockIdx.x * 8 + (threadIdx.x >> 5);
    int lane = threadIdx.x & 31;
    const float* x = in + (size_t)row * Ee;

    float4 v[4];
#pragma unroll
    for (int j = 0; j < 4; j++)
        v[j] = *(const float4*)(x + 4 * (lane + j * 32));

    float s = 0.f;
#pragma unroll
    for (int j = 0; j < 4; j++) s += v[j].x + v[j].y + v[j].z + v[j].w;
#pragma unroll
    for (int off = 16; off > 0; off >>= 1)
        s += __shfl_xor_sync(0xffffffffu, s, off);
    float m = s * (1.0f / Ee);

    float vs = 0.f;
#pragma unroll
    for (int j = 0; j < 4; j++) {
        float d0 = v[j].x - m, d1 = v[j].y - m, d2 = v[j].z - m, d3 = v[j].w - m;
        vs += d0 * d0 + d1 * d1 + d2 * d2 + d3 * d3;
    }
#pragma unroll
    for (int off = 16; off > 0; off >>= 1)
        vs += __shfl_xor_sync(0xffffffffu, vs, off);
    float inv = rsqrtf(vs * (1.0f / Ee) + 1e-5f);

#pragma unroll
    for (int j = 0; j < 4; j++) {
        int c = 4 * (lane + j * 32);
        float4 wv = *(const float4*)(w + c);
        float4 bv = *(const float4*)(bz + c);
        float y0 = (v[j].x - m) * inv * wv.x + bv.x;
        float y1 = (v[j].y - m) * inv * wv.y + bv.y;
        float y2 = (v[j].z - m) * inv * wv.z + bv.z;
        float y3 = (v[j].w - m) * inv * wv.w + bv.w;
        *(float4*)(out + (size_t)row * Ee + c) = make_float4(y0, y1, y2, y3);
        uint2 p0 = sp2(y0, y1);
        uint2 p1 = sp2(y2, y3);
        *(uint4*)(outp + (size_t)row * (Ee / 2) + (c >> 1)) =
            make_uint4(p0.x, p0.y, p1.x, p1.y);
    }
}

// ---------------- output head ----------------
__launch_bounds__(256)
__global__ void k_out_partial(const float* __restrict__ ow) {
    int b = blockIdx.y, c = blockIdx.x;
    const int per = (Ss * Ee) / CHUNKS;
    const float* x = g_x + (size_t)b * Ss * Ee + (size_t)c * per;
    const float* wr = ow + (size_t)c * per * OUTo;
    int t = threadIdx.x;
    float acc[OUTo] = {};
    for (int i = t; i < per; i += 256) {
        float xv = x[i];
#pragma unroll
        for (int o = 0; o < OUTo; o++) acc[o] = fmaf(xv, wr[(size_t)i * OUTo + o], acc[o]);
    }
    __shared__ float red[256 * OUTo];
#pragma unroll
    for (int o = 0; o < OUTo; o++) red[t * OUTo + o] = acc[o];
    __syncthreads();
    for (int off = 128; off > 0; off >>= 1) {
        if (t < off) {
#pragma unroll
            for (int o = 0; o < OUTo; o++)
                red[t * OUTo + o] += red[(t + off) * OUTo + o];
        }
        __syncthreads();
    }
    if (t == 0) {
#pragma unroll
        for (int o = 0; o < OUTo; o++)
            g_part[((size_t)b * CHUNKS + c) * OUTo + o] = red[o];
    }
}

__global__ void k_out_final(const float* __restrict__ ob, float* __restrict__ out) {
    int b = blockIdx.x;
    int o = threadIdx.x;
    if (o < OUTo) {
        float s = ob[o];
        for (int c = 0; c < CHUNKS; c++) s += g_part[(b * CHUNKS + c) * OUTo + o];
        out[b * OUTo + o] = s;
    }
}

// ---------------- host launcher ----------------
extern "C" void kernel_launch(void* const* d_in, const int* in_sizes, int n_in,
                              void* d_out, int out_size) {
    const int*   inputs = (const int*)d_in[0];
    const float* emb    = (const float*)d_in[1];
    const float* ln_w   = (const float*)d_in[2];
    const float* ln_b   = (const float*)d_in[3];
    const float* q_w    = (const float*)d_in[4];
    const float* q_b    = (const float*)d_in[5];
    const float* k_w    = (const float*)d_in[6];
    const float* k_b    = (const float*)d_in[7];
    const float* v_w    = (const float*)d_in[8];
    const float* v_b    = (const float*)d_in[9];
    const float* fc1_w  = (const float*)d_in[10];
    const float* fc1_b  = (const float*)d_in[11];
    const float* fc2_w  = (const float*)d_in[12];
    const float* fc2_b  = (const float*)d_in[13];
    const float* out_w  = (const float*)d_in[14];
    const float* out_b  = (const float*)d_in[15];
    float* out = (float*)d_out;

    static int smem_set = 0;
    if (!smem_set) {
        cudaFuncSetAttribute(k_fattn, cudaFuncAttributeMaxDynamicSharedMemorySize, FA_SMEM);
        smem_set = 1;
    }

    float *px, *pattn, *pbqkv;
    uint2 *pxp, *pqkvp, *phidp, *pwqkv, *pwfc1, *pwfc2;
    cudaGetSymbolAddress((void**)&px, g_x);
    cudaGetSymbolAddress((void**)&pattn, g_attn);
    cudaGetSymbolAddress((void**)&pxp, g_xp);
    cudaGetSymbolAddress((void**)&pqkvp, g_qkvp);
    cudaGetSymbolAddress((void**)&phidp, g_hidp);
    cudaGetSymbolAddress((void**)&pwqkv, g_wqkv);
    cudaGetSymbolAddress((void**)&pwfc1, g_wfc1);
    cudaGetSymbolAddress((void**)&pwfc2, g_wfc2);
    cudaGetSymbolAddress((void**)&pbqkv, g_bqkv);

    const int M = Bb * Ss;  // 4096

    k_pack_qkv<<<((Ee / 2) * 1536 + 255) / 256, 256>>>(q_w, k_w, v_w, q_b, k_b, v_b);
    k_pack_w<<<((Ee / 2) * HIDh + 255) / 256, 256>>>(fc1_w, pwfc1, Ee / 2, HIDh);
    k_pack_w<<<((HIDh / 2) * Ee + 255) / 256, 256>>>(fc2_w, pwfc2, HIDh / 2, Ee);

    k_embed<<<(Bb * Ss * (Ee / 2) + 255) / 256, 256>>>(inputs, emb);

    for (int l = 0; l < Ll; l++) {
        // QKV: 128x128 tiles, fp16-packed output for attention
        k_gemm128<1, 0, 1, 1><<<dim3(1536 / 128, M / 128), 256>>>(
            pxp, pwqkv, pbqkv, pqkvp, Ee, Ee / 2, 1536, 1536);

        k_build_vs<<<(Bb * Hh * (SKk / 2) * (DHh / 2) + 255) / 256, 256>>>();

        dim3 gf(Ss / 64, Bb * Hh);
        k_fattn<<<gf, 256, FA_SMEM>>>();

        k_ln<<<M / 8, 256>>>(pattn, ln_w, ln_b, px, pxp);

        // fc1: 128x128 tiles, relu, bf16-packed output
        k_gemm128<1, 1, 1, 0><<<dim3(HIDh / 128, M / 128), 256>>>(
            pxp, pwfc1, fc1_b, phidp, Ee, Ee / 2, HIDh, HIDh);
        // fc2: 64-wide core (residual + fp32 out), 256 CTAs
        dim3 g2(Ee / 64, M / 128);
        k_fc2<<<g2, 256>>>(fc2_b);

        k_ln<<<M / 8, 256>>>(pattn, ln_w, ln_b, px, pxp);
    }

    dim3 go(CHUNKS, Bb);
    k_out_partial<<<go, 256>>>(out_w);
    k_out_final<<<Bb, 32>>>(out_b, out);
}

// round 15
// speedup vs baseline: 1.2416x; 1.1032x over previous
#include <cuda_runtime.h>
#include <cuda_bf16.h>
#include <cuda_fp16.h>
#include <math.h>
#include <stdint.h>

#define Bb 2
#define Ss 2048
#define Ee 512
#define Hh 8
#define DHh 64
#define Ww 5
#define PADp 2
#define SKk 2044
#define HIDh 2048
#define Ll 6
#define OUTo 6
#define SCALEc 0.125f
#define CHUNKS 128
#define SP 2048

#define AST 132   // smem A row stride (uint2)
#define BST 68    // smem B row stride (uint2), 64-wide core
#define BSW 132   // smem B row stride (uint2), 128-wide core
// fattn strides
#define QST2 84
#define KST 68
#define PST 68
#define VST 68
#define GSW 66    // G row stride in uint32 words (132 halfs): EVEN -> aligned LDS.64, conflict-free

// ---------------- scratch ----------------
__device__ float g_x[Bb * Ss * Ee];
__device__ uint2 g_xp[Bb * Ss * (Ee / 2)];               // bf16 hi/lo (GEMM operand)
__device__ uint2 g_qkvp[Bb * Ss * 768];                  // fp16 hi/lo (attention operand)
__device__ uint2 g_hidp[(size_t)Bb * Ss * (HIDh / 2)];   // bf16 hi/lo
__device__ uint2 g_vsp[(size_t)Bb * Hh * (SP / 2) * DHh];// fp16 hi/lo
__device__ float g_attn[Bb * Ss * Ee];
__device__ float g_part[Bb * CHUNKS * OUTo];
__device__ uint2 g_wqkv[(Ee / 2) * 1536];
__device__ float g_bqkv[1536];
__device__ uint2 g_wfc1[(Ee / 2) * HIDh];
__device__ uint2 g_wfc2[(HIDh / 2) * Ee];

// ---------------- bf16 split/pack ----------------
__device__ __forceinline__ uint2 sp2(float x, float y) {
    __nv_bfloat16 xh = __float2bfloat16_rn(x);
    __nv_bfloat16 yh = __float2bfloat16_rn(y);
    float xr = x - __bfloat162float(xh);
    float yr = y - __bfloat162float(yh);
    __nv_bfloat16 xl = __float2bfloat16_rn(xr);
    __nv_bfloat16 yl = __float2bfloat16_rn(yr);
    uint2 w;
    w.x = ((uint32_t)__bfloat16_as_ushort(yh) << 16) | (uint32_t)__bfloat16_as_ushort(xh);
    w.y = ((uint32_t)__bfloat16_as_ushort(yl) << 16) | (uint32_t)__bfloat16_as_ushort(xl);
    return w;
}

// ---------------- fp16 split/pack ----------------
__device__ __forceinline__ uint32_t h2pack(float x, float y) {
    __half2 h = __floats2half2_rn(x, y);
    return *(uint32_t*)&h;
}
__device__ __forceinline__ float2 h2f2(uint32_t u) {
    __half2 h = *(__half2*)&u;
    return __half22float2(h);
}
__device__ __forceinline__ uint32_t hadd2u(uint32_t a, uint32_t b) {
    __half2 r = __hadd2(*(__half2*)&a, *(__half2*)&b);
    return *(uint32_t*)&r;
}
__device__ __forceinline__ uint2 sph2(float x, float y) {
    float hx = __half2float(__float2half_rn(x));
    float hy = __half2float(__float2half_rn(y));
    uint2 w;
    w.x = h2pack(hx, hy);
    w.y = h2pack(x - hx, y - hy);
    return w;
}

__device__ __forceinline__ void mma16(float c[4], uint32_t a0, uint32_t a1, uint32_t a2,
                                      uint32_t a3, uint32_t b0, uint32_t b1) {
    asm volatile(
        "mma.sync.aligned.m16n8k16.row.col.f32.bf16.bf16.f32 "
        "{%0,%1,%2,%3},{%4,%5,%6,%7},{%8,%9},{%0,%1,%2,%3};"
        : "+f"(c[0]), "+f"(c[1]), "+f"(c[2]), "+f"(c[3])
        : "r"(a0), "r"(a1), "r"(a2), "r"(a3), "r"(b0), "r"(b1));
}

__device__ __forceinline__ void mma16h(float c[4], uint32_t a0, uint32_t a1, uint32_t a2,
                                       uint32_t a3, uint32_t b0, uint32_t b1) {
    asm volatile(
        "mma.sync.aligned.m16n8k16.row.col.f32.f16.f16.f32 "
        "{%0,%1,%2,%3},{%4,%5,%6,%7},{%8,%9},{%0,%1,%2,%3};"
        : "+f"(c[0]), "+f"(c[1]), "+f"(c[2]), "+f"(c[3])
        : "r"(a0), "r"(a1), "r"(a2), "r"(a3), "r"(b0), "r"(b1));
}

// one 16-k chunk over 128x64 tile (warp tile 32x32) -- 64-wide core (bf16x3)
__device__ __forceinline__ void mma_chunk(const uint2* sA, const uint2* sB,
                                          int wm, int wn, int lane, float acc[2][4][4]) {
    int g = lane >> 2, tg = lane & 3;
    uint32_t ah[2][4], al[2][4];
#pragma unroll
    for (int mi = 0; mi < 2; mi++) {
        int m = wm * 32 + mi * 16 + g;
        uint2 u0 = sA[(size_t)tg * AST + m];
        uint2 u1 = sA[(size_t)tg * AST + m + 8];
        uint2 u2 = sA[(size_t)(tg + 4) * AST + m];
        uint2 u3 = sA[(size_t)(tg + 4) * AST + m + 8];
        ah[mi][0] = u0.x; al[mi][0] = u0.y;
        ah[mi][1] = u1.x; al[mi][1] = u1.y;
        ah[mi][2] = u2.x; al[mi][2] = u2.y;
        ah[mi][3] = u3.x; al[mi][3] = u3.y;
    }
#pragma unroll
    for (int ni = 0; ni < 4; ni++) {
        int n = wn * 32 + ni * 8 + g;
        uint2 v0 = sB[(size_t)tg * BST + n];
        uint2 v1 = sB[(size_t)(tg + 4) * BST + n];
#pragma unroll
        for (int mi = 0; mi < 2; mi++) {
            mma16(acc[mi][ni], ah[mi][0], ah[mi][1], ah[mi][2], ah[mi][3], v0.x, v1.x);
            mma16(acc[mi][ni], ah[mi][0], ah[mi][1], ah[mi][2], ah[mi][3], v0.y, v1.y);
            mma16(acc[mi][ni], al[mi][0], al[mi][1], al[mi][2], al[mi][3], v0.x, v1.x);
        }
    }
}

// ---------------- 64-wide packed GEMM core (fc2, bf16x3) ----------------
__launch_bounds__(256)
__global__ void k_fc2(const float* __restrict__ bias) {
    const uint2* __restrict__ A = g_hidp;
    const uint2* __restrict__ B = g_wfc2;
    const float* __restrict__ res = g_x;
    float* __restrict__ C = g_attn;
    const int K = HIDh, lda2 = HIDh / 2, ldb2 = Ee, ldc = Ee;

    __shared__ uint2 sA[2][8 * AST];
    __shared__ uint2 sB[2][8 * BST];
    int t = threadIdx.x, lane = t & 31, wid = t >> 5;
    int wm = wid & 3, wn = wid >> 2;
    int bm = blockIdx.y * 128, bn = blockIdx.x * 64;
    float acc[2][4][4] = {};

    int mA = t & 127, koA2 = (t >> 7) * 4;
    const uint2* Arow = A + (size_t)(bm + mA) * lda2 + koA2;
    int kpB = t >> 5, nB = (t & 31) * 2;
    const uint2* Bp = B + (size_t)kpB * ldb2 + bn + nB;

    uint4 a0 = *(const uint4*)(Arow);
    uint4 a1 = *(const uint4*)(Arow + 2);
    uint4 b0 = *(const uint4*)(Bp);

    {
        uint2* pa = sA[0];
        pa[(size_t)(koA2 + 0) * AST + mA] = make_uint2(a0.x, a0.y);
        pa[(size_t)(koA2 + 1) * AST + mA] = make_uint2(a0.z, a0.w);
        pa[(size_t)(koA2 + 2) * AST + mA] = make_uint2(a1.x, a1.y);
        pa[(size_t)(koA2 + 3) * AST + mA] = make_uint2(a1.z, a1.w);
        uint2* pb = sB[0];
        pb[(size_t)kpB * BST + nB]     = make_uint2(b0.x, b0.y);
        pb[(size_t)kpB * BST + nB + 1] = make_uint2(b0.z, b0.w);
    }
    __syncthreads();

    int nch = K >> 4;
    for (int ch = 0; ch < nch; ch++) {
        int s = ch & 1;
        bool more = (ch + 1 < nch);
        if (more) {
            int off = (ch + 1) * 8;
            a0 = *(const uint4*)(Arow + off);
            a1 = *(const uint4*)(Arow + off + 2);
            b0 = *(const uint4*)(Bp + (size_t)(ch + 1) * 8 * ldb2);
        }
        mma_chunk(sA[s], sB[s], wm, wn, lane, acc);
        if (more) {
            int s2 = s ^ 1;
            uint2* pa = sA[s2];
            pa[(size_t)(koA2 + 0) * AST + mA] = make_uint2(a0.x, a0.y);
            pa[(size_t)(koA2 + 1) * AST + mA] = make_uint2(a0.z, a0.w);
            pa[(size_t)(koA2 + 2) * AST + mA] = make_uint2(a1.x, a1.y);
            pa[(size_t)(koA2 + 3) * AST + mA] = make_uint2(a1.z, a1.w);
            uint2* pb = sB[s2];
            pb[(size_t)kpB * BST + nB]     = make_uint2(b0.x, b0.y);
            pb[(size_t)kpB * BST + nB + 1] = make_uint2(b0.z, b0.w);
        }
        __syncthreads();
    }

    int g = lane >> 2, tg = lane & 3;
#pragma unroll
    for (int mi = 0; mi < 2; mi++)
#pragma unroll
        for (int ni = 0; ni < 4; ni++) {
            int r0 = bm + wm * 32 + mi * 16 + g;
            int c0 = bn + wn * 32 + ni * 8 + 2 * tg;
            float bv0 = bias[c0], bv1 = bias[c0 + 1];
            float v00 = acc[mi][ni][0] + bv0 + res[(size_t)r0 * ldc + c0];
            float v01 = acc[mi][ni][1] + bv1 + res[(size_t)r0 * ldc + c0 + 1];
            float v10 = acc[mi][ni][2] + bv0 + res[(size_t)(r0 + 8) * ldc + c0];
            float v11 = acc[mi][ni][3] + bv1 + res[(size_t)(r0 + 8) * ldc + c0 + 1];
            C[(size_t)r0 * ldc + c0] = v00;
            C[(size_t)r0 * ldc + c0 + 1] = v01;
            C[(size_t)(r0 + 8) * ldc + c0] = v10;
            C[(size_t)(r0 + 8) * ldc + c0 + 1] = v11;
        }
}

// ---------------- 128x128 packed GEMM (qkv, fc1; bf16x3; PKH: fp16 vs bf16 out) ----
template <int BIAS, int RELU, int WPK, int PKH>
__launch_bounds__(256, 2)
__global__ void k_gemm128(const uint2* __restrict__ A, const uint2* __restrict__ B,
                          const float* __restrict__ bias,
                          uint2* __restrict__ Cp,
                          int K, int lda2, int ldb2, int ldc) {
    __shared__ uint2 sA[2][8 * AST];
    __shared__ uint2 sB2[2][8 * BSW];
    int t = threadIdx.x, lane = t & 31, wid = t >> 5;
    int wm = wid & 3, wn = wid >> 2;
    int g = lane >> 2, tg = lane & 3;
    int bm = blockIdx.y * 128, bn = blockIdx.x * 128;
    float acc[2][8][4] = {};

    int mA = t & 127, koA2 = (t >> 7) * 4;
    const uint2* Arow = A + (size_t)(bm + mA) * lda2 + koA2;
    int kpB = t >> 5, nB = (t & 31) * 4;
    const uint2* Bp = B + (size_t)kpB * ldb2 + bn + nB;

    uint4 a0 = *(const uint4*)(Arow);
    uint4 a1 = *(const uint4*)(Arow + 2);
    uint4 b0 = *(const uint4*)(Bp);
    uint4 b1 = *(const uint4*)(Bp + 2);

    {
        uint2* pa = sA[0];
        pa[(size_t)(koA2 + 0) * AST + mA] = make_uint2(a0.x, a0.y);
        pa[(size_t)(koA2 + 1) * AST + mA] = make_uint2(a0.z, a0.w);
        pa[(size_t)(koA2 + 2) * AST + mA] = make_uint2(a1.x, a1.y);
        pa[(size_t)(koA2 + 3) * AST + mA] = make_uint2(a1.z, a1.w);
        uint2* pb = sB2[0];
        pb[(size_t)kpB * BSW + nB]     = make_uint2(b0.x, b0.y);
        pb[(size_t)kpB * BSW + nB + 1] = make_uint2(b0.z, b0.w);
        pb[(size_t)kpB * BSW + nB + 2] = make_uint2(b1.x, b1.y);
        pb[(size_t)kpB * BSW + nB + 3] = make_uint2(b1.z, b1.w);
    }
    __syncthreads();

    int nch = K >> 4;
    for (int ch = 0; ch < nch; ch++) {
        int s = ch & 1;
        bool more = (ch + 1 < nch);
        if (more) {
            int off = (ch + 1) * 8;
            a0 = *(const uint4*)(Arow + off);
            a1 = *(const uint4*)(Arow + off + 2);
            const uint2* Bn = Bp + (size_t)(ch + 1) * 8 * ldb2;
            b0 = *(const uint4*)(Bn);
            b1 = *(const uint4*)(Bn + 2);
        }
        {
            const uint2* pa = sA[s];
            const uint2* pb = sB2[s];
            uint32_t ah[2][4], al[2][4];
#pragma unroll
            for (int mi = 0; mi < 2; mi++) {
                int m = wm * 32 + mi * 16 + g;
                uint2 u0 = pa[(size_t)tg * AST + m];
                uint2 u1 = pa[(size_t)tg * AST + m + 8];
                uint2 u2 = pa[(size_t)(tg + 4) * AST + m];
                uint2 u3 = pa[(size_t)(tg + 4) * AST + m + 8];
                ah[mi][0] = u0.x; al[mi][0] = u0.y;
                ah[mi][1] = u1.x; al[mi][1] = u1.y;
                ah[mi][2] = u2.x; al[mi][2] = u2.y;
                ah[mi][3] = u3.x; al[mi][3] = u3.y;
            }
#pragma unroll
            for (int ni = 0; ni < 8; ni++) {
                int n = wn * 64 + ni * 8 + g;
                uint2 v0 = pb[(size_t)tg * BSW + n];
                uint2 v1 = pb[(size_t)(tg + 4) * BSW + n];
#pragma unroll
                for (int mi = 0; mi < 2; mi++) {
                    mma16(acc[mi][ni], ah[mi][0], ah[mi][1], ah[mi][2], ah[mi][3], v0.x, v1.x);
                    mma16(acc[mi][ni], ah[mi][0], ah[mi][1], ah[mi][2], ah[mi][3], v0.y, v1.y);
                    mma16(acc[mi][ni], al[mi][0], al[mi][1], al[mi][2], al[mi][3], v0.x, v1.x);
                }
            }
        }
        if (more) {
            int s2 = s ^ 1;
            uint2* pa = sA[s2];
            pa[(size_t)(koA2 + 0) * AST + mA] = make_uint2(a0.x, a0.y);
            pa[(size_t)(koA2 + 1) * AST + mA] = make_uint2(a0.z, a0.w);
            pa[(size_t)(koA2 + 2) * AST + mA] = make_uint2(a1.x, a1.y);
            pa[(size_t)(koA2 + 3) * AST + mA] = make_uint2(a1.z, a1.w);
            uint2* pb = sB2[s2];
            pb[(size_t)kpB * BSW + nB]     = make_uint2(b0.x, b0.y);
            pb[(size_t)kpB * BSW + nB + 1] = make_uint2(b0.z, b0.w);
            pb[(size_t)kpB * BSW + nB + 2] = make_uint2(b1.x, b1.y);
            pb[(size_t)kpB * BSW + nB + 3] = make_uint2(b1.z, b1.w);
        }
        __syncthreads();
    }

#pragma unroll
    for (int mi = 0; mi < 2; mi++)
#pragma unroll
        for (int ni = 0; ni < 8; ni++) {
            int r0 = bm + wm * 32 + mi * 16 + g;
            int c0 = bn + wn * 64 + ni * 8 + 2 * tg;
            float v00 = acc[mi][ni][0], v01 = acc[mi][ni][1];
            float v10 = acc[mi][ni][2], v11 = acc[mi][ni][3];
            if (BIAS) {
                float bv0 = bias[c0], bv1 = bias[c0 + 1];
                v00 += bv0; v01 += bv1; v10 += bv0; v11 += bv1;
            }
            if (RELU) {
                v00 = fmaxf(v00, 0.f); v01 = fmaxf(v01, 0.f);
                v10 = fmaxf(v10, 0.f); v11 = fmaxf(v11, 0.f);
            }
            if (WPK) {
                if (PKH) {
                    Cp[(size_t)r0 * (ldc >> 1) + (c0 >> 1)] = sph2(v00, v01);
                    Cp[(size_t)(r0 + 8) * (ldc >> 1) + (c0 >> 1)] = sph2(v10, v11);
                } else {
                    Cp[(size_t)r0 * (ldc >> 1) + (c0 >> 1)] = sp2(v00, v01);
                    Cp[(size_t)(r0 + 8) * (ldc >> 1) + (c0 >> 1)] = sp2(v10, v11);
                }
            }
        }
}

// ---------------- weight packing ----------------
__global__ void k_pack_qkv(const float* __restrict__ qw, const float* __restrict__ kw,
                           const float* __restrict__ vw, const float* __restrict__ qb,
                           const float* __restrict__ kb, const float* __restrict__ vb) {
    int idx = blockIdx.x * 256 + threadIdx.x;
    if (idx < (Ee / 2) * 1536) {
        int n = idx % 1536, kp = idx / 1536;
        const float* W = (n < 512) ? qw : (n < 1024 ? kw : vw);
        int c = n & 511;
        g_wqkv[idx] = sp2(W[(size_t)(2 * kp) * 512 + c], W[(size_t)(2 * kp + 1) * 512 + c]);
    }
    if (idx < 1536)
        g_bqkv[idx] = (idx < 512) ? qb[idx] : (idx < 1024 ? kb[idx - 512] : vb[idx - 1024]);
}

__global__ void k_pack_w(const float* __restrict__ W, uint2* __restrict__ out, int Kp, int N) {
    int idx = blockIdx.x * 256 + threadIdx.x;
    if (idx >= Kp * N) return;
    int n = idx % N, kp = idx / N;
    out[idx] = sp2(W[(size_t)(2 * kp) * N + n], W[(size_t)(2 * kp + 1) * N + n]);
}

// ---------------- embedding + positional encoding ----------------
__global__ void k_embed(const int* __restrict__ inp, const float* __restrict__ emb) {
    int idx = blockIdx.x * blockDim.x + threadIdx.x;
    if (idx >= Bb * Ss * (Ee / 2)) return;
    int ep = idx % (Ee / 2);
    int bs = idx / (Ee / 2);
    int s = bs % Ss;
    int tok = inp[bs];
    int e0 = 2 * ep;
    const float LN1E4 = 9.210340371976184f;
    float freq = expf(-(float)e0 * (LN1E4 / (float)Ee));
    float ang = (float)s * freq;
    float x0 = emb[(size_t)tok * Ee + e0] + sinf(ang);
    float x1 = emb[(size_t)tok * Ee + e0 + 1] + cosf(ang);
    g_x[(size_t)bs * Ee + e0] = x0;
    g_x[(size_t)bs * Ee + e0 + 1] = x1;
    g_xp[(size_t)bs * (Ee / 2) + ep] = sp2(x0, x1);
}

// ---------------- window-summed V (fp16 packed in/out) ----------------
__global__ void k_build_vs() {
    int idx = blockIdx.x * blockDim.x + threadIdx.x;
    if (idx >= Bb * Hh * (SKk / 2) * (DHh / 2)) return;
    int dp = idx & 31;
    int rest = idx >> 5;
    int kp = rest % (SKk / 2);
    int bh = rest / (SKk / 2);
    int b = bh >> 3, h = bh & 7;
    const uint2* Vp = g_qkvp + (size_t)b * Ss * 768 + 512 + h * 32 + dp;
    int k = 2 * kp;
    float v0[6], v1[6];
#pragma unroll
    for (int r = 0; r < 6; r++) {
        uint2 w = Vp[(size_t)(k + r) * 768];
        float2 hi = h2f2(w.x), lo = h2f2(w.y);
        v0[r] = hi.x + lo.x;
        v1[r] = hi.y + lo.y;
    }
    float s00 = v0[0] + v0[1] + v0[2] + v0[3] + v0[4];
    float s10 = v0[1] + v0[2] + v0[3] + v0[4] + v0[5];
    float s01 = v1[0] + v1[1] + v1[2] + v1[3] + v1[4];
    float s11 = v1[1] + v1[2] + v1[3] + v1[4] + v1[5];
    uint2* dst = g_vsp + ((size_t)bh * (SP / 2) + kp) * DHh + 2 * dp;
    dst[0] = sph2(s00, s10);
    dst[1] = sph2(s01, s11);
}

// ---------------- fused attention (64-row q-tiles; fp16 path, fp16 G) --------
#define FA_OFF_Q  0                          // 32 x 84 uint   = 10752
#define FA_OFF_K  10752                      // 32 x 68 uint2  = 17408
#define FA_OFF_G  28160                      // 68 x 66 uint   = 17952
#define FA_OFF_P  46384                      // 32 x 68 uint   = 8704
#define FA_OFF_V  55088                      // 2 x 32 x 68 uint = 17408
#define FA_OFF_S  72496                      // sFac[64] + sLf[64]
#define FA_SMEM   73008

__launch_bounds__(256)
__global__ void k_fattn() {
    extern __shared__ char dyn[];
    uint32_t* sQ = (uint32_t*)(dyn + FA_OFF_Q);
    uint2* sK = (uint2*)(dyn + FA_OFF_K);
    uint32_t* sGh = (uint32_t*)(dyn + FA_OFF_G);   // [68][GSW] half2 words, 128-col ring
    uint32_t* sPh = (uint32_t*)(dyn + FA_OFF_P);
    uint32_t* sV = (uint32_t*)(dyn + FA_OFF_V);    // double buffered
    float* sFac = (float*)(dyn + FA_OFF_S);
    float* sLf = sFac + 64;

    int qt = blockIdx.x;
    int bh = blockIdx.y;
    int b = bh >> 3, h = bh & 7;
    int q0 = qt * 64;
    const uint2* Qb = g_qkvp + (size_t)b * Ss * 768 + h * 32;
    const uint2* Kb = g_qkvp + (size_t)b * Ss * 768 + 256 + h * 32;
    const uint2* Vb = g_vsp + (size_t)bh * (SP / 2) * DHh;

    int t = threadIdx.x, lane = t & 31, wid = t >> 5;
    int wm = wid & 3, wn = wid >> 2;
    int g = lane >> 2, tg = lane & 3;
    float acc[4][4] = {};
    float m_run = -1e30f, l_run = 0.f;
    int srow = t >> 2, kbase = (t & 3) * 16;

    // load Q tile (hi plane only): rows 0..67 = global q0-2..q0+65; 68..79 zero
    {
        int dpq = (t & 3) * 8;
        int rr = t >> 2;
#pragma unroll
        for (int rb = 0; rb < 80; rb += 64) {
            int r = rb + rr;
            if (r < 80) {
                int gr = q0 - 2 + r;
                bool ok = (r < 68) && (gr >= 0) && (gr < Ss);
#pragma unroll
                for (int u = 0; u < 8; u += 2) {
                    uint4 v = make_uint4(0, 0, 0, 0);
                    if (ok) v = *(const uint4*)(Qb + (size_t)gr * 768 + dpq + u);
                    sQ[(size_t)(dpq + u) * QST2 + r] = v.x;
                    sQ[(size_t)(dpq + u + 1) * QST2 + r] = v.z;
                }
            }
        }
    }
    // load K panel 0 (hi/lo)
    {
        int r = t >> 2, dpq = (t & 3) * 8;
        const uint2* src = Kb + (size_t)r * 768 + dpq;
#pragma unroll
        for (int u = 0; u < 8; u += 2) {
            uint4 v = *(const uint4*)(src + u);
            sK[(size_t)(dpq + u) * KST + r] = make_uint2(v.x, v.y);
            sK[(size_t)(dpq + u + 1) * KST + r] = make_uint2(v.z, v.w);
        }
    }
    __syncthreads();

    // gram panel 0 -> ring slot 0 (fp16 x2), packed half2 store
    {
        float accg[5][4] = {};
        int nb = wid * 8 + g;
#pragma unroll
        for (int c = 0; c < 4; c++) {
            uint2 v0 = sK[(size_t)(c * 8 + tg) * KST + nb];
            uint2 v1 = sK[(size_t)(c * 8 + tg + 4) * KST + nb];
#pragma unroll
            for (int mi = 0; mi < 5; mi++) {
                int m = mi * 16 + g;
                uint32_t u0 = sQ[(size_t)(c * 8 + tg) * QST2 + m];
                uint32_t u1 = sQ[(size_t)(c * 8 + tg) * QST2 + m + 8];
                uint32_t u2 = sQ[(size_t)(c * 8 + tg + 4) * QST2 + m];
                uint32_t u3 = sQ[(size_t)(c * 8 + tg + 4) * QST2 + m + 8];
                mma16h(accg[mi], u0, u1, u2, u3, v0.x, v1.x);
                mma16h(accg[mi], u0, u1, u2, u3, v0.y, v1.y);
            }
        }
        int cw = (wid * 8 + 2 * tg) >> 1;   // half2 word within ring
#pragma unroll
        for (int mi = 0; mi < 5; mi++) {
            int r0 = mi * 16 + g;
            if (r0 < 68)
                sGh[r0 * GSW + cw] = h2pack(accg[mi][0] * SCALEc, accg[mi][1] * SCALEc);
            if (r0 + 8 < 68)
                sGh[(r0 + 8) * GSW + cw] = h2pack(accg[mi][2] * SCALEc, accg[mi][3] * SCALEc);
        }
    }
    __syncthreads();

    for (int it = 0; it < 32; it++) {
        int k0 = it * 64;
        bool more = (it < 31);
        uint32_t* sVb = sV + (size_t)(it & 1) * 32 * VST;

        if (more) {
            int r = t >> 2, dpq = (t & 3) * 8;
            const uint2* src = Kb + (size_t)((it + 1) * 64 + r) * 768 + dpq;
#pragma unroll
            for (int u = 0; u < 8; u += 2) {
                uint4 v = *(const uint4*)(src + u);
                sK[(size_t)(dpq + u) * KST + r] = make_uint2(v.x, v.y);
                sK[(size_t)(dpq + u + 1) * KST + r] = make_uint2(v.z, v.w);
            }
        }
        // load V tile (hi plane only) into current buffer
        {
            int kpB = t >> 5, dB = (t & 31) * 2;
#pragma unroll
            for (int r = 0; r < 4; r++) {
                int kp = r * 8 + kpB;
                uint4 v = *(const uint4*)(Vb + (size_t)((k0 >> 1) + kp) * DHh + dB);
                sVb[(size_t)kp * VST + dB] = v.x;
                sVb[(size_t)kp * VST + dB + 1] = v.z;
            }
        }
        __syncthreads();   // A

        if (more) {
            float accg[5][4] = {};
            int nb = wid * 8 + g;
#pragma unroll
            for (int c = 0; c < 4; c++) {
                uint2 v0 = sK[(size_t)(c * 8 + tg) * KST + nb];
                uint2 v1 = sK[(size_t)(c * 8 + tg + 4) * KST + nb];
#pragma unroll
                for (int mi = 0; mi < 5; mi++) {
                    int m = mi * 16 + g;
                    uint32_t u0 = sQ[(size_t)(c * 8 + tg) * QST2 + m];
                    uint32_t u1 = sQ[(size_t)(c * 8 + tg) * QST2 + m + 8];
                    uint32_t u2 = sQ[(size_t)(c * 8 + tg + 4) * QST2 + m];
                    uint32_t u3 = sQ[(size_t)(c * 8 + tg + 4) * QST2 + m + 8];
                    mma16h(accg[mi], u0, u1, u2, u3, v0.x, v1.x);
                    mma16h(accg[mi], u0, u1, u2, u3, v0.y, v1.y);
                }
            }
            int cw = (((it + 1) & 1) * 64 + wid * 8 + 2 * tg) >> 1;
#pragma unroll
            for (int mi = 0; mi < 5; mi++) {
                int r0 = mi * 16 + g;
                if (r0 < 68)
                    sGh[r0 * GSW + cw] = h2pack(accg[mi][0] * SCALEc, accg[mi][1] * SCALEc);
                if (r0 + 8 < 68)
                    sGh[(r0 + 8) * GSW + cw] = h2pack(accg[mi][2] * SCALEc, accg[mi][3] * SCALEc);
            }
        }
        __syncthreads();   // B

        // scores: half2 shift-sum (5 rows x 5 LDS.64 + HADD2/PRMT)
        uint32_t sv2[8];
#pragma unroll
        for (int p = 0; p < 8; p++) sv2[p] = 0u;
        int cb0 = ((it & 1) << 6) + kbase;   // half-index into 128-col ring
#pragma unroll
        for (int j = 0; j < Ww; j++) {
            const uint32_t* rp = sGh + (srow + j) * GSW;
            uint32_t rr2[10];
#pragma unroll
            for (int m = 0; m < 5; m++) {
                uint2 w = *(const uint2*)(rp + (((cb0 + 4 * m) & 127) >> 1));
                rr2[2 * m] = w.x;
                rr2[2 * m + 1] = w.y;
            }
            if (j == 0 || j == 2 || j == 4) {
                int o = j >> 1;
#pragma unroll
                for (int p = 0; p < 8; p++) sv2[p] = hadd2u(sv2[p], rr2[p + o]);
            } else {
                int o = (j - 1) >> 1;
#pragma unroll
                for (int p = 0; p < 8; p++) {
                    uint32_t pr = __byte_perm(rr2[p + o], rr2[p + o + 1], 0x5432);
                    sv2[p] = hadd2u(sv2[p], pr);
                }
            }
        }
        float sv[16];
#pragma unroll
        for (int p = 0; p < 8; p++) {
            float2 f = h2f2(sv2[p]);
            sv[2 * p] = f.x;
            sv[2 * p + 1] = f.y;
        }
        float lmax = -1e30f;
#pragma unroll
        for (int i = 0; i < 16; i++) {
            if (k0 + kbase + i >= SKk) sv[i] = -1e30f;
            lmax = fmaxf(lmax, sv[i]);
        }
        lmax = fmaxf(lmax, __shfl_xor_sync(0xffffffffu, lmax, 1));
        lmax = fmaxf(lmax, __shfl_xor_sync(0xffffffffu, lmax, 2));
        float mnew = fmaxf(m_run, lmax);
        float lsum = 0.f;
#pragma unroll
        for (int i = 0; i < 16; i += 2) {
            float p0 = __expf(sv[i] - mnew);
            float p1 = __expf(sv[i + 1] - mnew);
            lsum += p0 + p1;
            sPh[(size_t)((kbase >> 1) + (i >> 1)) * PST + srow] = h2pack(p0, p1);
        }
        lsum += __shfl_xor_sync(0xffffffffu, lsum, 1);
        lsum += __shfl_xor_sync(0xffffffffu, lsum, 2);
        float fac = __expf(m_run - mnew);
        l_run = l_run * fac + lsum;
        m_run = mnew;
        if ((t & 3) == 0) sFac[srow] = fac;
        __syncthreads();   // C

        // rescale + AV MMA (fp16 x1)
        {
            float f0 = sFac[wm * 16 + g];
            float f1 = sFac[wm * 16 + g + 8];
#pragma unroll
            for (int ni = 0; ni < 4; ni++) {
                acc[ni][0] *= f0; acc[ni][1] *= f0;
                acc[ni][2] *= f1; acc[ni][3] *= f1;
            }
#pragma unroll
            for (int c = 0; c < 4; c++) {
                int m = wm * 16 + g;
                uint32_t u0 = sPh[(size_t)(c * 8 + tg) * PST + m];
                uint32_t u1 = sPh[(size_t)(c * 8 + tg) * PST + m + 8];
                uint32_t u2 = sPh[(size_t)(c * 8 + tg + 4) * PST + m];
                uint32_t u3 = sPh[(size_t)(c * 8 + tg + 4) * PST + m + 8];
#pragma unroll
                for (int ni = 0; ni < 4; ni++) {
                    int n = wn * 32 + ni * 8 + g;
                    uint32_t v0 = sVb[(size_t)(c * 8 + tg) * VST + n];
                    uint32_t v1 = sVb[(size_t)(c * 8 + tg + 4) * VST + n];
                    mma16h(acc[ni], u0, u1, u2, u3, v0, v1);
                }
            }
        }
        // no barrier D: sV double-buffered; sPh/sK/sG protected by next iter's A/B
    }

    __syncthreads();
    if ((t & 3) == 0) sLf[srow] = l_run;
    __syncthreads();

    float inv0 = 1.f / sLf[wm * 16 + g];
    float inv1 = 1.f / sLf[wm * 16 + g + 8];
    float* Cb = g_attn + (size_t)b * Ss * Ee + h * DHh;
#pragma unroll
    for (int ni = 0; ni < 4; ni++) {
        int r0 = q0 + wm * 16 + g;
        int c0 = wn * 32 + ni * 8 + 2 * tg;
        Cb[(size_t)r0 * Ee + c0] = acc[ni][0] * inv0;
        Cb[(size_t)r0 * Ee + c0 + 1] = acc[ni][1] * inv0;
        Cb[(size_t)(r0 + 8) * Ee + c0] = acc[ni][2] * inv1;
        Cb[(size_t)(r0 + 8) * Ee + c0 + 1] = acc[ni][3] * inv1;
    }
}

// ---------------- LayerNorm: one warp per row, shuffle-only reductions ----------------
__launch_bounds__(256)
__global__ void k_ln(const float* __restrict__ in, const float* __restrict__ w,
                     const float* __restrict__ bz, float* __restrict__ out,
                     uint2* __restrict__ outp) {
    int row = blockIdx.x * 8 + (threadIdx.x >> 5);
    int lane = threadIdx.x & 31;
    const float* x = in + (size_t)row * Ee;

    float4 v[4];
#pragma unroll
    for (int j = 0; j < 4; j++)
        v[j] = *(const float4*)(x + 4 * (lane + j * 32));

    float s = 0.f;
#pragma unroll
    for (int j = 0; j < 4; j++) s += v[j].x + v[j].y + v[j].z + v[j].w;
#pragma unroll
    for (int off = 16; off > 0; off >>= 1)
        s += __shfl_xor_sync(0xffffffffu, s, off);
    float m = s * (1.0f / Ee);

    float vs = 0.f;
#pragma unroll
    for (int j = 0; j < 4; j++) {
        float d0 = v[j].x - m, d1 = v[j].y - m, d2 = v[j].z - m, d3 = v[j].w - m;
        vs += d0 * d0 + d1 * d1 + d2 * d2 + d3 * d3;
    }
#pragma unroll
    for (int off = 16; off > 0; off >>= 1)
        vs += __shfl_xor_sync(0xffffffffu, vs, off);
    float inv = rsqrtf(vs * (1.0f / Ee) + 1e-5f);

#pragma unroll
    for (int j = 0; j < 4; j++) {
        int c = 4 * (lane + j * 32);
        float4 wv = *(const float4*)(w + c);
        float4 bv = *(const float4*)(bz + c);
        float y0 = (v[j].x - m) * inv * wv.x + bv.x;
        float y1 = (v[j].y - m) * inv * wv.y + bv.y;
        float y2 = (v[j].z - m) * inv * wv.z + bv.z;
        float y3 = (v[j].w - m) * inv * wv.w + bv.w;
        *(float4*)(out + (size_t)row * Ee + c) = make_float4(y0, y1, y2, y3);
        uint2 p0 = sp2(y0, y1);
        uint2 p1 = sp2(y2, y3);
        *(uint4*)(outp + (size_t)row * (Ee / 2) + (c >> 1)) =
            make_uint4(p0.x, p0.y, p1.x, p1.y);
    }
}

// ---------------- output head ----------------
__launch_bounds__(256)
__global__ void k_out_partial(const float* __restrict__ ow) {
    int b = blockIdx.y, c = blockIdx.x;
    const int per = (Ss * Ee) / CHUNKS;
    const float* x = g_x + (size_t)b * Ss * Ee + (size_t)c * per;
    const float* wr = ow + (size_t)c * per * OUTo;
    int t = threadIdx.x;
    float acc[OUTo] = {};
    for (int i = t; i < per; i += 256) {
        float xv = x[i];
#pragma unroll
        for (int o = 0; o < OUTo; o++) acc[o] = fmaf(xv, wr[(size_t)i * OUTo + o], acc[o]);
    }
    __shared__ float red[256 * OUTo];
#pragma unroll
    for (int o = 0; o < OUTo; o++) red[t * OUTo + o] = acc[o];
    __syncthreads();
    for (int off = 128; off > 0; off >>= 1) {
        if (t < off) {
#pragma unroll
            for (int o = 0; o < OUTo; o++)
                red[t * OUTo + o] += red[(t + off) * OUTo + o];
        }
        __syncthreads();
    }
    if (t == 0) {
#pragma unroll
        for (int o = 0; o < OUTo; o++)
            g_part[((size_t)b * CHUNKS + c) * OUTo + o] = red[o];
    }
}

__global__ void k_out_final(const float* __restrict__ ob, float* __restrict__ out) {
    int b = blockIdx.x;
    int o = threadIdx.x;
    if (o < OUTo) {
        float s = ob[o];
        for (int c = 0; c < CHUNKS; c++) s += g_part[(b * CHUNKS + c) * OUTo + o];
        out[b * OUTo + o] = s;
    }
}

// ---------------- host launcher ----------------
extern "C" void kernel_launch(void* const* d_in, const int* in_sizes, int n_in,
                              void* d_out, int out_size) {
    const int*   inputs = (const int*)d_in[0];
    const float* emb    = (const float*)d_in[1];
    const float* ln_w   = (const float*)d_in[2];
    const float* ln_b   = (const float*)d_in[3];
    const float* q_w    = (const float*)d_in[4];
    const float* q_b    = (const float*)d_in[5];
    const float* k_w    = (const float*)d_in[6];
    const float* k_b    = (const float*)d_in[7];
    const float* v_w    = (const float*)d_in[8];
    const float* v_b    = (const float*)d_in[9];
    const float* fc1_w  = (const float*)d_in[10];
    const float* fc1_b  = (const float*)d_in[11];
    const float* fc2_w  = (const float*)d_in[12];
    const float* fc2_b  = (const float*)d_in[13];
    const float* out_w  = (const float*)d_in[14];
    const float* out_b  = (const float*)d_in[15];
    float* out = (float*)d_out;

    static int smem_set = 0;
    if (!smem_set) {
        cudaFuncSetAttribute(k_fattn, cudaFuncAttributeMaxDynamicSharedMemorySize, FA_SMEM);
        smem_set = 1;
    }

    float *px, *pattn, *pbqkv;
    uint2 *pxp, *pqkvp, *phidp, *pwqkv, *pwfc1, *pwfc2;
    cudaGetSymbolAddress((void**)&px, g_x);
    cudaGetSymbolAddress((void**)&pattn, g_attn);
    cudaGetSymbolAddress((void**)&pxp, g_xp);
    cudaGetSymbolAddress((void**)&pqkvp, g_qkvp);
    cudaGetSymbolAddress((void**)&phidp, g_hidp);
    cudaGetSymbolAddress((void**)&pwqkv, g_wqkv);
    cudaGetSymbolAddress((void**)&pwfc1, g_wfc1);
    cudaGetSymbolAddress((void**)&pwfc2, g_wfc2);
    cudaGetSymbolAddress((void**)&pbqkv, g_bqkv);

    const int M = Bb * Ss;  // 4096

    k_pack_qkv<<<((Ee / 2) * 1536 + 255) / 256, 256>>>(q_w, k_w, v_w, q_b, k_b, v_b);
    k_pack_w<<<((Ee / 2) * HIDh + 255) / 256, 256>>>(fc1_w, pwfc1, Ee / 2, HIDh);
    k_pack_w<<<((HIDh / 2) * Ee + 255) / 256, 256>>>(fc2_w, pwfc2, HIDh / 2, Ee);

    k_embed<<<(Bb * Ss * (Ee / 2) + 255) / 256, 256>>>(inputs, emb);

    for (int l = 0; l < Ll; l++) {
        // QKV: 128x128 tiles, fp16-packed output for attention
        k_gemm128<1, 0, 1, 1><<<dim3(1536 / 128, M / 128), 256>>>(
            pxp, pwqkv, pbqkv, pqkvp, Ee, Ee / 2, 1536, 1536);

        k_build_vs<<<(Bb * Hh * (SKk / 2) * (DHh / 2) + 255) / 256, 256>>>();

        dim3 gf(Ss / 64, Bb * Hh);
        k_fattn<<<gf, 256, FA_SMEM>>>();

        k_ln<<<M / 8, 256>>>(pattn, ln_w, ln_b, px, pxp);

        // fc1: 128x128 tiles, relu, bf16-packed output
        k_gemm128<1, 1, 1, 0><<<dim3(HIDh / 128, M / 128), 256>>>(
            pxp, pwfc1, fc1_b, phidp, Ee, Ee / 2, HIDh, HIDh);
        // fc2: 64-wide core (residual + fp32 out), 256 CTAs
        dim3 g2(Ee / 64, M / 128);
        k_fc2<<<g2, 256>>>(fc2_b);

        k_ln<<<M / 8, 256>>>(pattn, ln_w, ln_b, px, pxp);
    }

    dim3 go(CHUNKS, Bb);
    k_out_partial<<<go, 256>>>(out_w);
    k_out_final<<<Bb, 32>>>(out_b, out);
}

// round 16
// speedup vs baseline: 1.5451x; 1.2444x over previous
#include <cuda_runtime.h>
#include <cuda_bf16.h>
#include <cuda_fp16.h>
#include <math.h>
#include <stdint.h>

#define Bb 2
#define Ss 2048
#define Ee 512
#define Hh 8
#define DHh 64
#define Ww 5
#define PADp 2
#define SKk 2044
#define HIDh 2048
#define Ll 6
#define OUTo 6
#define SCALEc 0.125f
#define CHUNKS 128
#define SP 2048

#define AST 132   // smem A row stride (uint32, single-fp16 pairs)
#define BST 68    // smem B row stride (uint2), 64-wide core
#define BSW 132   // smem B row stride (uint2), 128-wide core
// fattn strides
#define QST2 84
#define KST 68
#define PST 68
#define VST 68
#define GSW 66    // G row stride in uint32 (132 halfs): even -> aligned LDS.64

// ---------------- scratch ----------------
__device__ float g_x[Bb * Ss * Ee];
__device__ uint32_t g_xp[Bb * Ss * (Ee / 2)];            // single fp16 pairs (GEMM A)
__device__ uint2 g_qkvp[Bb * Ss * 768];                  // fp16 hi/lo (attention operand)
__device__ uint32_t g_hid1[(size_t)Bb * Ss * (HIDh / 2)];// single fp16 pairs (fc1 out)
__device__ uint2 g_vsp[(size_t)Bb * Hh * (SP / 2) * DHh];// fp16 hi/lo
__device__ float g_attn[Bb * Ss * Ee];
__device__ float g_part[Bb * CHUNKS * OUTo];
__device__ uint2 g_wqkv[(Ee / 2) * 1536];                // fp16 hi/lo weights
__device__ float g_bqkv[1536];
__device__ uint2 g_wfc1[(Ee / 2) * HIDh];
__device__ uint2 g_wfc2[(HIDh / 2) * Ee];

// ---------------- fp16 pack helpers ----------------
__device__ __forceinline__ uint32_t h2pack(float x, float y) {
    __half2 h = __floats2half2_rn(x, y);
    return *(uint32_t*)&h;
}
__device__ __forceinline__ float2 h2f2(uint32_t u) {
    __half2 h = *(__half2*)&u;
    return __half22float2(h);
}
__device__ __forceinline__ uint32_t hadd2u(uint32_t a, uint32_t b) {
    __half2 r = __hadd2(*(__half2*)&a, *(__half2*)&b);
    return *(uint32_t*)&r;
}
__device__ __forceinline__ uint2 sph2(float x, float y) {
    float hx = __half2float(__float2half_rn(x));
    float hy = __half2float(__float2half_rn(y));
    uint2 w;
    w.x = h2pack(hx, hy);
    w.y = h2pack(x - hx, y - hy);
    return w;
}

__device__ __forceinline__ void mma16h(float c[4], uint32_t a0, uint32_t a1, uint32_t a2,
                                       uint32_t a3, uint32_t b0, uint32_t b1) {
    asm volatile(
        "mma.sync.aligned.m16n8k16.row.col.f32.f16.f16.f32 "
        "{%0,%1,%2,%3},{%4,%5,%6,%7},{%8,%9},{%0,%1,%2,%3};"
        : "+f"(c[0]), "+f"(c[1]), "+f"(c[2]), "+f"(c[3])
        : "r"(a0), "r"(a1), "r"(a2), "r"(a3), "r"(b0), "r"(b1));
}

// one 16-k chunk over 128x64 tile (warp tile 32x32): A single fp16, B hi/lo fp16 (x2)
__device__ __forceinline__ void mma_chunk_h(const uint32_t* sA, const uint2* sB,
                                            int wm, int wn, int lane, float acc[2][4][4]) {
    int g = lane >> 2, tg = lane & 3;
    uint32_t ah[2][4];
#pragma unroll
    for (int mi = 0; mi < 2; mi++) {
        int m = wm * 32 + mi * 16 + g;
        ah[mi][0] = sA[(size_t)tg * AST + m];
        ah[mi][1] = sA[(size_t)tg * AST + m + 8];
        ah[mi][2] = sA[(size_t)(tg + 4) * AST + m];
        ah[mi][3] = sA[(size_t)(tg + 4) * AST + m + 8];
    }
#pragma unroll
    for (int ni = 0; ni < 4; ni++) {
        int n = wn * 32 + ni * 8 + g;
        uint2 v0 = sB[(size_t)tg * BST + n];
        uint2 v1 = sB[(size_t)(tg + 4) * BST + n];
#pragma unroll
        for (int mi = 0; mi < 2; mi++) {
            mma16h(acc[mi][ni], ah[mi][0], ah[mi][1], ah[mi][2], ah[mi][3], v0.x, v1.x);
            mma16h(acc[mi][ni], ah[mi][0], ah[mi][1], ah[mi][2], ah[mi][3], v0.y, v1.y);
        }
    }
}

// ---------------- 64-wide GEMM (fc2, fp16 x2) ----------------
__launch_bounds__(256)
__global__ void k_fc2(const float* __restrict__ bias) {
    const uint32_t* __restrict__ A = g_hid1;
    const uint2* __restrict__ B = g_wfc2;
    const float* __restrict__ res = g_x;
    float* __restrict__ C = g_attn;
    const int K = HIDh, lda2 = HIDh / 2, ldb2 = Ee, ldc = Ee;

    __shared__ uint32_t sA[2][8 * AST];
    __shared__ uint2 sB[2][8 * BST];
    int t = threadIdx.x, lane = t & 31, wid = t >> 5;
    int wm = wid & 3, wn = wid >> 2;
    int bm = blockIdx.y * 128, bn = blockIdx.x * 64;
    float acc[2][4][4] = {};

    int mA = t & 127, koA2 = (t >> 7) * 4;
    const uint32_t* Arow = A + (size_t)(bm + mA) * lda2 + koA2;
    int kpB = t >> 5, nB = (t & 31) * 2;
    const uint2* Bp = B + (size_t)kpB * ldb2 + bn + nB;

    uint4 a0 = *(const uint4*)(Arow);
    uint4 b0 = *(const uint4*)(Bp);

    {
        uint32_t* pa = sA[0];
        pa[(size_t)(koA2 + 0) * AST + mA] = a0.x;
        pa[(size_t)(koA2 + 1) * AST + mA] = a0.y;
        pa[(size_t)(koA2 + 2) * AST + mA] = a0.z;
        pa[(size_t)(koA2 + 3) * AST + mA] = a0.w;
        uint2* pb = sB[0];
        pb[(size_t)kpB * BST + nB]     = make_uint2(b0.x, b0.y);
        pb[(size_t)kpB * BST + nB + 1] = make_uint2(b0.z, b0.w);
    }
    __syncthreads();

    int nch = K >> 4;
    for (int ch = 0; ch < nch; ch++) {
        int s = ch & 1;
        bool more = (ch + 1 < nch);
        if (more) {
            a0 = *(const uint4*)(Arow + (ch + 1) * 8);
            b0 = *(const uint4*)(Bp + (size_t)(ch + 1) * 8 * ldb2);
        }
        mma_chunk_h(sA[s], sB[s], wm, wn, lane, acc);
        if (more) {
            int s2 = s ^ 1;
            uint32_t* pa = sA[s2];
            pa[(size_t)(koA2 + 0) * AST + mA] = a0.x;
            pa[(size_t)(koA2 + 1) * AST + mA] = a0.y;
            pa[(size_t)(koA2 + 2) * AST + mA] = a0.z;
            pa[(size_t)(koA2 + 3) * AST + mA] = a0.w;
            uint2* pb = sB[s2];
            pb[(size_t)kpB * BST + nB]     = make_uint2(b0.x, b0.y);
            pb[(size_t)kpB * BST + nB + 1] = make_uint2(b0.z, b0.w);
        }
        __syncthreads();
    }

    int g = lane >> 2, tg = lane & 3;
#pragma unroll
    for (int mi = 0; mi < 2; mi++)
#pragma unroll
        for (int ni = 0; ni < 4; ni++) {
            int r0 = bm + wm * 32 + mi * 16 + g;
            int c0 = bn + wn * 32 + ni * 8 + 2 * tg;
            float bv0 = bias[c0], bv1 = bias[c0 + 1];
            float v00 = acc[mi][ni][0] + bv0 + res[(size_t)r0 * ldc + c0];
            float v01 = acc[mi][ni][1] + bv1 + res[(size_t)r0 * ldc + c0 + 1];
            float v10 = acc[mi][ni][2] + bv0 + res[(size_t)(r0 + 8) * ldc + c0];
            float v11 = acc[mi][ni][3] + bv1 + res[(size_t)(r0 + 8) * ldc + c0 + 1];
            C[(size_t)r0 * ldc + c0] = v00;
            C[(size_t)r0 * ldc + c0 + 1] = v01;
            C[(size_t)(r0 + 8) * ldc + c0] = v10;
            C[(size_t)(r0 + 8) * ldc + c0 + 1] = v11;
        }
}

// ---------------- 128x128 GEMM (qkv, fc1; fp16 x2) -------------------------------
// OUTH=0: uint2 hi/lo out (sph2; qkv). OUTH=1: uint32 single-fp16 out (h2pack; fc1).
template <int BIAS, int RELU, int OUTH>
__launch_bounds__(256, 2)
__global__ void k_gemm128(const uint32_t* __restrict__ A, const uint2* __restrict__ B,
                          const float* __restrict__ bias,
                          uint2* __restrict__ Cp2, uint32_t* __restrict__ Cp1,
                          int K, int lda2, int ldb2, int ldc) {
    __shared__ uint32_t sA[2][8 * AST];
    __shared__ uint2 sB2[2][8 * BSW];
    int t = threadIdx.x, lane = t & 31, wid = t >> 5;
    int wm = wid & 3, wn = wid >> 2;
    int g = lane >> 2, tg = lane & 3;
    int bm = blockIdx.y * 128, bn = blockIdx.x * 128;
    float acc[2][8][4] = {};

    int mA = t & 127, koA2 = (t >> 7) * 4;
    const uint32_t* Arow = A + (size_t)(bm + mA) * lda2 + koA2;
    int kpB = t >> 5, nB = (t & 31) * 4;
    const uint2* Bp = B + (size_t)kpB * ldb2 + bn + nB;

    uint4 a0 = *(const uint4*)(Arow);
    uint4 b0 = *(const uint4*)(Bp);
    uint4 b1 = *(const uint4*)(Bp + 2);

    {
        uint32_t* pa = sA[0];
        pa[(size_t)(koA2 + 0) * AST + mA] = a0.x;
        pa[(size_t)(koA2 + 1) * AST + mA] = a0.y;
        pa[(size_t)(koA2 + 2) * AST + mA] = a0.z;
        pa[(size_t)(koA2 + 3) * AST + mA] = a0.w;
        uint2* pb = sB2[0];
        pb[(size_t)kpB * BSW + nB]     = make_uint2(b0.x, b0.y);
        pb[(size_t)kpB * BSW + nB + 1] = make_uint2(b0.z, b0.w);
        pb[(size_t)kpB * BSW + nB + 2] = make_uint2(b1.x, b1.y);
        pb[(size_t)kpB * BSW + nB + 3] = make_uint2(b1.z, b1.w);
    }
    __syncthreads();

    int nch = K >> 4;
    for (int ch = 0; ch < nch; ch++) {
        int s = ch & 1;
        bool more = (ch + 1 < nch);
        if (more) {
            a0 = *(const uint4*)(Arow + (ch + 1) * 8);
            const uint2* Bn = Bp + (size_t)(ch + 1) * 8 * ldb2;
            b0 = *(const uint4*)(Bn);
            b1 = *(const uint4*)(Bn + 2);
        }
        {
            const uint32_t* pa = sA[s];
            const uint2* pb = sB2[s];
            uint32_t ah[2][4];
#pragma unroll
            for (int mi = 0; mi < 2; mi++) {
                int m = wm * 32 + mi * 16 + g;
                ah[mi][0] = pa[(size_t)tg * AST + m];
                ah[mi][1] = pa[(size_t)tg * AST + m + 8];
                ah[mi][2] = pa[(size_t)(tg + 4) * AST + m];
                ah[mi][3] = pa[(size_t)(tg + 4) * AST + m + 8];
            }
#pragma unroll
            for (int ni = 0; ni < 8; ni++) {
                int n = wn * 64 + ni * 8 + g;
                uint2 v0 = pb[(size_t)tg * BSW + n];
                uint2 v1 = pb[(size_t)(tg + 4) * BSW + n];
#pragma unroll
                for (int mi = 0; mi < 2; mi++) {
                    mma16h(acc[mi][ni], ah[mi][0], ah[mi][1], ah[mi][2], ah[mi][3], v0.x, v1.x);
                    mma16h(acc[mi][ni], ah[mi][0], ah[mi][1], ah[mi][2], ah[mi][3], v0.y, v1.y);
                }
            }
        }
        if (more) {
            int s2 = s ^ 1;
            uint32_t* pa = sA[s2];
            pa[(size_t)(koA2 + 0) * AST + mA] = a0.x;
            pa[(size_t)(koA2 + 1) * AST + mA] = a0.y;
            pa[(size_t)(koA2 + 2) * AST + mA] = a0.z;
            pa[(size_t)(koA2 + 3) * AST + mA] = a0.w;
            uint2* pb = sB2[s2];
            pb[(size_t)kpB * BSW + nB]     = make_uint2(b0.x, b0.y);
            pb[(size_t)kpB * BSW + nB + 1] = make_uint2(b0.z, b0.w);
            pb[(size_t)kpB * BSW + nB + 2] = make_uint2(b1.x, b1.y);
            pb[(size_t)kpB * BSW + nB + 3] = make_uint2(b1.z, b1.w);
        }
        __syncthreads();
    }

#pragma unroll
    for (int mi = 0; mi < 2; mi++)
#pragma unroll
        for (int ni = 0; ni < 8; ni++) {
            int r0 = bm + wm * 32 + mi * 16 + g;
            int c0 = bn + wn * 64 + ni * 8 + 2 * tg;
            float v00 = acc[mi][ni][0], v01 = acc[mi][ni][1];
            float v10 = acc[mi][ni][2], v11 = acc[mi][ni][3];
            if (BIAS) {
                float bv0 = bias[c0], bv1 = bias[c0 + 1];
                v00 += bv0; v01 += bv1; v10 += bv0; v11 += bv1;
            }
            if (RELU) {
                v00 = fmaxf(v00, 0.f); v01 = fmaxf(v01, 0.f);
                v10 = fmaxf(v10, 0.f); v11 = fmaxf(v11, 0.f);
            }
            if (OUTH == 0) {
                Cp2[(size_t)r0 * (ldc >> 1) + (c0 >> 1)] = sph2(v00, v01);
                Cp2[(size_t)(r0 + 8) * (ldc >> 1) + (c0 >> 1)] = sph2(v10, v11);
            } else {
                Cp1[(size_t)r0 * (ldc >> 1) + (c0 >> 1)] = h2pack(v00, v01);
                Cp1[(size_t)(r0 + 8) * (ldc >> 1) + (c0 >> 1)] = h2pack(v10, v11);
            }
        }
}

// ---------------- weight packing (fp16 hi/lo) ----------------
__global__ void k_pack_qkv(const float* __restrict__ qw, const float* __restrict__ kw,
                           const float* __restrict__ vw, const float* __restrict__ qb,
                           const float* __restrict__ kb, const float* __restrict__ vb) {
    int idx = blockIdx.x * 256 + threadIdx.x;
    if (idx < (Ee / 2) * 1536) {
        int n = idx % 1536, kp = idx / 1536;
        const float* W = (n < 512) ? qw : (n < 1024 ? kw : vw);
        int c = n & 511;
        g_wqkv[idx] = sph2(W[(size_t)(2 * kp) * 512 + c], W[(size_t)(2 * kp + 1) * 512 + c]);
    }
    if (idx < 1536)
        g_bqkv[idx] = (idx < 512) ? qb[idx] : (idx < 1024 ? kb[idx - 512] : vb[idx - 1024]);
}

__global__ void k_pack_w(const float* __restrict__ W, uint2* __restrict__ out, int Kp, int N) {
    int idx = blockIdx.x * 256 + threadIdx.x;
    if (idx >= Kp * N) return;
    int n = idx % N, kp = idx / N;
    out[idx] = sph2(W[(size_t)(2 * kp) * N + n], W[(size_t)(2 * kp + 1) * N + n]);
}

// ---------------- embedding + positional encoding ----------------
__global__ void k_embed(const int* __restrict__ inp, const float* __restrict__ emb) {
    int idx = blockIdx.x * blockDim.x + threadIdx.x;
    if (idx >= Bb * Ss * (Ee / 2)) return;
    int ep = idx % (Ee / 2);
    int bs = idx / (Ee / 2);
    int s = bs % Ss;
    int tok = inp[bs];
    int e0 = 2 * ep;
    const float LN1E4 = 9.210340371976184f;
    float freq = expf(-(float)e0 * (LN1E4 / (float)Ee));
    float ang = (float)s * freq;
    float x0 = emb[(size_t)tok * Ee + e0] + sinf(ang);
    float x1 = emb[(size_t)tok * Ee + e0 + 1] + cosf(ang);
    g_x[(size_t)bs * Ee + e0] = x0;
    g_x[(size_t)bs * Ee + e0 + 1] = x1;
    g_xp[(size_t)bs * (Ee / 2) + ep] = h2pack(x0, x1);
}

// ---------------- window-summed V (fp16 packed in/out) ----------------
__global__ void k_build_vs() {
    int idx = blockIdx.x * blockDim.x + threadIdx.x;
    if (idx >= Bb * Hh * (SKk / 2) * (DHh / 2)) return;
    int dp = idx & 31;
    int rest = idx >> 5;
    int kp = rest % (SKk / 2);
    int bh = rest / (SKk / 2);
    int b = bh >> 3, h = bh & 7;
    const uint2* Vp = g_qkvp + (size_t)b * Ss * 768 + 512 + h * 32 + dp;
    int k = 2 * kp;
    float v0[6], v1[6];
#pragma unroll
    for (int r = 0; r < 6; r++) {
        uint2 w = Vp[(size_t)(k + r) * 768];
        float2 hi = h2f2(w.x), lo = h2f2(w.y);
        v0[r] = hi.x + lo.x;
        v1[r] = hi.y + lo.y;
    }
    float s00 = v0[0] + v0[1] + v0[2] + v0[3] + v0[4];
    float s10 = v0[1] + v0[2] + v0[3] + v0[4] + v0[5];
    float s01 = v1[0] + v1[1] + v1[2] + v1[3] + v1[4];
    float s11 = v1[1] + v1[2] + v1[3] + v1[4] + v1[5];
    uint2* dst = g_vsp + ((size_t)bh * (SP / 2) + kp) * DHh + 2 * dp;
    dst[0] = sph2(s00, s10);
    dst[1] = sph2(s01, s11);
}

// ---------------- fused attention (unchanged from R15) --------
#define FA_OFF_Q  0
#define FA_OFF_K  10752
#define FA_OFF_G  28160
#define FA_OFF_P  46384
#define FA_OFF_V  55088
#define FA_OFF_S  72496
#define FA_SMEM   73008

__launch_bounds__(256)
__global__ void k_fattn() {
    extern __shared__ char dyn[];
    uint32_t* sQ = (uint32_t*)(dyn + FA_OFF_Q);
    uint2* sK = (uint2*)(dyn + FA_OFF_K);
    uint32_t* sGh = (uint32_t*)(dyn + FA_OFF_G);
    uint32_t* sPh = (uint32_t*)(dyn + FA_OFF_P);
    uint32_t* sV = (uint32_t*)(dyn + FA_OFF_V);
    float* sFac = (float*)(dyn + FA_OFF_S);
    float* sLf = sFac + 64;

    int qt = blockIdx.x;
    int bh = blockIdx.y;
    int b = bh >> 3, h = bh & 7;
    int q0 = qt * 64;
    const uint2* Qb = g_qkvp + (size_t)b * Ss * 768 + h * 32;
    const uint2* Kb = g_qkvp + (size_t)b * Ss * 768 + 256 + h * 32;
    const uint2* Vb = g_vsp + (size_t)bh * (SP / 2) * DHh;

    int t = threadIdx.x, lane = t & 31, wid = t >> 5;
    int wm = wid & 3, wn = wid >> 2;
    int g = lane >> 2, tg = lane & 3;
    float acc[4][4] = {};
    float m_run = -1e30f, l_run = 0.f;
    int srow = t >> 2, kbase = (t & 3) * 16;

    {
        int dpq = (t & 3) * 8;
        int rr = t >> 2;
#pragma unroll
        for (int rb = 0; rb < 80; rb += 64) {
            int r = rb + rr;
            if (r < 80) {
                int gr = q0 - 2 + r;
                bool ok = (r < 68) && (gr >= 0) && (gr < Ss);
#pragma unroll
                for (int u = 0; u < 8; u += 2) {
                    uint4 v = make_uint4(0, 0, 0, 0);
                    if (ok) v = *(const uint4*)(Qb + (size_t)gr * 768 + dpq + u);
                    sQ[(size_t)(dpq + u) * QST2 + r] = v.x;
                    sQ[(size_t)(dpq + u + 1) * QST2 + r] = v.z;
                }
            }
        }
    }
    {
        int r = t >> 2, dpq = (t & 3) * 8;
        const uint2* src = Kb + (size_t)r * 768 + dpq;
#pragma unroll
        for (int u = 0; u < 8; u += 2) {
            uint4 v = *(const uint4*)(src + u);
            sK[(size_t)(dpq + u) * KST + r] = make_uint2(v.x, v.y);
            sK[(size_t)(dpq + u + 1) * KST + r] = make_uint2(v.z, v.w);
        }
    }
    __syncthreads();

    {
        float accg[5][4] = {};
        int nb = wid * 8 + g;
#pragma unroll
        for (int c = 0; c < 4; c++) {
            uint2 v0 = sK[(size_t)(c * 8 + tg) * KST + nb];
            uint2 v1 = sK[(size_t)(c * 8 + tg + 4) * KST + nb];
#pragma unroll
            for (int mi = 0; mi < 5; mi++) {
                int m = mi * 16 + g;
                uint32_t u0 = sQ[(size_t)(c * 8 + tg) * QST2 + m];
                uint32_t u1 = sQ[(size_t)(c * 8 + tg) * QST2 + m + 8];
                uint32_t u2 = sQ[(size_t)(c * 8 + tg + 4) * QST2 + m];
                uint32_t u3 = sQ[(size_t)(c * 8 + tg + 4) * QST2 + m + 8];
                mma16h(accg[mi], u0, u1, u2, u3, v0.x, v1.x);
                mma16h(accg[mi], u0, u1, u2, u3, v0.y, v1.y);
            }
        }
        int cw = (wid * 8 + 2 * tg) >> 1;
#pragma unroll
        for (int mi = 0; mi < 5; mi++) {
            int r0 = mi * 16 + g;
            if (r0 < 68)
                sGh[r0 * GSW + cw] = h2pack(accg[mi][0] * SCALEc, accg[mi][1] * SCALEc);
            if (r0 + 8 < 68)
                sGh[(r0 + 8) * GSW + cw] = h2pack(accg[mi][2] * SCALEc, accg[mi][3] * SCALEc);
        }
    }
    __syncthreads();

    for (int it = 0; it < 32; it++) {
        int k0 = it * 64;
        bool more = (it < 31);
        uint32_t* sVb = sV + (size_t)(it & 1) * 32 * VST;

        if (more) {
            int r = t >> 2, dpq = (t & 3) * 8;
            const uint2* src = Kb + (size_t)((it + 1) * 64 + r) * 768 + dpq;
#pragma unroll
            for (int u = 0; u < 8; u += 2) {
                uint4 v = *(const uint4*)(src + u);
                sK[(size_t)(dpq + u) * KST + r] = make_uint2(v.x, v.y);
                sK[(size_t)(dpq + u + 1) * KST + r] = make_uint2(v.z, v.w);
            }
        }
        {
            int kpB = t >> 5, dB = (t & 31) * 2;
#pragma unroll
            for (int r = 0; r < 4; r++) {
                int kp = r * 8 + kpB;
                uint4 v = *(const uint4*)(Vb + (size_t)((k0 >> 1) + kp) * DHh + dB);
                sVb[(size_t)kp * VST + dB] = v.x;
                sVb[(size_t)kp * VST + dB + 1] = v.z;
            }
        }
        __syncthreads();   // A

        if (more) {
            float accg[5][4] = {};
            int nb = wid * 8 + g;
#pragma unroll
            for (int c = 0; c < 4; c++) {
                uint2 v0 = sK[(size_t)(c * 8 + tg) * KST + nb];
                uint2 v1 = sK[(size_t)(c * 8 + tg + 4) * KST + nb];
#pragma unroll
                for (int mi = 0; mi < 5; mi++) {
                    int m = mi * 16 + g;
                    uint32_t u0 = sQ[(size_t)(c * 8 + tg) * QST2 + m];
                    uint32_t u1 = sQ[(size_t)(c * 8 + tg) * QST2 + m + 8];
                    uint32_t u2 = sQ[(size_t)(c * 8 + tg + 4) * QST2 + m];
                    uint32_t u3 = sQ[(size_t)(c * 8 + tg + 4) * QST2 + m + 8];
                    mma16h(accg[mi], u0, u1, u2, u3, v0.x, v1.x);
                    mma16h(accg[mi], u0, u1, u2, u3, v0.y, v1.y);
                }
            }
            int cw = (((it + 1) & 1) * 64 + wid * 8 + 2 * tg) >> 1;
#pragma unroll
            for (int mi = 0; mi < 5; mi++) {
                int r0 = mi * 16 + g;
                if (r0 < 68)
                    sGh[r0 * GSW + cw] = h2pack(accg[mi][0] * SCALEc, accg[mi][1] * SCALEc);
                if (r0 + 8 < 68)
                    sGh[(r0 + 8) * GSW + cw] = h2pack(accg[mi][2] * SCALEc, accg[mi][3] * SCALEc);
            }
        }
        __syncthreads();   // B

        uint32_t sv2[8];
#pragma unroll
        for (int p = 0; p < 8; p++) sv2[p] = 0u;
        int cb0 = ((it & 1) << 6) + kbase;
#pragma unroll
        for (int j = 0; j < Ww; j++) {
            const uint32_t* rp = sGh + (srow + j) * GSW;
            uint32_t rr2[10];
#pragma unroll
            for (int m = 0; m < 5; m++) {
                uint2 w = *(const uint2*)(rp + (((cb0 + 4 * m) & 127) >> 1));
                rr2[2 * m] = w.x;
                rr2[2 * m + 1] = w.y;
            }
            if (j == 0 || j == 2 || j == 4) {
                int o = j >> 1;
#pragma unroll
                for (int p = 0; p < 8; p++) sv2[p] = hadd2u(sv2[p], rr2[p + o]);
            } else {
                int o = (j - 1) >> 1;
#pragma unroll
                for (int p = 0; p < 8; p++) {
                    uint32_t pr = __byte_perm(rr2[p + o], rr2[p + o + 1], 0x5432);
                    sv2[p] = hadd2u(sv2[p], pr);
                }
            }
        }
        float sv[16];
#pragma unroll
        for (int p = 0; p < 8; p++) {
            float2 f = h2f2(sv2[p]);
            sv[2 * p] = f.x;
            sv[2 * p + 1] = f.y;
        }
        float lmax = -1e30f;
#pragma unroll
        for (int i = 0; i < 16; i++) {
            if (k0 + kbase + i >= SKk) sv[i] = -1e30f;
            lmax = fmaxf(lmax, sv[i]);
        }
        lmax = fmaxf(lmax, __shfl_xor_sync(0xffffffffu, lmax, 1));
        lmax = fmaxf(lmax, __shfl_xor_sync(0xffffffffu, lmax, 2));
        float mnew = fmaxf(m_run, lmax);
        float lsum = 0.f;
#pragma unroll
        for (int i = 0; i < 16; i += 2) {
            float p0 = __expf(sv[i] - mnew);
            float p1 = __expf(sv[i + 1] - mnew);
            lsum += p0 + p1;
            sPh[(size_t)((kbase >> 1) + (i >> 1)) * PST + srow] = h2pack(p0, p1);
        }
        lsum += __shfl_xor_sync(0xffffffffu, lsum, 1);
        lsum += __shfl_xor_sync(0xffffffffu, lsum, 2);
        float fac = __expf(m_run - mnew);
        l_run = l_run * fac + lsum;
        m_run = mnew;
        if ((t & 3) == 0) sFac[srow] = fac;
        __syncthreads();   // C

        {
            float f0 = sFac[wm * 16 + g];
            float f1 = sFac[wm * 16 + g + 8];
#pragma unroll
            for (int ni = 0; ni < 4; ni++) {
                acc[ni][0] *= f0; acc[ni][1] *= f0;
                acc[ni][2] *= f1; acc[ni][3] *= f1;
            }
#pragma unroll
            for (int c = 0; c < 4; c++) {
                int m = wm * 16 + g;
                uint32_t u0 = sPh[(size_t)(c * 8 + tg) * PST + m];
                uint32_t u1 = sPh[(size_t)(c * 8 + tg) * PST + m + 8];
                uint32_t u2 = sPh[(size_t)(c * 8 + tg + 4) * PST + m];
                uint32_t u3 = sPh[(size_t)(c * 8 + tg + 4) * PST + m + 8];
#pragma unroll
                for (int ni = 0; ni < 4; ni++) {
                    int n = wn * 32 + ni * 8 + g;
                    uint32_t v0 = sVb[(size_t)(c * 8 + tg) * VST + n];
                    uint32_t v1 = sVb[(size_t)(c * 8 + tg + 4) * VST + n];
                    mma16h(acc[ni], u0, u1, u2, u3, v0, v1);
                }
            }
        }
    }

    __syncthreads();
    if ((t & 3) == 0) sLf[srow] = l_run;
    __syncthreads();

    float inv0 = 1.f / sLf[wm * 16 + g];
    float inv1 = 1.f / sLf[wm * 16 + g + 8];
    float* Cb = g_attn + (size_t)b * Ss * Ee + h * DHh;
#pragma unroll
    for (int ni = 0; ni < 4; ni++) {
        int r0 = q0 + wm * 16 + g;
        int c0 = wn * 32 + ni * 8 + 2 * tg;
        Cb[(size_t)r0 * Ee + c0] = acc[ni][0] * inv0;
        Cb[(size_t)r0 * Ee + c0 + 1] = acc[ni][1] * inv0;
        Cb[(size_t)(r0 + 8) * Ee + c0] = acc[ni][2] * inv1;
        Cb[(size_t)(r0 + 8) * Ee + c0 + 1] = acc[ni][3] * inv1;
    }
}

// ---------------- LayerNorm: warp per row, single-fp16 packed out ----------------
__launch_bounds__(256)
__global__ void k_ln(const float* __restrict__ in, const float* __restrict__ w,
                     const float* __restrict__ bz, float* __restrict__ out,
                     uint32_t* __restrict__ outp) {
    int row = blockIdx.x * 8 + (threadIdx.x >> 5);
    int lane = threadIdx.x & 31;
    const float* x = in + (size_t)row * Ee;

    float4 v[4];
#pragma unroll
    for (int j = 0; j < 4; j++)
        v[j] = *(const float4*)(x + 4 * (lane + j * 32));

    float s = 0.f;
#pragma unroll
    for (int j = 0; j < 4; j++) s += v[j].x + v[j].y + v[j].z + v[j].w;
#pragma unroll
    for (int off = 16; off > 0; off >>= 1)
        s += __shfl_xor_sync(0xffffffffu, s, off);
    float m = s * (1.0f / Ee);

    float vs = 0.f;
#pragma unroll
    for (int j = 0; j < 4; j++) {
        float d0 = v[j].x - m, d1 = v[j].y - m, d2 = v[j].z - m, d3 = v[j].w - m;
        vs += d0 * d0 + d1 * d1 + d2 * d2 + d3 * d3;
    }
#pragma unroll
    for (int off = 16; off > 0; off >>= 1)
        vs += __shfl_xor_sync(0xffffffffu, vs, off);
    float inv = rsqrtf(vs * (1.0f / Ee) + 1e-5f);

#pragma unroll
    for (int j = 0; j < 4; j++) {
        int c = 4 * (lane + j * 32);
        float4 wv = *(const float4*)(w + c);
        float4 bv = *(const float4*)(bz + c);
        float y0 = (v[j].x - m) * inv * wv.x + bv.x;
        float y1 = (v[j].y - m) * inv * wv.y + bv.y;
        float y2 = (v[j].z - m) * inv * wv.z + bv.z;
        float y3 = (v[j].w - m) * inv * wv.w + bv.w;
        *(float4*)(out + (size_t)row * Ee + c) = make_float4(y0, y1, y2, y3);
        *(uint2*)(outp + (size_t)row * (Ee / 2) + (c >> 1)) =
            make_uint2(h2pack(y0, y1), h2pack(y2, y3));
    }
}

// ---------------- output head ----------------
__launch_bounds__(256)
__global__ void k_out_partial(const float* __restrict__ ow) {
    int b = blockIdx.y, c = blockIdx.x;
    const int per = (Ss * Ee) / CHUNKS;
    const float* x = g_x + (size_t)b * Ss * Ee + (size_t)c * per;
    const float* wr = ow + (size_t)c * per * OUTo;
    int t = threadIdx.x;
    float acc[OUTo] = {};
    for (int i = t; i < per; i += 256) {
        float xv = x[i];
#pragma unroll
        for (int o = 0; o < OUTo; o++) acc[o] = fmaf(xv, wr[(size_t)i * OUTo + o], acc[o]);
    }
    __shared__ float red[256 * OUTo];
#pragma unroll
    for (int o = 0; o < OUTo; o++) red[t * OUTo + o] = acc[o];
    __syncthreads();
    for (int off = 128; off > 0; off >>= 1) {
        if (t < off) {
#pragma unroll
            for (int o = 0; o < OUTo; o++)
                red[t * OUTo + o] += red[(t + off) * OUTo + o];
        }
        __syncthreads();
    }
    if (t == 0) {
#pragma unroll
        for (int o = 0; o < OUTo; o++)
            g_part[((size_t)b * CHUNKS + c) * OUTo + o] = red[o];
    }
}

__global__ void k_out_final(const float* __restrict__ ob, float* __restrict__ out) {
    int b = blockIdx.x;
    int o = threadIdx.x;
    if (o < OUTo) {
        float s = ob[o];
        for (int c = 0; c < CHUNKS; c++) s += g_part[(b * CHUNKS + c) * OUTo + o];
        out[b * OUTo + o] = s;
    }
}

// ---------------- host launcher ----------------
extern "C" void kernel_launch(void* const* d_in, const int* in_sizes, int n_in,
                              void* d_out, int out_size) {
    const int*   inputs = (const int*)d_in[0];
    const float* emb    = (const float*)d_in[1];
    const float* ln_w   = (const float*)d_in[2];
    const float* ln_b   = (const float*)d_in[3];
    const float* q_w    = (const float*)d_in[4];
    const float* q_b    = (const float*)d_in[5];
    const float* k_w    = (const float*)d_in[6];
    const float* k_b    = (const float*)d_in[7];
    const float* v_w    = (const float*)d_in[8];
    const float* v_b    = (const float*)d_in[9];
    const float* fc1_w  = (const float*)d_in[10];
    const float* fc1_b  = (const float*)d_in[11];
    const float* fc2_w  = (const float*)d_in[12];
    const float* fc2_b  = (const float*)d_in[13];
    const float* out_w  = (const float*)d_in[14];
    const float* out_b  = (const float*)d_in[15];
    float* out = (float*)d_out;

    static int smem_set = 0;
    if (!smem_set) {
        cudaFuncSetAttribute(k_fattn, cudaFuncAttributeMaxDynamicSharedMemorySize, FA_SMEM);
        smem_set = 1;
    }

    float *px, *pattn, *pbqkv;
    uint32_t *pxp, *phid1;
    uint2 *pqkvp, *pwqkv, *pwfc1, *pwfc2;
    cudaGetSymbolAddress((void**)&px, g_x);
    cudaGetSymbolAddress((void**)&pattn, g_attn);
    cudaGetSymbolAddress((void**)&pxp, g_xp);
    cudaGetSymbolAddress((void**)&pqkvp, g_qkvp);
    cudaGetSymbolAddress((void**)&phid1, g_hid1);
    cudaGetSymbolAddress((void**)&pwqkv, g_wqkv);
    cudaGetSymbolAddress((void**)&pwfc1, g_wfc1);
    cudaGetSymbolAddress((void**)&pwfc2, g_wfc2);
    cudaGetSymbolAddress((void**)&pbqkv, g_bqkv);

    const int M = Bb * Ss;  // 4096

    k_pack_qkv<<<((Ee / 2) * 1536 + 255) / 256, 256>>>(q_w, k_w, v_w, q_b, k_b, v_b);
    k_pack_w<<<((Ee / 2) * HIDh + 255) / 256, 256>>>(fc1_w, pwfc1, Ee / 2, HIDh);
    k_pack_w<<<((HIDh / 2) * Ee + 255) / 256, 256>>>(fc2_w, pwfc2, HIDh / 2, Ee);

    k_embed<<<(Bb * Ss * (Ee / 2) + 255) / 256, 256>>>(inputs, emb);

    for (int l = 0; l < Ll; l++) {
        // QKV: fp16 x2, hi/lo-packed output for attention
        k_gemm128<1, 0, 0><<<dim3(1536 / 128, M / 128), 256>>>(
            pxp, pwqkv, pbqkv, pqkvp, nullptr, Ee, Ee / 2, 1536, 1536);

        k_build_vs<<<(Bb * Hh * (SKk / 2) * (DHh / 2) + 255) / 256, 256>>>();

        dim3 gf(Ss / 64, Bb * Hh);
        k_fattn<<<gf, 256, FA_SMEM>>>();

        k_ln<<<M / 8, 256>>>(pattn, ln_w, ln_b, px, pxp);

        // fc1: fp16 x2, relu, single-fp16 output
        k_gemm128<1, 1, 1><<<dim3(HIDh / 128, M / 128), 256>>>(
            pxp, pwfc1, fc1_b, nullptr, phid1, Ee, Ee / 2, HIDh, HIDh);
        // fc2: 64-wide fp16 x2, residual + fp32 out
        dim3 g2(Ee / 64, M / 128);
        k_fc2<<<g2, 256>>>(fc2_b);

        k_ln<<<M / 8, 256>>>(pattn, ln_w, ln_b, px, pxp);
    }

    dim3 go(CHUNKS, Bb);
    k_out_partial<<<go, 256>>>(out_w);
    k_out_final<<<Bb, 32>>>(out_b, out);
}

// round 17
// speedup vs baseline: 1.5686x; 1.0153x over previous
#include <cuda_runtime.h>
#include <cuda_bf16.h>
#include <cuda_fp16.h>
#include <math.h>
#include <stdint.h>

#define Bb 2
#define Ss 2048
#define Ee 512
#define Hh 8
#define DHh 64
#define Ww 5
#define PADp 2
#define SKk 2044
#define HIDh 2048
#define Ll 6
#define OUTo 6
#define SCALEc 0.125f
#define CHUNKS 128
#define SP 2048

#define AST 132   // smem A row stride (uint32, single-fp16 pairs)
#define BST 68    // smem B row stride (uint2), 64-wide core (fc2, hi/lo)
#define BSW 132   // smem B row stride (uint32), 128-wide core (single plane)
// fattn strides
#define QST2 84
#define KST 68
#define PST 68
#define VST 68
#define GSW 66    // G row stride in uint32 (132 halfs): even -> aligned LDS.64

// ---------------- scratch ----------------
__device__ float g_x[Bb * Ss * Ee];
__device__ uint32_t g_xp[Bb * Ss * (Ee / 2)];            // single fp16 pairs (GEMM A)
__device__ uint2 g_qkvp[Bb * Ss * 768];                  // fp16 hi/lo (attention operand)
__device__ uint32_t g_hid1[(size_t)Bb * Ss * (HIDh / 2)];// single fp16 pairs (fc1 out)
__device__ uint2 g_vsp[(size_t)Bb * Hh * (SP / 2) * DHh];// fp16 hi/lo
__device__ float g_attn[Bb * Ss * Ee];
__device__ float g_part[Bb * CHUNKS * OUTo];
__device__ uint32_t g_wqkv[(Ee / 2) * 1536];             // single fp16 weights
__device__ float g_bqkv[1536];
__device__ uint32_t g_wfc1[(Ee / 2) * HIDh];             // single fp16 weights
__device__ uint2 g_wfc2[(HIDh / 2) * Ee];                // hi/lo fp16 weights (anchor)

// ---------------- fp16 pack helpers ----------------
__device__ __forceinline__ uint32_t h2pack(float x, float y) {
    __half2 h = __floats2half2_rn(x, y);
    return *(uint32_t*)&h;
}
__device__ __forceinline__ float2 h2f2(uint32_t u) {
    __half2 h = *(__half2*)&u;
    return __half22float2(h);
}
__device__ __forceinline__ uint32_t hadd2u(uint32_t a, uint32_t b) {
    __half2 r = __hadd2(*(__half2*)&a, *(__half2*)&b);
    return *(uint32_t*)&r;
}
__device__ __forceinline__ uint2 sph2(float x, float y) {
    float hx = __half2float(__float2half_rn(x));
    float hy = __half2float(__float2half_rn(y));
    uint2 w;
    w.x = h2pack(hx, hy);
    w.y = h2pack(x - hx, y - hy);
    return w;
}

__device__ __forceinline__ void mma16h(float c[4], uint32_t a0, uint32_t a1, uint32_t a2,
                                       uint32_t a3, uint32_t b0, uint32_t b1) {
    asm volatile(
        "mma.sync.aligned.m16n8k16.row.col.f32.f16.f16.f32 "
        "{%0,%1,%2,%3},{%4,%5,%6,%7},{%8,%9},{%0,%1,%2,%3};"
        : "+f"(c[0]), "+f"(c[1]), "+f"(c[2]), "+f"(c[3])
        : "r"(a0), "r"(a1), "r"(a2), "r"(a3), "r"(b0), "r"(b1));
}

// ---------------- 64-wide GEMM (fc2: A single fp16, B hi/lo -> x2) ----------------
__launch_bounds__(256)
__global__ void k_fc2(const float* __restrict__ bias) {
    const uint32_t* __restrict__ A = g_hid1;
    const uint2* __restrict__ B = g_wfc2;
    const float* __restrict__ res = g_x;
    float* __restrict__ C = g_attn;
    const int K = HIDh, lda2 = HIDh / 2, ldb2 = Ee, ldc = Ee;

    __shared__ uint32_t sA[2][8 * AST];
    __shared__ uint2 sB[2][8 * BST];
    int t = threadIdx.x, lane = t & 31, wid = t >> 5;
    int wm = wid & 3, wn = wid >> 2;
    int bm = blockIdx.y * 128, bn = blockIdx.x * 64;
    float acc[2][4][4] = {};

    int mA = t & 127, koA2 = (t >> 7) * 4;
    const uint32_t* Arow = A + (size_t)(bm + mA) * lda2 + koA2;
    int kpB = t >> 5, nB = (t & 31) * 2;
    const uint2* Bp = B + (size_t)kpB * ldb2 + bn + nB;

    uint4 a0 = *(const uint4*)(Arow);
    uint4 b0 = *(const uint4*)(Bp);

    {
        uint32_t* pa = sA[0];
        pa[(size_t)(koA2 + 0) * AST + mA] = a0.x;
        pa[(size_t)(koA2 + 1) * AST + mA] = a0.y;
        pa[(size_t)(koA2 + 2) * AST + mA] = a0.z;
        pa[(size_t)(koA2 + 3) * AST + mA] = a0.w;
        uint2* pb = sB[0];
        pb[(size_t)kpB * BST + nB]     = make_uint2(b0.x, b0.y);
        pb[(size_t)kpB * BST + nB + 1] = make_uint2(b0.z, b0.w);
    }
    __syncthreads();

    int nch = K >> 4;
    for (int ch = 0; ch < nch; ch++) {
        int s = ch & 1;
        bool more = (ch + 1 < nch);
        if (more) {
            a0 = *(const uint4*)(Arow + (ch + 1) * 8);
            b0 = *(const uint4*)(Bp + (size_t)(ch + 1) * 8 * ldb2);
        }
        {
            const uint32_t* pa = sA[s];
            const uint2* pb = sB[s];
            int g = lane >> 2, tg = lane & 3;
            uint32_t ah[2][4];
#pragma unroll
            for (int mi = 0; mi < 2; mi++) {
                int m = wm * 32 + mi * 16 + g;
                ah[mi][0] = pa[(size_t)tg * AST + m];
                ah[mi][1] = pa[(size_t)tg * AST + m + 8];
                ah[mi][2] = pa[(size_t)(tg + 4) * AST + m];
                ah[mi][3] = pa[(size_t)(tg + 4) * AST + m + 8];
            }
#pragma unroll
            for (int ni = 0; ni < 4; ni++) {
                int n = wn * 32 + ni * 8 + g;
                uint2 v0 = pb[(size_t)tg * BST + n];
                uint2 v1 = pb[(size_t)(tg + 4) * BST + n];
#pragma unroll
                for (int mi = 0; mi < 2; mi++) {
                    mma16h(acc[mi][ni], ah[mi][0], ah[mi][1], ah[mi][2], ah[mi][3], v0.x, v1.x);
                    mma16h(acc[mi][ni], ah[mi][0], ah[mi][1], ah[mi][2], ah[mi][3], v0.y, v1.y);
                }
            }
        }
        if (more) {
            int s2 = s ^ 1;
            uint32_t* pa = sA[s2];
            pa[(size_t)(koA2 + 0) * AST + mA] = a0.x;
            pa[(size_t)(koA2 + 1) * AST + mA] = a0.y;
            pa[(size_t)(koA2 + 2) * AST + mA] = a0.z;
            pa[(size_t)(koA2 + 3) * AST + mA] = a0.w;
            uint2* pb = sB[s2];
            pb[(size_t)kpB * BST + nB]     = make_uint2(b0.x, b0.y);
            pb[(size_t)kpB * BST + nB + 1] = make_uint2(b0.z, b0.w);
        }
        __syncthreads();
    }

    int g = lane >> 2, tg = lane & 3;
#pragma unroll
    for (int mi = 0; mi < 2; mi++)
#pragma unroll
        for (int ni = 0; ni < 4; ni++) {
            int r0 = bm + wm * 32 + mi * 16 + g;
            int c0 = bn + wn * 32 + ni * 8 + 2 * tg;
            float bv0 = bias[c0], bv1 = bias[c0 + 1];
            float v00 = acc[mi][ni][0] + bv0 + res[(size_t)r0 * ldc + c0];
            float v01 = acc[mi][ni][1] + bv1 + res[(size_t)r0 * ldc + c0 + 1];
            float v10 = acc[mi][ni][2] + bv0 + res[(size_t)(r0 + 8) * ldc + c0];
            float v11 = acc[mi][ni][3] + bv1 + res[(size_t)(r0 + 8) * ldc + c0 + 1];
            C[(size_t)r0 * ldc + c0] = v00;
            C[(size_t)r0 * ldc + c0 + 1] = v01;
            C[(size_t)(r0 + 8) * ldc + c0] = v10;
            C[(size_t)(r0 + 8) * ldc + c0 + 1] = v11;
        }
}

// ---------------- 128x128 GEMM (qkv, fc1; A+B single fp16 -> x1) -----------------
// OUTH=0: uint2 hi/lo out (sph2; qkv). OUTH=1: uint32 single-fp16 out (h2pack; fc1).
template <int BIAS, int RELU, int OUTH>
__launch_bounds__(256, 2)
__global__ void k_gemm128(const uint32_t* __restrict__ A, const uint32_t* __restrict__ B,
                          const float* __restrict__ bias,
                          uint2* __restrict__ Cp2, uint32_t* __restrict__ Cp1,
                          int K, int lda2, int ldb2, int ldc) {
    __shared__ uint32_t sA[2][8 * AST];
    __shared__ uint32_t sB2[2][8 * BSW];
    int t = threadIdx.x, lane = t & 31, wid = t >> 5;
    int wm = wid & 3, wn = wid >> 2;
    int g = lane >> 2, tg = lane & 3;
    int bm = blockIdx.y * 128, bn = blockIdx.x * 128;
    float acc[2][8][4] = {};

    int mA = t & 127, koA2 = (t >> 7) * 4;
    const uint32_t* Arow = A + (size_t)(bm + mA) * lda2 + koA2;
    int kpB = t >> 5, nB = (t & 31) * 4;
    const uint32_t* Bp = B + (size_t)kpB * ldb2 + bn + nB;

    uint4 a0 = *(const uint4*)(Arow);
    uint4 b0 = *(const uint4*)(Bp);

    {
        uint32_t* pa = sA[0];
        pa[(size_t)(koA2 + 0) * AST + mA] = a0.x;
        pa[(size_t)(koA2 + 1) * AST + mA] = a0.y;
        pa[(size_t)(koA2 + 2) * AST + mA] = a0.z;
        pa[(size_t)(koA2 + 3) * AST + mA] = a0.w;
        uint32_t* pb = sB2[0];
        pb[(size_t)kpB * BSW + nB]     = b0.x;
        pb[(size_t)kpB * BSW + nB + 1] = b0.y;
        pb[(size_t)kpB * BSW + nB + 2] = b0.z;
        pb[(size_t)kpB * BSW + nB + 3] = b0.w;
    }
    __syncthreads();

    int nch = K >> 4;
    for (int ch = 0; ch < nch; ch++) {
        int s = ch & 1;
        bool more = (ch + 1 < nch);
        if (more) {
            a0 = *(const uint4*)(Arow + (ch + 1) * 8);
            b0 = *(const uint4*)(Bp + (size_t)(ch + 1) * 8 * ldb2);
        }
        {
            const uint32_t* pa = sA[s];
            const uint32_t* pb = sB2[s];
            uint32_t ah[2][4];
#pragma unroll
            for (int mi = 0; mi < 2; mi++) {
                int m = wm * 32 + mi * 16 + g;
                ah[mi][0] = pa[(size_t)tg * AST + m];
                ah[mi][1] = pa[(size_t)tg * AST + m + 8];
                ah[mi][2] = pa[(size_t)(tg + 4) * AST + m];
                ah[mi][3] = pa[(size_t)(tg + 4) * AST + m + 8];
            }
#pragma unroll
            for (int ni = 0; ni < 8; ni++) {
                int n = wn * 64 + ni * 8 + g;
                uint32_t v0 = pb[(size_t)tg * BSW + n];
                uint32_t v1 = pb[(size_t)(tg + 4) * BSW + n];
#pragma unroll
                for (int mi = 0; mi < 2; mi++)
                    mma16h(acc[mi][ni], ah[mi][0], ah[mi][1], ah[mi][2], ah[mi][3], v0, v1);
            }
        }
        if (more) {
            int s2 = s ^ 1;
            uint32_t* pa = sA[s2];
            pa[(size_t)(koA2 + 0) * AST + mA] = a0.x;
            pa[(size_t)(koA2 + 1) * AST + mA] = a0.y;
            pa[(size_t)(koA2 + 2) * AST + mA] = a0.z;
            pa[(size_t)(koA2 + 3) * AST + mA] = a0.w;
            uint32_t* pb = sB2[s2];
            pb[(size_t)kpB * BSW + nB]     = b0.x;
            pb[(size_t)kpB * BSW + nB + 1] = b0.y;
            pb[(size_t)kpB * BSW + nB + 2] = b0.z;
            pb[(size_t)kpB * BSW + nB + 3] = b0.w;
        }
        __syncthreads();
    }

#pragma unroll
    for (int mi = 0; mi < 2; mi++)
#pragma unroll
        for (int ni = 0; ni < 8; ni++) {
            int r0 = bm + wm * 32 + mi * 16 + g;
            int c0 = bn + wn * 64 + ni * 8 + 2 * tg;
            float v00 = acc[mi][ni][0], v01 = acc[mi][ni][1];
            float v10 = acc[mi][ni][2], v11 = acc[mi][ni][3];
            if (BIAS) {
                float bv0 = bias[c0], bv1 = bias[c0 + 1];
                v00 += bv0; v01 += bv1; v10 += bv0; v11 += bv1;
            }
            if (RELU) {
                v00 = fmaxf(v00, 0.f); v01 = fmaxf(v01, 0.f);
                v10 = fmaxf(v10, 0.f); v11 = fmaxf(v11, 0.f);
            }
            if (OUTH == 0) {
                Cp2[(size_t)r0 * (ldc >> 1) + (c0 >> 1)] = sph2(v00, v01);
                Cp2[(size_t)(r0 + 8) * (ldc >> 1) + (c0 >> 1)] = sph2(v10, v11);
            } else {
                Cp1[(size_t)r0 * (ldc >> 1) + (c0 >> 1)] = h2pack(v00, v01);
                Cp1[(size_t)(r0 + 8) * (ldc >> 1) + (c0 >> 1)] = h2pack(v10, v11);
            }
        }
}

// ---------------- weight packing ----------------
__global__ void k_pack_qkv(const float* __restrict__ qw, const float* __restrict__ kw,
                           const float* __restrict__ vw, const float* __restrict__ qb,
                           const float* __restrict__ kb, const float* __restrict__ vb) {
    int idx = blockIdx.x * 256 + threadIdx.x;
    if (idx < (Ee / 2) * 1536) {
        int n = idx % 1536, kp = idx / 1536;
        const float* W = (n < 512) ? qw : (n < 1024 ? kw : vw);
        int c = n & 511;
        g_wqkv[idx] = h2pack(W[(size_t)(2 * kp) * 512 + c], W[(size_t)(2 * kp + 1) * 512 + c]);
    }
    if (idx < 1536)
        g_bqkv[idx] = (idx < 512) ? qb[idx] : (idx < 1024 ? kb[idx - 512] : vb[idx - 1024]);
}

__global__ void k_pack_w1(const float* __restrict__ W, uint32_t* __restrict__ out, int Kp, int N) {
    int idx = blockIdx.x * 256 + threadIdx.x;
    if (idx >= Kp * N) return;
    int n = idx % N, kp = idx / N;
    out[idx] = h2pack(W[(size_t)(2 * kp) * N + n], W[(size_t)(2 * kp + 1) * N + n]);
}

__global__ void k_pack_w2(const float* __restrict__ W, uint2* __restrict__ out, int Kp, int N) {
    int idx = blockIdx.x * 256 + threadIdx.x;
    if (idx >= Kp * N) return;
    int n = idx % N, kp = idx / N;
    out[idx] = sph2(W[(size_t)(2 * kp) * N + n], W[(size_t)(2 * kp + 1) * N + n]);
}

// ---------------- embedding + positional encoding ----------------
__global__ void k_embed(const int* __restrict__ inp, const float* __restrict__ emb) {
    int idx = blockIdx.x * blockDim.x + threadIdx.x;
    if (idx >= Bb * Ss * (Ee / 2)) return;
    int ep = idx % (Ee / 2);
    int bs = idx / (Ee / 2);
    int s = bs % Ss;
    int tok = inp[bs];
    int e0 = 2 * ep;
    const float LN1E4 = 9.210340371976184f;
    float freq = expf(-(float)e0 * (LN1E4 / (float)Ee));
    float ang = (float)s * freq;
    float x0 = emb[(size_t)tok * Ee + e0] + sinf(ang);
    float x1 = emb[(size_t)tok * Ee + e0 + 1] + cosf(ang);
    g_x[(size_t)bs * Ee + e0] = x0;
    g_x[(size_t)bs * Ee + e0 + 1] = x1;
    g_xp[(size_t)bs * (Ee / 2) + ep] = h2pack(x0, x1);
}

// ---------------- window-summed V (fp16 packed in/out) ----------------
__global__ void k_build_vs() {
    int idx = blockIdx.x * blockDim.x + threadIdx.x;
    if (idx >= Bb * Hh * (SKk / 2) * (DHh / 2)) return;
    int dp = idx & 31;
    int rest = idx >> 5;
    int kp = rest % (SKk / 2);
    int bh = rest / (SKk / 2);
    int b = bh >> 3, h = bh & 7;
    const uint2* Vp = g_qkvp + (size_t)b * Ss * 768 + 512 + h * 32 + dp;
    int k = 2 * kp;
    float v0[6], v1[6];
#pragma unroll
    for (int r = 0; r < 6; r++) {
        uint2 w = Vp[(size_t)(k + r) * 768];
        float2 hi = h2f2(w.x), lo = h2f2(w.y);
        v0[r] = hi.x + lo.x;
        v1[r] = hi.y + lo.y;
    }
    float s00 = v0[0] + v0[1] + v0[2] + v0[3] + v0[4];
    float s10 = v0[1] + v0[2] + v0[3] + v0[4] + v0[5];
    float s01 = v1[0] + v1[1] + v1[2] + v1[3] + v1[4];
    float s11 = v1[1] + v1[2] + v1[3] + v1[4] + v1[5];
    uint2* dst = g_vsp + ((size_t)bh * (SP / 2) + kp) * DHh + 2 * dp;
    dst[0] = sph2(s00, s10);
    dst[1] = sph2(s01, s11);
}

// ---------------- fused attention (K single fp16 -> gram x1) --------
#define FA_OFF_Q  0                          // 32 x 84 uint   = 10752
#define FA_OFF_K  10752                      // 32 x 68 uint   = 8704
#define FA_OFF_G  19456                      // 68 x 66 uint   = 17952
#define FA_OFF_P  37408                      // 32 x 68 uint   = 8704
#define FA_OFF_V  46112                      // 2 x 32 x 68 uint = 17408
#define FA_OFF_S  63520                      // sFac[64] + sLf[64]
#define FA_SMEM   64032

__launch_bounds__(256)
__global__ void k_fattn() {
    extern __shared__ char dyn[];
    uint32_t* sQ = (uint32_t*)(dyn + FA_OFF_Q);
    uint32_t* sK = (uint32_t*)(dyn + FA_OFF_K);
    uint32_t* sGh = (uint32_t*)(dyn + FA_OFF_G);
    uint32_t* sPh = (uint32_t*)(dyn + FA_OFF_P);
    uint32_t* sV = (uint32_t*)(dyn + FA_OFF_V);
    float* sFac = (float*)(dyn + FA_OFF_S);
    float* sLf = sFac + 64;

    int qt = blockIdx.x;
    int bh = blockIdx.y;
    int b = bh >> 3, h = bh & 7;
    int q0 = qt * 64;
    const uint2* Qb = g_qkvp + (size_t)b * Ss * 768 + h * 32;
    const uint2* Kb = g_qkvp + (size_t)b * Ss * 768 + 256 + h * 32;
    const uint2* Vb = g_vsp + (size_t)bh * (SP / 2) * DHh;

    int t = threadIdx.x, lane = t & 31, wid = t >> 5;
    int wm = wid & 3, wn = wid >> 2;
    int g = lane >> 2, tg = lane & 3;
    float acc[4][4] = {};
    float m_run = -1e30f, l_run = 0.f;
    int srow = t >> 2, kbase = (t & 3) * 16;

    // load Q tile (hi plane only)
    {
        int dpq = (t & 3) * 8;
        int rr = t >> 2;
#pragma unroll
        for (int rb = 0; rb < 80; rb += 64) {
            int r = rb + rr;
            if (r < 80) {
                int gr = q0 - 2 + r;
                bool ok = (r < 68) && (gr >= 0) && (gr < Ss);
#pragma unroll
                for (int u = 0; u < 8; u += 2) {
                    uint4 v = make_uint4(0, 0, 0, 0);
                    if (ok) v = *(const uint4*)(Qb + (size_t)gr * 768 + dpq + u);
                    sQ[(size_t)(dpq + u) * QST2 + r] = v.x;
                    sQ[(size_t)(dpq + u + 1) * QST2 + r] = v.z;
                }
            }
        }
    }
    // load K panel 0 (hi plane only)
    {
        int r = t >> 2, dpq = (t & 3) * 8;
        const uint2* src = Kb + (size_t)r * 768 + dpq;
#pragma unroll
        for (int u = 0; u < 8; u += 2) {
            uint4 v = *(const uint4*)(src + u);
            sK[(size_t)(dpq + u) * KST + r] = v.x;
            sK[(size_t)(dpq + u + 1) * KST + r] = v.z;
        }
    }
    __syncthreads();

    // gram panel 0 -> ring slot 0 (fp16 x1)
    {
        float accg[5][4] = {};
        int nb = wid * 8 + g;
#pragma unroll
        for (int c = 0; c < 4; c++) {
            uint32_t v0 = sK[(size_t)(c * 8 + tg) * KST + nb];
            uint32_t v1 = sK[(size_t)(c * 8 + tg + 4) * KST + nb];
#pragma unroll
            for (int mi = 0; mi < 5; mi++) {
                int m = mi * 16 + g;
                uint32_t u0 = sQ[(size_t)(c * 8 + tg) * QST2 + m];
                uint32_t u1 = sQ[(size_t)(c * 8 + tg) * QST2 + m + 8];
                uint32_t u2 = sQ[(size_t)(c * 8 + tg + 4) * QST2 + m];
                uint32_t u3 = sQ[(size_t)(c * 8 + tg + 4) * QST2 + m + 8];
                mma16h(accg[mi], u0, u1, u2, u3, v0, v1);
            }
        }
        int cw = (wid * 8 + 2 * tg) >> 1;
#pragma unroll
        for (int mi = 0; mi < 5; mi++) {
            int r0 = mi * 16 + g;
            if (r0 < 68)
                sGh[r0 * GSW + cw] = h2pack(accg[mi][0] * SCALEc, accg[mi][1] * SCALEc);
            if (r0 + 8 < 68)
                sGh[(r0 + 8) * GSW + cw] = h2pack(accg[mi][2] * SCALEc, accg[mi][3] * SCALEc);
        }
    }
    __syncthreads();

    for (int it = 0; it < 32; it++) {
        int k0 = it * 64;
        bool more = (it < 31);
        uint32_t* sVb = sV + (size_t)(it & 1) * 32 * VST;

        if (more) {
            int r = t >> 2, dpq = (t & 3) * 8;
            const uint2* src = Kb + (size_t)((it + 1) * 64 + r) * 768 + dpq;
#pragma unroll
            for (int u = 0; u < 8; u += 2) {
                uint4 v = *(const uint4*)(src + u);
                sK[(size_t)(dpq + u) * KST + r] = v.x;
                sK[(size_t)(dpq + u + 1) * KST + r] = v.z;
            }
        }
        {
            int kpB = t >> 5, dB = (t & 31) * 2;
#pragma unroll
            for (int r = 0; r < 4; r++) {
                int kp = r * 8 + kpB;
                uint4 v = *(const uint4*)(Vb + (size_t)((k0 >> 1) + kp) * DHh + dB);
                sVb[(size_t)kp * VST + dB] = v.x;
                sVb[(size_t)kp * VST + dB + 1] = v.z;
            }
        }
        __syncthreads();   // A

        if (more) {
            float accg[5][4] = {};
            int nb = wid * 8 + g;
#pragma unroll
            for (int c = 0; c < 4; c++) {
                uint32_t v0 = sK[(size_t)(c * 8 + tg) * KST + nb];
                uint32_t v1 = sK[(size_t)(c * 8 + tg + 4) * KST + nb];
#pragma unroll
                for (int mi = 0; mi < 5; mi++) {
                    int m = mi * 16 + g;
                    uint32_t u0 = sQ[(size_t)(c * 8 + tg) * QST2 + m];
                    uint32_t u1 = sQ[(size_t)(c * 8 + tg) * QST2 + m + 8];
                    uint32_t u2 = sQ[(size_t)(c * 8 + tg + 4) * QST2 + m];
                    uint32_t u3 = sQ[(size_t)(c * 8 + tg + 4) * QST2 + m + 8];
                    mma16h(accg[mi], u0, u1, u2, u3, v0, v1);
                }
            }
            int cw = (((it + 1) & 1) * 64 + wid * 8 + 2 * tg) >> 1;
#pragma unroll
            for (int mi = 0; mi < 5; mi++) {
                int r0 = mi * 16 + g;
                if (r0 < 68)
                    sGh[r0 * GSW + cw] = h2pack(accg[mi][0] * SCALEc, accg[mi][1] * SCALEc);
                if (r0 + 8 < 68)
                    sGh[(r0 + 8) * GSW + cw] = h2pack(accg[mi][2] * SCALEc, accg[mi][3] * SCALEc);
            }
        }
        __syncthreads();   // B

        uint32_t sv2[8];
#pragma unroll
        for (int p = 0; p < 8; p++) sv2[p] = 0u;
        int cb0 = ((it & 1) << 6) + kbase;
#pragma unroll
        for (int j = 0; j < Ww; j++) {
            const uint32_t* rp = sGh + (srow + j) * GSW;
            uint32_t rr2[10];
#pragma unroll
            for (int m = 0; m < 5; m++) {
                uint2 w = *(const uint2*)(rp + (((cb0 + 4 * m) & 127) >> 1));
                rr2[2 * m] = w.x;
                rr2[2 * m + 1] = w.y;
            }
            if (j == 0 || j == 2 || j == 4) {
                int o = j >> 1;
#pragma unroll
                for (int p = 0; p < 8; p++) sv2[p] = hadd2u(sv2[p], rr2[p + o]);
            } else {
                int o = (j - 1) >> 1;
#pragma unroll
                for (int p = 0; p < 8; p++) {
                    uint32_t pr = __byte_perm(rr2[p + o], rr2[p + o + 1], 0x5432);
                    sv2[p] = hadd2u(sv2[p], pr);
                }
            }
        }
        float sv[16];
#pragma unroll
        for (int p = 0; p < 8; p++) {
            float2 f = h2f2(sv2[p]);
            sv[2 * p] = f.x;
            sv[2 * p + 1] = f.y;
        }
        float lmax = -1e30f;
#pragma unroll
        for (int i = 0; i < 16; i++) {
            if (k0 + kbase + i >= SKk) sv[i] = -1e30f;
            lmax = fmaxf(lmax, sv[i]);
        }
        lmax = fmaxf(lmax, __shfl_xor_sync(0xffffffffu, lmax, 1));
        lmax = fmaxf(lmax, __shfl_xor_sync(0xffffffffu, lmax, 2));
        float mnew = fmaxf(m_run, lmax);
        float lsum = 0.f;
#pragma unroll
        for (int i = 0; i < 16; i += 2) {
            float p0 = __expf(sv[i] - mnew);
            float p1 = __expf(sv[i + 1] - mnew);
            lsum += p0 + p1;
            sPh[(size_t)((kbase >> 1) + (i >> 1)) * PST + srow] = h2pack(p0, p1);
        }
        lsum += __shfl_xor_sync(0xffffffffu, lsum, 1);
        lsum += __shfl_xor_sync(0xffffffffu, lsum, 2);
        float fac = __expf(m_run - mnew);
        l_run = l_run * fac + lsum;
        m_run = mnew;
        if ((t & 3) == 0) sFac[srow] = fac;
        __syncthreads();   // C

        {
            float f0 = sFac[wm * 16 + g];
            float f1 = sFac[wm * 16 + g + 8];
#pragma unroll
            for (int ni = 0; ni < 4; ni++) {
                acc[ni][0] *= f0; acc[ni][1] *= f0;
                acc[ni][2] *= f1; acc[ni][3] *= f1;
            }
#pragma unroll
            for (int c = 0; c < 4; c++) {
                int m = wm * 16 + g;
                uint32_t u0 = sPh[(size_t)(c * 8 + tg) * PST + m];
                uint32_t u1 = sPh[(size_t)(c * 8 + tg) * PST + m + 8];
                uint32_t u2 = sPh[(size_t)(c * 8 + tg + 4) * PST + m];
                uint32_t u3 = sPh[(size_t)(c * 8 + tg + 4) * PST + m + 8];
#pragma unroll
                for (int ni = 0; ni < 4; ni++) {
                    int n = wn * 32 + ni * 8 + g;
                    uint32_t v0 = sVb[(size_t)(c * 8 + tg) * VST + n];
                    uint32_t v1 = sVb[(size_t)(c * 8 + tg + 4) * VST + n];
                    mma16h(acc[ni], u0, u1, u2, u3, v0, v1);
                }
            }
        }
    }

    __syncthreads();
    if ((t & 3) == 0) sLf[srow] = l_run;
    __syncthreads();

    float inv0 = 1.f / sLf[wm * 16 + g];
    float inv1 = 1.f / sLf[wm * 16 + g + 8];
    float* Cb = g_attn + (size_t)b * Ss * Ee + h * DHh;
#pragma unroll
    for (int ni = 0; ni < 4; ni++) {
        int r0 = q0 + wm * 16 + g;
        int c0 = wn * 32 + ni * 8 + 2 * tg;
        Cb[(size_t)r0 * Ee + c0] = acc[ni][0] * inv0;
        Cb[(size_t)r0 * Ee + c0 + 1] = acc[ni][1] * inv0;
        Cb[(size_t)(r0 + 8) * Ee + c0] = acc[ni][2] * inv1;
        Cb[(size_t)(r0 + 8) * Ee + c0 + 1] = acc[ni][3] * inv1;
    }
}

// ---------------- LayerNorm: warp per row, single-fp16 packed out ----------------
__launch_bounds__(256)
__global__ void k_ln(const float* __restrict__ in, const float* __restrict__ w,
                     const float* __restrict__ bz, float* __restrict__ out,
                     uint32_t* __restrict__ outp) {
    int row = blockIdx.x * 8 + (threadIdx.x >> 5);
    int lane = threadIdx.x & 31;
    const float* x = in + (size_t)row * Ee;

    float4 v[4];
#pragma unroll
    for (int j = 0; j < 4; j++)
        v[j] = *(const float4*)(x + 4 * (lane + j * 32));

    float s = 0.f;
#pragma unroll
    for (int j = 0; j < 4; j++) s += v[j].x + v[j].y + v[j].z + v[j].w;
#pragma unroll
    for (int off = 16; off > 0; off >>= 1)
        s += __shfl_xor_sync(0xffffffffu, s, off);
    float m = s * (1.0f / Ee);

    float vs = 0.f;
#pragma unroll
    for (int j = 0; j < 4; j++) {
        float d0 = v[j].x - m, d1 = v[j].y - m, d2 = v[j].z - m, d3 = v[j].w - m;
        vs += d0 * d0 + d1 * d1 + d2 * d2 + d3 * d3;
    }
#pragma unroll
    for (int off = 16; off > 0; off >>= 1)
        vs += __shfl_xor_sync(0xffffffffu, vs, off);
    float inv = rsqrtf(vs * (1.0f / Ee) + 1e-5f);

#pragma unroll
    for (int j = 0; j < 4; j++) {
        int c = 4 * (lane + j * 32);
        float4 wv = *(const float4*)(w + c);
        float4 bv = *(const float4*)(bz + c);
        float y0 = (v[j].x - m) * inv * wv.x + bv.x;
        float y1 = (v[j].y - m) * inv * wv.y + bv.y;
        float y2 = (v[j].z - m) * inv * wv.z + bv.z;
        float y3 = (v[j].w - m) * inv * wv.w + bv.w;
        *(float4*)(out + (size_t)row * Ee + c) = make_float4(y0, y1, y2, y3);
        *(uint2*)(outp + (size_t)row * (Ee / 2) + (c >> 1)) =
            make_uint2(h2pack(y0, y1), h2pack(y2, y3));
    }
}

// ---------------- output head ----------------
__launch_bounds__(256)
__global__ void k_out_partial(const float* __restrict__ ow) {
    int b = blockIdx.y, c = blockIdx.x;
    const int per = (Ss * Ee) / CHUNKS;
    const float* x = g_x + (size_t)b * Ss * Ee + (size_t)c * per;
    const float* wr = ow + (size_t)c * per * OUTo;
    int t = threadIdx.x;
    float acc[OUTo] = {};
    for (int i = t; i < per; i += 256) {
        float xv = x[i];
#pragma unroll
        for (int o = 0; o < OUTo; o++) acc[o] = fmaf(xv, wr[(size_t)i * OUTo + o], acc[o]);
    }
    __shared__ float red[256 * OUTo];
#pragma unroll
    for (int o = 0; o < OUTo; o++) red[t * OUTo + o] = acc[o];
    __syncthreads();
    for (int off = 128; off > 0; off >>= 1) {
        if (t < off) {
#pragma unroll
            for (int o = 0; o < OUTo; o++)
                red[t * OUTo + o] += red[(t + off) * OUTo + o];
        }
        __syncthreads();
    }
    if (t == 0) {
#pragma unroll
        for (int o = 0; o < OUTo; o++)
            g_part[((size_t)b * CHUNKS + c) * OUTo + o] = red[o];
    }
}

__global__ void k_out_final(const float* __restrict__ ob, float* __restrict__ out) {
    int b = blockIdx.x;
    int o = threadIdx.x;
    if (o < OUTo) {
        float s = ob[o];
        for (int c = 0; c < CHUNKS; c++) s += g_part[(b * CHUNKS + c) * OUTo + o];
        out[b * OUTo + o] = s;
    }
}

// ---------------- host launcher ----------------
extern "C" void kernel_launch(void* const* d_in, const int* in_sizes, int n_in,
                              void* d_out, int out_size) {
    const int*   inputs = (const int*)d_in[0];
    const float* emb    = (const float*)d_in[1];
    const float* ln_w   = (const float*)d_in[2];
    const float* ln_b   = (const float*)d_in[3];
    const float* q_w    = (const float*)d_in[4];
    const float* q_b    = (const float*)d_in[5];
    const float* k_w    = (const float*)d_in[6];
    const float* k_b    = (const float*)d_in[7];
    const float* v_w    = (const float*)d_in[8];
    const float* v_b    = (const float*)d_in[9];
    const float* fc1_w  = (const float*)d_in[10];
    const float* fc1_b  = (const float*)d_in[11];
    const float* fc2_w  = (const float*)d_in[12];
    const float* fc2_b  = (const float*)d_in[13];
    const float* out_w  = (const float*)d_in[14];
    const float* out_b  = (const float*)d_in[15];
    float* out = (float*)d_out;

    static int smem_set = 0;
    if (!smem_set) {
        cudaFuncSetAttribute(k_fattn, cudaFuncAttributeMaxDynamicSharedMemorySize, FA_SMEM);
        smem_set = 1;
    }

    float *px, *pattn, *pbqkv;
    uint32_t *pxp, *phid1, *pwqkv, *pwfc1;
    uint2 *pqkvp, *pwfc2;
    cudaGetSymbolAddress((void**)&px, g_x);
    cudaGetSymbolAddress((void**)&pattn, g_attn);
    cudaGetSymbolAddress((void**)&pxp, g_xp);
    cudaGetSymbolAddress((void**)&pqkvp, g_qkvp);
    cudaGetSymbolAddress((void**)&phid1, g_hid1);
    cudaGetSymbolAddress((void**)&pwqkv, g_wqkv);
    cudaGetSymbolAddress((void**)&pwfc1, g_wfc1);
    cudaGetSymbolAddress((void**)&pwfc2, g_wfc2);
    cudaGetSymbolAddress((void**)&pbqkv, g_bqkv);

    const int M = Bb * Ss;  // 4096

    k_pack_qkv<<<((Ee / 2) * 1536 + 255) / 256, 256>>>(q_w, k_w, v_w, q_b, k_b, v_b);
    k_pack_w1<<<((Ee / 2) * HIDh + 255) / 256, 256>>>(fc1_w, pwfc1, Ee / 2, HIDh);
    k_pack_w2<<<((HIDh / 2) * Ee + 255) / 256, 256>>>(fc2_w, pwfc2, HIDh / 2, Ee);

    k_embed<<<(Bb * Ss * (Ee / 2) + 255) / 256, 256>>>(inputs, emb);

    for (int l = 0; l < Ll; l++) {
        // QKV: fp16 x1, hi/lo-packed output for attention
        k_gemm128<1, 0, 0><<<dim3(1536 / 128, M / 128), 256>>>(
            pxp, pwqkv, pbqkv, pqkvp, nullptr, Ee, Ee / 2, 1536, 1536);

        k_build_vs<<<(Bb * Hh * (SKk / 2) * (DHh / 2) + 255) / 256, 256>>>();

        dim3 gf(Ss / 64, Bb * Hh);
        k_fattn<<<gf, 256, FA_SMEM>>>();

        k_ln<<<M / 8, 256>>>(pattn, ln_w, ln_b, px, pxp);

        // fc1: fp16 x1, relu, single-fp16 output
        k_gemm128<1, 1, 1><<<dim3(HIDh / 128, M / 128), 256>>>(
            pxp, pwfc1, fc1_b, nullptr, phid1, Ee, Ee / 2, HIDh, HIDh);
        // fc2: 64-wide fp16 x2 (weights hi/lo anchor), residual + fp32 out
        dim3 g2(Ee / 64, M / 128);
        k_fc2<<<g2, 256>>>(fc2_b);

        k_ln<<<M / 8, 256>>>(pattn, ln_w, ln_b, px, pxp);
    }

    dim3 go(CHUNKS, Bb);
    k_out_partial<<<go, 256>>>(out_w);
    k_out_final<<<Bb, 32>>>(out_b, out);
}